// round 5
// baseline (speedup 1.0000x reference)
#include <cuda_runtime.h>
#include <cuda_bf16.h>
#include <math.h>
#include <stdint.h>

#define BATCH 8
#define NNODE 2048
#define FEAT  256
#define ROWS  (BATCH * NNODE)   // 16384
#define ALPHA_LR 0.2f
#define NEG_BIG  -9.0e15f

#if defined(__CUDA_ARCH_FEAT_SM103_ALL) || defined(__CUDA_ARCH_FEAT_SM100_ALL)
#define HAS_TC 1
#else
#define HAS_TC 0
#endif

// -------- scratch (device globals; no allocation allowed) --------
__device__ float g_Wh[(size_t)ROWS * FEAT];                      // 16 MB fp32
__device__ __nv_bfloat16 g_WhT_hi[(size_t)BATCH * FEAT * NNODE]; // 8 MB  Wh^T hi
__device__ __nv_bfloat16 g_WhT_lo[(size_t)BATCH * FEAT * NNODE]; // 8 MB  Wh^T lo
__device__ float g_s1[ROWS];
__device__ float g_s2[ROWS];
__device__ float g_m [ROWS];
__device__ float g_li[ROWS];

// ======================= helpers =======================
__device__ __forceinline__ uint32_t smem_u32(const void* p) {
    uint32_t a;
    asm("{ .reg .u64 t; cvta.to.shared.u64 t, %1; cvt.u32.u64 %0, t; }"
        : "=r"(a) : "l"(p));
    return a;
}
// packed fp32x2 (used by fallback path)
__device__ __forceinline__ void fma2(unsigned long long& d,
                                     unsigned long long a,
                                     unsigned long long b) {
    asm("fma.rn.f32x2 %0, %1, %2, %0;" : "+l"(d) : "l"(a), "l"(b));
}
__device__ __forceinline__ unsigned long long dup2(float w) {
    unsigned long long r;
    asm("mov.b64 %0, {%1, %1};" : "=l"(r) : "f"(w));
    return r;
}
__device__ __forceinline__ void unpack2(unsigned long long v, float& lo, float& hi) {
    asm("mov.b64 {%0, %1}, %2;" : "=f"(lo), "=f"(hi) : "l"(v));
}

#if HAS_TC
__device__ __forceinline__ uint32_t elect1() {
    uint32_t p;
    asm volatile("{ .reg .pred p; elect.sync _|p, 0xFFFFFFFF; selp.b32 %0,1,0,p; }"
                 : "=r"(p));
    return p;
}
#define TC_ALLOC(sm, n)   asm volatile("tcgen05.alloc.cta_group::1.sync.aligned.shared::cta.b32 [%0], %1;" :: "r"(sm), "r"(n) : "memory")
#define TC_DEALLOC(t, n)  asm volatile("tcgen05.dealloc.cta_group::1.sync.aligned.b32 %0, %1;" :: "r"(t), "r"(n))
#define TC_WAIT_ST()      asm volatile("tcgen05.wait::st.sync.aligned;" ::: "memory")
#define TC_WAIT_LD()      asm volatile("tcgen05.wait::ld.sync.aligned;" ::: "memory")
#define TC_FENCE_BEFORE() asm volatile("tcgen05.fence::before_thread_sync;" ::: "memory")
#define TC_FENCE_AFTER()  asm volatile("tcgen05.fence::after_thread_sync;" ::: "memory")
#define FENCE_ASYNC_SH()  asm volatile("fence.proxy.async.shared::cta;" ::: "memory")
#define TC_COMMIT(mb)     asm volatile("tcgen05.commit.cta_group::1.mbarrier::arrive::one.shared::cluster.b64 [%0];" :: "r"(mb) : "memory")
#define MBAR_INIT(mb, c)  asm volatile("mbarrier.init.shared.b64 [%0], %1;" :: "r"(mb), "r"(c) : "memory")
#define MBAR_INVAL(mb)    asm volatile("mbarrier.inval.shared.b64 [%0];" :: "r"(mb) : "memory")

#define MBAR_WAIT(mb, ph) do {                                                   \
    uint32_t _mb = (mb); uint32_t _ph = (ph); uint32_t _done;                    \
    asm volatile("{ .reg .pred p; mbarrier.try_wait.parity.acquire.cta.shared::cta.b64 p, [%1], %2; selp.b32 %0,1,0,p; }" \
                 : "=r"(_done) : "r"(_mb), "r"(_ph) : "memory");                 \
    if (!_done) {                                                                \
        asm volatile("{ .reg .pred P1; WL_%=: mbarrier.try_wait.parity.acquire.cta.shared::cta.b64 P1, [%0], %1, 0x989680; @P1 bra.uni WD_%=; bra.uni WL_%=; WD_%=: }" \
                     :: "r"(_mb), "r"(_ph) : "memory");                          \
    }                                                                            \
} while (0)

#define TC_ST_X16(tm, r)                                                         \
    asm volatile("tcgen05.st.sync.aligned.32x32b.x16.b32 [%0], "                 \
        "{%1,%2,%3,%4,%5,%6,%7,%8,%9,%10,%11,%12,%13,%14,%15,%16};"              \
        :: "r"(tm),                                                              \
           "r"((r)[0]),  "r"((r)[1]),  "r"((r)[2]),  "r"((r)[3]),                \
           "r"((r)[4]),  "r"((r)[5]),  "r"((r)[6]),  "r"((r)[7]),                \
           "r"((r)[8]),  "r"((r)[9]),  "r"((r)[10]), "r"((r)[11]),               \
           "r"((r)[12]), "r"((r)[13]), "r"((r)[14]), "r"((r)[15]) : "memory")

#define TC_LD_X32(r, tm)                                                         \
    asm volatile("tcgen05.ld.sync.aligned.32x32b.x32.b32 "                       \
        "{%0,%1,%2,%3,%4,%5,%6,%7,%8,%9,%10,%11,%12,%13,%14,%15,"                \
        "%16,%17,%18,%19,%20,%21,%22,%23,%24,%25,%26,%27,%28,%29,%30,%31}, [%32];" \
        : "=r"((r)[0]),  "=r"((r)[1]),  "=r"((r)[2]),  "=r"((r)[3]),             \
          "=r"((r)[4]),  "=r"((r)[5]),  "=r"((r)[6]),  "=r"((r)[7]),             \
          "=r"((r)[8]),  "=r"((r)[9]),  "=r"((r)[10]), "=r"((r)[11]),            \
          "=r"((r)[12]), "=r"((r)[13]), "=r"((r)[14]), "=r"((r)[15]),            \
          "=r"((r)[16]), "=r"((r)[17]), "=r"((r)[18]), "=r"((r)[19]),            \
          "=r"((r)[20]), "=r"((r)[21]), "=r"((r)[22]), "=r"((r)[23]),            \
          "=r"((r)[24]), "=r"((r)[25]), "=r"((r)[26]), "=r"((r)[27]),            \
          "=r"((r)[28]), "=r"((r)[29]), "=r"((r)[30]), "=r"((r)[31])             \
        : "r"(tm))

__device__ __forceinline__ void mma_f16_ts(uint32_t d, uint32_t a, uint64_t bdesc,
                                           uint32_t idesc, uint32_t en) {
    asm volatile("{ .reg .pred p; setp.ne.u32 p, %4, 0;\n\t"
        "tcgen05.mma.cta_group::1.kind::f16 [%0], [%1], %2, %3, {%5,%5,%5,%5}, p;\n\t}"
        :: "r"(d), "r"(a), "l"(bdesc), "r"(idesc), "r"(en), "r"(0u) : "memory");
}

#define SWZ128(x) ((x) ^ (((x) >> 3) & 0x70))
// K-major SW128 descriptor base: layout=2, version=1, SBO=64, LBO=1
__device__ __forceinline__ uint64_t kdesc(uint32_t addr) {
    const uint64_t base = (uint64_t(2) << 61) | (uint64_t(1) << 46)
                        | (uint64_t(64) << 32) | (uint64_t(1) << 16);
    return base | ((uint64_t)(addr >> 4) & 0x3FFF);
}
// idesc kind::f16: dtype=F32, atype=btype=BF16, N=64, M=128
#define IDESC_F16 ((1u << 4) | (1u << 7) | (1u << 10) | (8u << 17) | (8u << 24))
#endif // HAS_TC

// ================= K1: Wh = h @ W  (fp32 SIMT) =================
__global__ __launch_bounds__(256) void k_gemm(const float* __restrict__ A,
                                              const float* __restrict__ B) {
    __shared__ float As[16][64];
    __shared__ float Bs[16][64];
    const int m0 = blockIdx.y * 64;
    const int n0 = blockIdx.x * 64;
    const int t  = threadIdx.x;
    const int ty = t >> 4, tx = t & 15;

    float acc[4][4];
#pragma unroll
    for (int i = 0; i < 4; i++)
#pragma unroll
        for (int j = 0; j < 4; j++) acc[i][j] = 0.f;

    for (int k0 = 0; k0 < 256; k0 += 16) {
        {
            int i  = t >> 2, kq = t & 3;
            float4 v = *(const float4*)&A[(size_t)(m0 + i) * 256 + k0 + kq * 4];
            As[kq * 4 + 0][i] = v.x; As[kq * 4 + 1][i] = v.y;
            As[kq * 4 + 2][i] = v.z; As[kq * 4 + 3][i] = v.w;
        }
        {
            int kk = t >> 4, j4 = t & 15;
            float4 v = *(const float4*)&B[(size_t)(k0 + kk) * 256 + n0 + j4 * 4];
            Bs[kk][j4 * 4 + 0] = v.x; Bs[kk][j4 * 4 + 1] = v.y;
            Bs[kk][j4 * 4 + 2] = v.z; Bs[kk][j4 * 4 + 3] = v.w;
        }
        __syncthreads();
#pragma unroll
        for (int kk = 0; kk < 16; kk++) {
            float a[4], b[4];
#pragma unroll
            for (int x = 0; x < 4; x++) { a[x] = As[kk][ty * 4 + x]; b[x] = Bs[kk][tx * 4 + x]; }
#pragma unroll
            for (int i = 0; i < 4; i++)
#pragma unroll
                for (int j = 0; j < 4; j++) acc[i][j] = fmaf(a[i], b[j], acc[i][j]);
        }
        __syncthreads();
    }
#pragma unroll
    for (int i = 0; i < 4; i++) {
        int row = m0 + ty * 4 + i;
#pragma unroll
        for (int j = 0; j < 4; j++)
            g_Wh[(size_t)row * 256 + n0 + tx * 4 + j] = acc[i][j];
    }
}

// ================= K2: s1/s2 row dot products =================
__global__ __launch_bounds__(256) void k_s(const float* __restrict__ a) {
    const int row = blockIdx.x;
    const int t   = threadIdx.x;
    float v  = g_Wh[(size_t)row * 256 + t];
    float p1 = v * a[t];
    float p2 = v * a[256 + t];
#pragma unroll
    for (int o = 16; o; o >>= 1) {
        p1 += __shfl_down_sync(0xffffffffu, p1, o);
        p2 += __shfl_down_sync(0xffffffffu, p2, o);
    }
    __shared__ float r1[8], r2[8];
    if ((t & 31) == 0) { r1[t >> 5] = p1; r2[t >> 5] = p2; }
    __syncthreads();
    if (t == 0) {
        float s1 = 0.f, s2 = 0.f;
#pragma unroll
        for (int w = 0; w < 8; w++) { s1 += r1[w]; s2 += r2[w]; }
        g_s1[row] = s1;
        g_s2[row] = s2;
    }
}

// ================= K3: per-row softmax stats (m, 1/l) =================
__global__ __launch_bounds__(256) void k_ml(const int* __restrict__ adj) {
    const int gwarp = (blockIdx.x * blockDim.x + threadIdx.x) >> 5;
    const int lane  = threadIdx.x & 31;
    if (gwarp >= ROWS) return;
    const int b = gwarp >> 11;
    const float  s1   = g_s1[gwarp];
    const int*   arow = adj + (size_t)gwarp * NNODE;
    const float* s2p  = g_s2 + (size_t)b * NNODE;

    float m = -INFINITY, l = 0.f;
    for (int j = lane; j < NNODE; j += 32) {
        float x = s1 + s2p[j];
        float e = (x > 0.f) ? x : ALPHA_LR * x;
        e = (arow[j] > 0) ? e : NEG_BIG;
        if (e > m) { l = l * __expf(m - e) + 1.f; m = e; }
        else       { l += __expf(e - m); }
    }
#pragma unroll
    for (int o = 16; o; o >>= 1) {
        float m2 = __shfl_down_sync(0xffffffffu, m, o);
        float l2 = __shfl_down_sync(0xffffffffu, l, o);
        float M  = fmaxf(m, m2);
        l = l * __expf(m - M) + l2 * __expf(m2 - M);
        m = M;
    }
    if (lane == 0) { g_m[gwarp] = m; g_li[gwarp] = 1.f / l; }
}

// ======== K3b: transpose + bf16 hi/lo split:  WhT[b][f][j] ========
__global__ __launch_bounds__(256) void k_tr() {
    __shared__ float tile[32][33];
    const int b  = blockIdx.z;
    const int j0 = blockIdx.x * 32;
    const int f0 = blockIdx.y * 32;
    const int tx = threadIdx.x & 31;
    const int ty = threadIdx.x >> 5;   // 0..7
#pragma unroll
    for (int k = 0; k < 4; k++) {
        int j = j0 + ty + k * 8;
        tile[ty + k * 8][tx] = g_Wh[((size_t)(b * NNODE + j)) * 256 + f0 + tx];
    }
    __syncthreads();
#pragma unroll
    for (int k = 0; k < 4; k++) {
        int f = f0 + ty + k * 8;
        float w = tile[tx][ty + k * 8];
        __nv_bfloat16 hi = __float2bfloat16(w);
        __nv_bfloat16 lo = __float2bfloat16(w - __bfloat162float(hi));
        size_t o = (((size_t)(b * FEAT + f)) << 11) + j0 + tx;
        g_WhT_hi[o] = hi;
        g_WhT_lo[o] = lo;
    }
}

// ================= K4: attention @ Wh + ELU =================
// TC path: TS-mode bf16 tcgen05 MMA; P and Wh both hi/lo split (3 MMA terms).
// TMEM: D cols 0..255, P_hi cols 256..287, P_lo cols 288..319.
// Fallback path (non-sm_103a compile): f32x2 register GEMM.
#define SMEM_B_BYTES (2 * 4 * 64 * 128)   // 65536
#define SMEM_DYN     (SMEM_B_BYTES + 1024)
__global__ __launch_bounds__(256, 1) void k_attn_tc(const int* __restrict__ adj,
                                                    float* __restrict__ out) {
    extern __shared__ char smraw[];
    __shared__ float s1S[128], mS[128], liS[128];

    const int t   = threadIdx.x;
    const int b   = blockIdx.y;
    const int i0  = blockIdx.x * 128;
    const int rowbase = b * NNODE + i0;

    if (t < 128) {
        s1S[t] = g_s1[rowbase + t];
        mS [t] = g_m [rowbase + t];
        liS[t] = g_li[rowbase + t];
    }

#if HAS_TC
    // ================== tcgen05 path ==================
    __shared__ uint32_t tmem_ptr_s;
    __shared__ __align__(8) unsigned long long mbar_s;

    char* smB = (char*)(((uintptr_t)smraw + 1023) & ~(uintptr_t)1023);
    const uint32_t smB_u  = smem_u32(smB);
    const uint32_t mbar_u = smem_u32(&mbar_s);
    const uint32_t tptr_u = smem_u32(&tmem_ptr_s);
    const int wid = t >> 5;

    if (wid == 0) TC_ALLOC(tptr_u, 512);
    if (t == 0)   MBAR_INIT(mbar_u, 1);
    __syncthreads();
    uint32_t tmem;
    asm volatile("ld.shared.b32 %0, [%1];" : "=r"(tmem) : "r"(tptr_u));

    int par = 0;
    for (int tile = 0; tile < NNODE / 64; tile++) {
        const int j0 = tile * 64;
        if (t < 128) {
            // ---- P compute: row = t, two 32-j halves, hi/lo bf16 split
            const float s1v = s1S[t], mv = mS[t], lv = liS[t];
            const uint32_t woff = ((uint32_t)wid) << 21;
#pragma unroll
            for (int hj = 0; hj < 2; hj++) {
                const int4*   ar  = (const int4*)&adj[(size_t)(rowbase + t) * NNODE + j0 + hj * 32];
                const float4* s2p = (const float4*)&g_s2[b * NNODE + j0 + hj * 32];
                uint32_t pkh[16], pkl[16];
#pragma unroll
                for (int g = 0; g < 4; g++) {
                    int4   a0 = ar[g * 2],  a1 = ar[g * 2 + 1];
                    float4 q0 = s2p[g * 2], q1 = s2p[g * 2 + 1];
                    float xs[8] = {q0.x, q0.y, q0.z, q0.w, q1.x, q1.y, q1.z, q1.w};
                    int   av[8] = {a0.x, a0.y, a0.z, a0.w, a1.x, a1.y, a1.z, a1.w};
                    float ph[8], pl[8];
#pragma unroll
                    for (int i = 0; i < 8; i++) {
                        float x = s1v + xs[i];
                        float e = (x > 0.f) ? x : ALPHA_LR * x;
                        e = (av[i] > 0) ? e : NEG_BIG;
                        float p = __expf(e - mv) * lv;
                        __nv_bfloat16 hb = __float2bfloat16(p);
                        float hr = __bfloat162float(hb);
                        ph[i] = hr;
                        pl[i] = p - hr;
                    }
#pragma unroll
                    for (int i = 0; i < 4; i++) {
                        __nv_bfloat162 h2 = __floats2bfloat162_rn(ph[2 * i], ph[2 * i + 1]);
                        __nv_bfloat162 l2 = __floats2bfloat162_rn(pl[2 * i], pl[2 * i + 1]);
                        pkh[g * 4 + i] = *(uint32_t*)&h2;
                        pkl[g * 4 + i] = *(uint32_t*)&l2;
                    }
                }
                TC_ST_X16(tmem + 256 + hj * 16 + woff, pkh);
                TC_ST_X16(tmem + 288 + hj * 16 + woff, pkl);
            }
            TC_WAIT_ST();
            TC_FENCE_BEFORE();
        } else {
            // ---- B staging: Wh^T hi/lo, 4 N-chunks x [64 n][64 k] bf16 SW128
            const int t2 = t - 128;
#pragma unroll
            for (int i = 0; i < 32; i++) {
                int idx   = t2 + i * 128;
                int k4    = idx & 7;
                int n     = (idx >> 3) & 63;
                int chunk = (idx >> 9) & 3;
                int half  = idx >> 11;
                const __nv_bfloat16* src = half ? g_WhT_lo : g_WhT_hi;
                uint4 v = *(const uint4*)&src[(((size_t)(b * FEAT + chunk * 64 + n)) << 11) + j0 + k4 * 8];
                uint32_t off = (uint32_t)(half * 32768 + chunk * 8192)
                             + SWZ128((uint32_t)(n * 128 + k4 * 16));
                *(uint4*)(smB + off) = v;
            }
            FENCE_ASYNC_SH();
        }
        __syncthreads();

        if (wid == 0) {
            TC_FENCE_AFTER();
            if (elect1()) {
                // terms: 0 = P_hi*W_hi, 1 = P_lo*W_hi, 2 = P_hi*W_lo
#pragma unroll
                for (int term = 0; term < 3; term++) {
                    const uint32_t a_base = tmem + ((term == 1) ? 288 : 256);
                    const uint32_t w_half = (term == 2) ? 32768u : 0u;
#pragma unroll
                    for (int chunk = 0; chunk < 4; chunk++) {
                        uint64_t bd  = kdesc(smB_u + w_half + chunk * 8192);
                        uint32_t dtm = tmem + chunk * 64;
#pragma unroll
                        for (int ks = 0; ks < 4; ks++) {
                            uint32_t en = (tile != 0) | (term != 0) | (ks != 0);
                            mma_f16_ts(dtm, a_base + ks * 8, bd + ks * 2, IDESC_F16, en);
                        }
                    }
                }
                TC_COMMIT(mbar_u);
            }
        }
        MBAR_WAIT(mbar_u, par);
        par ^= 1;
    }

    // ---- epilogue: LDTM, ELU, store
    TC_FENCE_AFTER();
    if (t < 128) {
        const size_t rowoff = (size_t)(rowbase + t) * 256;
#pragma unroll
        for (int base = 0; base < 256; base += 32) {
            uint32_t d[32];
            TC_LD_X32(d, tmem + base);
            TC_WAIT_LD();
#pragma unroll
            for (int q = 0; q < 8; q++) {
                float v0 = __uint_as_float(d[q * 4 + 0]);
                float v1 = __uint_as_float(d[q * 4 + 1]);
                float v2 = __uint_as_float(d[q * 4 + 2]);
                float v3 = __uint_as_float(d[q * 4 + 3]);
                float4 o;
                o.x = (v0 > 0.f) ? v0 : expm1f(v0);
                o.y = (v1 > 0.f) ? v1 : expm1f(v1);
                o.z = (v2 > 0.f) ? v2 : expm1f(v2);
                o.w = (v3 > 0.f) ? v3 : expm1f(v3);
                *(float4*)&out[rowoff + base + q * 4] = o;
            }
        }
    }
    __syncthreads();
    if (t == 0) MBAR_INVAL(mbar_u);
    __syncthreads();
    if (wid == 0) TC_DEALLOC(tmem, 512);

#else
    // ================== fallback: f32x2 register GEMM ==================
    float (*whS)[128] = (float (*)[128])smraw;           // 16x128 = 8 KB
    float (*pS)[128]  = (float (*)[128])(smraw + 8192);  // 16x128 = 8 KB

    const int tr = t >> 4, tc = t & 15;
    const int w_kk = t >> 4, w_f0 = (t & 15) * 8;
    const int p_r  = t >> 1, p_kq = (t & 1) * 8;

    for (int fb = 0; fb < 256; fb += 128) {
        unsigned long long acc[4][8];
#pragma unroll
        for (int i = 0; i < 4; i++)
#pragma unroll
            for (int c = 0; c < 8; c++) acc[i][c] = 0ull;

        for (int j0 = 0; j0 < NNODE; j0 += 16) {
            __syncthreads();
            {
                const float* src = &g_Wh[((size_t)(b * NNODE + j0 + w_kk)) * 256 + fb + w_f0];
                float4 v0 = *(const float4*)src;
                float4 v1 = *(const float4*)(src + 4);
                *(float4*)&whS[w_kk][w_f0]     = v0;
                *(float4*)&whS[w_kk][w_f0 + 4] = v1;
            }
            {
                const int* ar = &adj[((size_t)(rowbase + p_r)) * NNODE + j0 + p_kq];
                int4 a0 = *(const int4*)ar;
                int4 a1 = *(const int4*)(ar + 4);
                int av[8] = {a0.x, a0.y, a0.z, a0.w, a1.x, a1.y, a1.z, a1.w};
                float s1v = s1S[p_r], mv = mS[p_r], lv = liS[p_r];
                const float* s2p = &g_s2[b * NNODE + j0 + p_kq];
#pragma unroll
                for (int i = 0; i < 8; i++) {
                    float x = s1v + s2p[i];
                    float e = (x > 0.f) ? x : ALPHA_LR * x;
                    e = (av[i] > 0) ? e : NEG_BIG;
                    pS[p_kq + i][p_r] = __expf(e - mv) * lv;
                }
            }
            __syncthreads();

#pragma unroll 4
            for (int kk = 0; kk < 16; kk++) {
                ulonglong2 pA = *(const ulonglong2*)&pS[kk][tr * 4];
                ulonglong2 pB = *(const ulonglong2*)&pS[kk][64 + tr * 4];
                float4 wA = *(const float4*)&whS[kk][tc * 4];
                float4 wB = *(const float4*)&whS[kk][64 + tc * 4];
                unsigned long long w2[8];
                w2[0] = dup2(wA.x); w2[1] = dup2(wA.y);
                w2[2] = dup2(wA.z); w2[3] = dup2(wA.w);
                w2[4] = dup2(wB.x); w2[5] = dup2(wB.y);
                w2[6] = dup2(wB.z); w2[7] = dup2(wB.w);
#pragma unroll
                for (int c = 0; c < 8; c++) {
                    fma2(acc[0][c], pA.x, w2[c]);
                    fma2(acc[1][c], pA.y, w2[c]);
                    fma2(acc[2][c], pB.x, w2[c]);
                    fma2(acc[3][c], pB.y, w2[c]);
                }
            }
        }

#pragma unroll
        for (int ip = 0; ip < 4; ip++) {
            int rloc = (ip < 2) ? (tr * 4 + ip * 2) : (64 + tr * 4 + (ip - 2) * 2);
            float lo[8], hi[8];
#pragma unroll
            for (int c = 0; c < 8; c++) unpack2(acc[ip][c], lo[c], hi[c]);
#pragma unroll
            for (int h2 = 0; h2 < 2; h2++) {
                float* v = h2 ? hi : lo;
                size_t rowoff = ((size_t)(rowbase + rloc + h2)) * 256;
                float4 oA, oB;
                oA.x = (v[0] > 0.f) ? v[0] : expm1f(v[0]);
                oA.y = (v[1] > 0.f) ? v[1] : expm1f(v[1]);
                oA.z = (v[2] > 0.f) ? v[2] : expm1f(v[2]);
                oA.w = (v[3] > 0.f) ? v[3] : expm1f(v[3]);
                oB.x = (v[4] > 0.f) ? v[4] : expm1f(v[4]);
                oB.y = (v[5] > 0.f) ? v[5] : expm1f(v[5]);
                oB.z = (v[6] > 0.f) ? v[6] : expm1f(v[6]);
                oB.w = (v[7] > 0.f) ? v[7] : expm1f(v[7]);
                *(float4*)&out[rowoff + fb + tc * 4]      = oA;
                *(float4*)&out[rowoff + fb + 64 + tc * 4] = oB;
            }
        }
    }
#endif
}

// ================= launcher =================
extern "C" void kernel_launch(void* const* d_in, const int* in_sizes, int n_in,
                              void* d_out, int out_size) {
    const float* h   = (const float*)d_in[0];   // (8,2048,256) f32
    const int*   adj = (const int*)  d_in[1];   // (8,2048,2048) i32
    const float* W   = (const float*)d_in[2];   // (256,256) f32
    const float* a   = (const float*)d_in[3];   // (512,1) f32
    float* out = (float*)d_out;                 // (8,2048,256) f32

    cudaFuncSetAttribute(k_attn_tc, cudaFuncAttributeMaxDynamicSharedMemorySize,
                         SMEM_DYN);

    k_gemm<<<dim3(4, 256), 256>>>(h, W);
    k_s   <<<ROWS, 256>>>(a);
    k_ml  <<<ROWS / 8, 256>>>(adj);
    k_tr  <<<dim3(NNODE / 32, FEAT / 32, BATCH), 256>>>();
    k_attn_tc<<<dim3(NNODE / 128, BATCH), 256, SMEM_DYN>>>(adj, out);
}

// round 6
// speedup vs baseline: 1.3125x; 1.3125x over previous
#include <cuda_runtime.h>
#include <cuda_bf16.h>
#include <math.h>
#include <stdint.h>

#define BATCH 8
#define NNODE 2048
#define FEAT  256
#define ROWS  (BATCH * NNODE)   // 16384
#define ALPHA_LR 0.2f
#define NEG_BIG  -9.0e15f

#if defined(__CUDA_ARCH_FEAT_SM103_ALL) || defined(__CUDA_ARCH_FEAT_SM100_ALL)
#define HAS_TC 1
#else
#define HAS_TC 0
#endif

// -------- scratch (device globals; no allocation allowed) --------
__device__ float g_Wh[(size_t)ROWS * FEAT];                      // 16 MB fp32
__device__ __nv_bfloat16 g_WhT_hi[(size_t)BATCH * FEAT * NNODE]; // 8 MB  Wh^T hi
__device__ __nv_bfloat16 g_WhT_lo[(size_t)BATCH * FEAT * NNODE]; // 8 MB  Wh^T lo
__device__ float g_s1[ROWS];
__device__ float g_s2[ROWS];
__device__ float g_m [ROWS];
__device__ float g_li[ROWS];

// ======================= helpers =======================
__device__ __forceinline__ uint32_t smem_u32(const void* p) {
    uint32_t a;
    asm("{ .reg .u64 t; cvta.to.shared.u64 t, %1; cvt.u32.u64 %0, t; }"
        : "=r"(a) : "l"(p));
    return a;
}
// packed fp32x2 (used by fallback path)
__device__ __forceinline__ void fma2(unsigned long long& d,
                                     unsigned long long a,
                                     unsigned long long b) {
    asm("fma.rn.f32x2 %0, %1, %2, %0;" : "+l"(d) : "l"(a), "l"(b));
}
__device__ __forceinline__ unsigned long long dup2(float w) {
    unsigned long long r;
    asm("mov.b64 %0, {%1, %1};" : "=l"(r) : "f"(w));
    return r;
}
__device__ __forceinline__ void unpack2(unsigned long long v, float& lo, float& hi) {
    asm("mov.b64 {%0, %1}, %2;" : "=f"(lo), "=f"(hi) : "l"(v));
}

#if HAS_TC
__device__ __forceinline__ uint32_t elect1() {
    uint32_t p;
    asm volatile("{ .reg .pred p; elect.sync _|p, 0xFFFFFFFF; selp.b32 %0,1,0,p; }"
                 : "=r"(p));
    return p;
}
#define TC_ALLOC(sm, n)   asm volatile("tcgen05.alloc.cta_group::1.sync.aligned.shared::cta.b32 [%0], %1;" :: "r"(sm), "r"(n) : "memory")
#define TC_DEALLOC(t, n)  asm volatile("tcgen05.dealloc.cta_group::1.sync.aligned.b32 %0, %1;" :: "r"(t), "r"(n))
#define TC_WAIT_LD()      asm volatile("tcgen05.wait::ld.sync.aligned;" ::: "memory")
#define TC_FENCE_BEFORE() asm volatile("tcgen05.fence::before_thread_sync;" ::: "memory")
#define TC_FENCE_AFTER()  asm volatile("tcgen05.fence::after_thread_sync;" ::: "memory")
#define FENCE_ASYNC_SH()  asm volatile("fence.proxy.async.shared::cta;" ::: "memory")
#define TC_COMMIT(mb)     asm volatile("tcgen05.commit.cta_group::1.mbarrier::arrive::one.shared::cluster.b64 [%0];" :: "r"(mb) : "memory")
#define MBAR_INIT(mb, c)  asm volatile("mbarrier.init.shared.b64 [%0], %1;" :: "r"(mb), "r"(c) : "memory")
#define MBAR_INVAL(mb)    asm volatile("mbarrier.inval.shared.b64 [%0];" :: "r"(mb) : "memory")

#define MBAR_WAIT(mb, ph) do {                                                   \
    uint32_t _mb = (mb); uint32_t _ph = (ph); uint32_t _done;                    \
    asm volatile("{ .reg .pred p; mbarrier.try_wait.parity.acquire.cta.shared::cta.b64 p, [%1], %2; selp.b32 %0,1,0,p; }" \
                 : "=r"(_done) : "r"(_mb), "r"(_ph) : "memory");                 \
    if (!_done) {                                                                \
        asm volatile("{ .reg .pred P1; WL_%=: mbarrier.try_wait.parity.acquire.cta.shared::cta.b64 P1, [%0], %1, 0x989680; @P1 bra.uni WD_%=; bra.uni WL_%=; WD_%=: }" \
                     :: "r"(_mb), "r"(_ph) : "memory");                          \
    }                                                                            \
} while (0)

#define TC_LD_X32(r, tm)                                                         \
    asm volatile("tcgen05.ld.sync.aligned.32x32b.x32.b32 "                       \
        "{%0,%1,%2,%3,%4,%5,%6,%7,%8,%9,%10,%11,%12,%13,%14,%15,"                \
        "%16,%17,%18,%19,%20,%21,%22,%23,%24,%25,%26,%27,%28,%29,%30,%31}, [%32];" \
        : "=r"((r)[0]),  "=r"((r)[1]),  "=r"((r)[2]),  "=r"((r)[3]),             \
          "=r"((r)[4]),  "=r"((r)[5]),  "=r"((r)[6]),  "=r"((r)[7]),             \
          "=r"((r)[8]),  "=r"((r)[9]),  "=r"((r)[10]), "=r"((r)[11]),            \
          "=r"((r)[12]), "=r"((r)[13]), "=r"((r)[14]), "=r"((r)[15]),            \
          "=r"((r)[16]), "=r"((r)[17]), "=r"((r)[18]), "=r"((r)[19]),            \
          "=r"((r)[20]), "=r"((r)[21]), "=r"((r)[22]), "=r"((r)[23]),            \
          "=r"((r)[24]), "=r"((r)[25]), "=r"((r)[26]), "=r"((r)[27]),            \
          "=r"((r)[28]), "=r"((r)[29]), "=r"((r)[30]), "=r"((r)[31])             \
        : "r"(tm))

// SS-mode bf16 MMA: A and B both via SMEM descriptors
__device__ __forceinline__ void mma_f16_ss(uint32_t d, uint64_t adesc, uint64_t bdesc,
                                           uint32_t idesc, uint32_t en) {
    asm volatile("{ .reg .pred p; setp.ne.u32 p, %4, 0;\n\t"
        "tcgen05.mma.cta_group::1.kind::f16 [%0], %1, %2, %3, {%5,%5,%5,%5}, p;\n\t}"
        :: "r"(d), "l"(adesc), "l"(bdesc), "r"(idesc), "r"(en), "r"(0u) : "memory");
}

#define SWZ128(x) ((x) ^ (((x) >> 3) & 0x70))
// K-major SW128 descriptor base: layout=2, version=1, SBO=64, LBO=1
__device__ __forceinline__ uint64_t kdesc(uint32_t addr) {
    const uint64_t base = (uint64_t(2) << 61) | (uint64_t(1) << 46)
                        | (uint64_t(64) << 32) | (uint64_t(1) << 16);
    return base | ((uint64_t)(addr >> 4) & 0x3FFF);
}
// idesc kind::f16: dtype=F32, atype=btype=BF16, N=64, M=128
#define IDESC_F16 ((1u << 4) | (1u << 7) | (1u << 10) | (8u << 17) | (8u << 24))
#endif // HAS_TC

// ================= K1: Wh = h @ W  (fp32 SIMT) =================
__global__ __launch_bounds__(256) void k_gemm(const float* __restrict__ A,
                                              const float* __restrict__ B) {
    __shared__ float As[16][64];
    __shared__ float Bs[16][64];
    const int m0 = blockIdx.y * 64;
    const int n0 = blockIdx.x * 64;
    const int t  = threadIdx.x;
    const int ty = t >> 4, tx = t & 15;

    float acc[4][4];
#pragma unroll
    for (int i = 0; i < 4; i++)
#pragma unroll
        for (int j = 0; j < 4; j++) acc[i][j] = 0.f;

    for (int k0 = 0; k0 < 256; k0 += 16) {
        {
            int i  = t >> 2, kq = t & 3;
            float4 v = *(const float4*)&A[(size_t)(m0 + i) * 256 + k0 + kq * 4];
            As[kq * 4 + 0][i] = v.x; As[kq * 4 + 1][i] = v.y;
            As[kq * 4 + 2][i] = v.z; As[kq * 4 + 3][i] = v.w;
        }
        {
            int kk = t >> 4, j4 = t & 15;
            float4 v = *(const float4*)&B[(size_t)(k0 + kk) * 256 + n0 + j4 * 4];
            Bs[kk][j4 * 4 + 0] = v.x; Bs[kk][j4 * 4 + 1] = v.y;
            Bs[kk][j4 * 4 + 2] = v.z; Bs[kk][j4 * 4 + 3] = v.w;
        }
        __syncthreads();
#pragma unroll
        for (int kk = 0; kk < 16; kk++) {
            float a[4], b[4];
#pragma unroll
            for (int x = 0; x < 4; x++) { a[x] = As[kk][ty * 4 + x]; b[x] = Bs[kk][tx * 4 + x]; }
#pragma unroll
            for (int i = 0; i < 4; i++)
#pragma unroll
                for (int j = 0; j < 4; j++) acc[i][j] = fmaf(a[i], b[j], acc[i][j]);
        }
        __syncthreads();
    }
#pragma unroll
    for (int i = 0; i < 4; i++) {
        int row = m0 + ty * 4 + i;
#pragma unroll
        for (int j = 0; j < 4; j++)
            g_Wh[(size_t)row * 256 + n0 + tx * 4 + j] = acc[i][j];
    }
}

// ================= K2: s1/s2 row dot products =================
__global__ __launch_bounds__(256) void k_s(const float* __restrict__ a) {
    const int row = blockIdx.x;
    const int t   = threadIdx.x;
    float v  = g_Wh[(size_t)row * 256 + t];
    float p1 = v * a[t];
    float p2 = v * a[256 + t];
#pragma unroll
    for (int o = 16; o; o >>= 1) {
        p1 += __shfl_down_sync(0xffffffffu, p1, o);
        p2 += __shfl_down_sync(0xffffffffu, p2, o);
    }
    __shared__ float r1[8], r2[8];
    if ((t & 31) == 0) { r1[t >> 5] = p1; r2[t >> 5] = p2; }
    __syncthreads();
    if (t == 0) {
        float s1 = 0.f, s2 = 0.f;
#pragma unroll
        for (int w = 0; w < 8; w++) { s1 += r1[w]; s2 += r2[w]; }
        g_s1[row] = s1;
        g_s2[row] = s2;
    }
}

// ================= K3: per-row softmax stats (m, 1/l) =================
__global__ __launch_bounds__(256) void k_ml(const int* __restrict__ adj) {
    const int gwarp = (blockIdx.x * blockDim.x + threadIdx.x) >> 5;
    const int lane  = threadIdx.x & 31;
    if (gwarp >= ROWS) return;
    const int b = gwarp >> 11;
    const float  s1   = g_s1[gwarp];
    const int*   arow = adj + (size_t)gwarp * NNODE;
    const float* s2p  = g_s2 + (size_t)b * NNODE;

    float m = -INFINITY, l = 0.f;
    for (int j = lane; j < NNODE; j += 32) {
        float x = s1 + s2p[j];
        float e = (x > 0.f) ? x : ALPHA_LR * x;
        e = (arow[j] > 0) ? e : NEG_BIG;
        if (e > m) { l = l * __expf(m - e) + 1.f; m = e; }
        else       { l += __expf(e - m); }
    }
#pragma unroll
    for (int o = 16; o; o >>= 1) {
        float m2 = __shfl_down_sync(0xffffffffu, m, o);
        float l2 = __shfl_down_sync(0xffffffffu, l, o);
        float M  = fmaxf(m, m2);
        l = l * __expf(m - M) + l2 * __expf(m2 - M);
        m = M;
    }
    if (lane == 0) { g_m[gwarp] = m; g_li[gwarp] = 1.f / l; }
}

// ======== K3b: transpose + bf16 hi/lo split:  WhT[b][f][j] ========
__global__ __launch_bounds__(256) void k_tr() {
    __shared__ float tile[32][33];
    const int b  = blockIdx.z;
    const int j0 = blockIdx.x * 32;
    const int f0 = blockIdx.y * 32;
    const int tx = threadIdx.x & 31;
    const int ty = threadIdx.x >> 5;   // 0..7
#pragma unroll
    for (int k = 0; k < 4; k++) {
        int j = j0 + ty + k * 8;
        tile[ty + k * 8][tx] = g_Wh[((size_t)(b * NNODE + j)) * 256 + f0 + tx];
    }
    __syncthreads();
#pragma unroll
    for (int k = 0; k < 4; k++) {
        int f = f0 + ty + k * 8;
        float w = tile[tx][ty + k * 8];
        __nv_bfloat16 hi = __float2bfloat16(w);
        __nv_bfloat16 lo = __float2bfloat16(w - __bfloat162float(hi));
        size_t o = (((size_t)(b * FEAT + f)) << 11) + j0 + tx;
        g_WhT_hi[o] = hi;
        g_WhT_lo[o] = lo;
    }
}

// ================= K4: attention @ Wh + ELU =================
// TC path: SS-mode bf16 tcgen05 MMA, 2-stage pipelined.
//   Dynamic SMEM: P[2 buf][hi/lo 16KB each] = 64KB, B[2 buf][hi/lo 32KB] = 128KB.
//   P tile: 128 rows x 64 j bf16, K-major SW128 (128B rows).
//   B tile: 4 chunks x 64 n x 64 k bf16 SW128, hi then lo.
//   TMEM: D cols 0..255 fp32.
// Fallback (non-sm_103a compile): f32x2 register GEMM.
#define P_BUF_BYTES 32768            // hi 16K + lo 16K
#define B_BUF_BYTES 65536            // hi 32K + lo 32K
#define SMEM_DYN    (2 * P_BUF_BYTES + 2 * B_BUF_BYTES + 1024)   // 197632
__global__ __launch_bounds__(256, 1) void k_attn_tc(const int* __restrict__ adj,
                                                    float* __restrict__ out) {
    extern __shared__ char smraw[];
    __shared__ float s1S[128], mS[128], liS[128];

    const int t   = threadIdx.x;
    const int b   = blockIdx.y;
    const int i0  = blockIdx.x * 128;
    const int rowbase = b * NNODE + i0;

    if (t < 128) {
        s1S[t] = g_s1[rowbase + t];
        mS [t] = g_m [rowbase + t];
        liS[t] = g_li[rowbase + t];
    }

#if HAS_TC
    // ================== pipelined tcgen05 SS path ==================
    __shared__ uint32_t tmem_ptr_s;
    __shared__ __align__(8) unsigned long long mbar_s[2];

    char* smP = (char*)(((uintptr_t)smraw + 1023) & ~(uintptr_t)1023);
    char* smB = smP + 2 * P_BUF_BYTES;
    const uint32_t smP_u  = smem_u32(smP);
    const uint32_t smB_u  = smem_u32(smB);
    const uint32_t mbar_u = smem_u32(&mbar_s[0]);
    const uint32_t tptr_u = smem_u32(&tmem_ptr_s);
    const int wid = t >> 5;

    if (wid == 0) TC_ALLOC(tptr_u, 256);
    if (t == 0) { MBAR_INIT(mbar_u, 1); MBAR_INIT(mbar_u + 8, 1); }
    __syncthreads();
    uint32_t tmem;
    asm volatile("ld.shared.b32 %0, [%1];" : "=r"(tmem) : "r"(tptr_u));

    // per-thread produce indices
    const int pr  = t & 127;          // P row
    const int phj = t >> 7;           // j half (32 j)

    int phase[2] = {0, 0};

    for (int t32 = 0; t32 < NNODE / 64; t32++) {
        const int buf = t32 & 1;
        const int j0  = t32 * 64;
        if (t32 >= 2) {               // buffer free once its prior MMA finished
            MBAR_WAIT(mbar_u + 8 * buf, phase[buf]);
            phase[buf] ^= 1;
        }

        // ---- produce P tile (all 256 threads; thread = (row, 32-j half))
        {
            char* dstH = smP + buf * P_BUF_BYTES;
            char* dstL = dstH + 16384;
            const int4*   ar  = (const int4*)&adj[(size_t)(rowbase + pr) * NNODE + j0 + phj * 32];
            const float4* s2p = (const float4*)&g_s2[b * NNODE + j0 + phj * 32];
            const float s1v = s1S[pr], mv = mS[pr], lv = liS[pr];
#pragma unroll
            for (int q = 0; q < 4; q++) {         // 8 j each
                int4   a0 = ar[q * 2],  a1 = ar[q * 2 + 1];
                float4 q0 = s2p[q * 2], q1 = s2p[q * 2 + 1];
                float xs[8] = {q0.x, q0.y, q0.z, q0.w, q1.x, q1.y, q1.z, q1.w};
                int   av[8] = {a0.x, a0.y, a0.z, a0.w, a1.x, a1.y, a1.z, a1.w};
                uint32_t hv[4], lvv[4];
#pragma unroll
                for (int i = 0; i < 4; i++) {
                    float p2v[2], l2v[2];
#pragma unroll
                    for (int k = 0; k < 2; k++) {
                        float x = s1v + xs[i * 2 + k];
                        float e = (x > 0.f) ? x : ALPHA_LR * x;
                        e = (av[i * 2 + k] > 0) ? e : NEG_BIG;
                        float p = __expf(e - mv) * lv;
                        __nv_bfloat16 hb = __float2bfloat16(p);
                        float hr = __bfloat162float(hb);
                        p2v[k] = hr;
                        l2v[k] = p - hr;
                    }
                    __nv_bfloat162 h2 = __floats2bfloat162_rn(p2v[0], p2v[1]);
                    __nv_bfloat162 l2 = __floats2bfloat162_rn(l2v[0], l2v[1]);
                    hv[i]  = *(uint32_t*)&h2;
                    lvv[i] = *(uint32_t*)&l2;
                }
                uint32_t byteoff = SWZ128((uint32_t)(pr * 128 + phj * 64 + q * 16));
                *(uint4*)(dstH + byteoff) = make_uint4(hv[0], hv[1], hv[2], hv[3]);
                *(uint4*)(dstL + byteoff) = make_uint4(lvv[0], lvv[1], lvv[2], lvv[3]);
            }
        }
        // ---- produce B tile (all 256 threads, 16 x uint4 each)
        {
            char* dstB = smB + buf * B_BUF_BYTES;
#pragma unroll
            for (int i = 0; i < 16; i++) {
                int idx   = t + i * 256;
                int k4    = idx & 7;
                int n     = (idx >> 3) & 63;
                int chunk = (idx >> 9) & 3;
                int half  = (idx >> 11) & 1;
                const __nv_bfloat16* src = half ? g_WhT_lo : g_WhT_hi;
                uint4 v = *(const uint4*)&src[(((size_t)(b * FEAT + chunk * 64 + n)) << 11) + j0 + k4 * 8];
                uint32_t off = (uint32_t)(half * 32768 + chunk * 8192)
                             + SWZ128((uint32_t)(n * 128 + k4 * 16));
                *(uint4*)(dstB + off) = v;
            }
        }
        FENCE_ASYNC_SH();
        __syncthreads();

        // ---- issue MMAs for this tile (no wait — drains while next produce runs)
        if (wid == 0) {
            if (elect1()) {
                const uint32_t pbase = smP_u + buf * P_BUF_BYTES;
                const uint32_t bbase = smB_u + buf * B_BUF_BYTES;
                // terms: 0 = P_hi*W_hi, 1 = P_lo*W_hi, 2 = P_hi*W_lo
#pragma unroll
                for (int term = 0; term < 3; term++) {
                    const uint64_t ad = kdesc(pbase + ((term == 1) ? 16384u : 0u));
                    const uint32_t wh = (term == 2) ? 32768u : 0u;
#pragma unroll
                    for (int chunk = 0; chunk < 4; chunk++) {
                        const uint64_t bd = kdesc(bbase + wh + chunk * 8192);
                        const uint32_t dtm = tmem + chunk * 64;
#pragma unroll
                        for (int ks = 0; ks < 4; ks++) {
                            uint32_t en = (t32 != 0) | (term != 0) | (ks != 0);
                            mma_f16_ss(dtm, ad + ks * 2, bd + ks * 2, IDESC_F16, en);
                        }
                    }
                }
                TC_COMMIT(mbar_u + 8 * buf);
            }
        }
    }

    // drain the last two tiles
    MBAR_WAIT(mbar_u,     phase[0]);
    MBAR_WAIT(mbar_u + 8, phase[1]);
    TC_FENCE_AFTER();

    // ---- epilogue: LDTM, ELU, store
    if (t < 128) {
        const size_t rowoff = (size_t)(rowbase + t) * 256;
#pragma unroll
        for (int base = 0; base < 256; base += 32) {
            uint32_t d[32];
            TC_LD_X32(d, tmem + base);
            TC_WAIT_LD();
#pragma unroll
            for (int q = 0; q < 8; q++) {
                float v0 = __uint_as_float(d[q * 4 + 0]);
                float v1 = __uint_as_float(d[q * 4 + 1]);
                float v2 = __uint_as_float(d[q * 4 + 2]);
                float v3 = __uint_as_float(d[q * 4 + 3]);
                float4 o;
                o.x = (v0 > 0.f) ? v0 : expm1f(v0);
                o.y = (v1 > 0.f) ? v1 : expm1f(v1);
                o.z = (v2 > 0.f) ? v2 : expm1f(v2);
                o.w = (v3 > 0.f) ? v3 : expm1f(v3);
                *(float4*)&out[rowoff + base + q * 4] = o;
            }
        }
    }
    __syncthreads();
    if (t == 0) { MBAR_INVAL(mbar_u); MBAR_INVAL(mbar_u + 8); }
    __syncthreads();
    if (wid == 0) TC_DEALLOC(tmem, 256);

#else
    // ================== fallback: f32x2 register GEMM ==================
    float (*whS)[128] = (float (*)[128])smraw;           // 16x128 = 8 KB
    float (*pS)[128]  = (float (*)[128])(smraw + 8192);  // 16x128 = 8 KB

    const int tr = t >> 4, tc = t & 15;
    const int w_kk = t >> 4, w_f0 = (t & 15) * 8;
    const int p_r  = t >> 1, p_kq = (t & 1) * 8;

    for (int fb = 0; fb < 256; fb += 128) {
        unsigned long long acc[4][8];
#pragma unroll
        for (int i = 0; i < 4; i++)
#pragma unroll
            for (int c = 0; c < 8; c++) acc[i][c] = 0ull;

        for (int j0 = 0; j0 < NNODE; j0 += 16) {
            __syncthreads();
            {
                const float* src = &g_Wh[((size_t)(b * NNODE + j0 + w_kk)) * 256 + fb + w_f0];
                float4 v0 = *(const float4*)src;
                float4 v1 = *(const float4*)(src + 4);
                *(float4*)&whS[w_kk][w_f0]     = v0;
                *(float4*)&whS[w_kk][w_f0 + 4] = v1;
            }
            {
                const int* ar = &adj[((size_t)(rowbase + p_r)) * NNODE + j0 + p_kq];
                int4 a0 = *(const int4*)ar;
                int4 a1 = *(const int4*)(ar + 4);
                int av[8] = {a0.x, a0.y, a0.z, a0.w, a1.x, a1.y, a1.z, a1.w};
                float s1v = s1S[p_r], mv = mS[p_r], lv = liS[p_r];
                const float* s2p = &g_s2[b * NNODE + j0 + p_kq];
#pragma unroll
                for (int i = 0; i < 8; i++) {
                    float x = s1v + s2p[i];
                    float e = (x > 0.f) ? x : ALPHA_LR * x;
                    e = (av[i] > 0) ? e : NEG_BIG;
                    pS[p_kq + i][p_r] = __expf(e - mv) * lv;
                }
            }
            __syncthreads();

#pragma unroll 4
            for (int kk = 0; kk < 16; kk++) {
                ulonglong2 pA = *(const ulonglong2*)&pS[kk][tr * 4];
                ulonglong2 pB = *(const ulonglong2*)&pS[kk][64 + tr * 4];
                float4 wA = *(const float4*)&whS[kk][tc * 4];
                float4 wB = *(const float4*)&whS[kk][64 + tc * 4];
                unsigned long long w2[8];
                w2[0] = dup2(wA.x); w2[1] = dup2(wA.y);
                w2[2] = dup2(wA.z); w2[3] = dup2(wA.w);
                w2[4] = dup2(wB.x); w2[5] = dup2(wB.y);
                w2[6] = dup2(wB.z); w2[7] = dup2(wB.w);
#pragma unroll
                for (int c = 0; c < 8; c++) {
                    fma2(acc[0][c], pA.x, w2[c]);
                    fma2(acc[1][c], pA.y, w2[c]);
                    fma2(acc[2][c], pB.x, w2[c]);
                    fma2(acc[3][c], pB.y, w2[c]);
                }
            }
        }

#pragma unroll
        for (int ip = 0; ip < 4; ip++) {
            int rloc = (ip < 2) ? (tr * 4 + ip * 2) : (64 + tr * 4 + (ip - 2) * 2);
            float lo[8], hi[8];
#pragma unroll
            for (int c = 0; c < 8; c++) unpack2(acc[ip][c], lo[c], hi[c]);
#pragma unroll
            for (int h2 = 0; h2 < 2; h2++) {
                float* v = h2 ? hi : lo;
                size_t rowoff = ((size_t)(rowbase + rloc + h2)) * 256;
                float4 oA, oB;
                oA.x = (v[0] > 0.f) ? v[0] : expm1f(v[0]);
                oA.y = (v[1] > 0.f) ? v[1] : expm1f(v[1]);
                oA.z = (v[2] > 0.f) ? v[2] : expm1f(v[2]);
                oA.w = (v[3] > 0.f) ? v[3] : expm1f(v[3]);
                oB.x = (v[4] > 0.f) ? v[4] : expm1f(v[4]);
                oB.y = (v[5] > 0.f) ? v[5] : expm1f(v[5]);
                oB.z = (v[6] > 0.f) ? v[6] : expm1f(v[6]);
                oB.w = (v[7] > 0.f) ? v[7] : expm1f(v[7]);
                *(float4*)&out[rowoff + fb + tc * 4]      = oA;
                *(float4*)&out[rowoff + fb + 64 + tc * 4] = oB;
            }
        }
    }
#endif
}

// ================= launcher =================
extern "C" void kernel_launch(void* const* d_in, const int* in_sizes, int n_in,
                              void* d_out, int out_size) {
    const float* h   = (const float*)d_in[0];   // (8,2048,256) f32
    const int*   adj = (const int*)  d_in[1];   // (8,2048,2048) i32
    const float* W   = (const float*)d_in[2];   // (256,256) f32
    const float* a   = (const float*)d_in[3];   // (512,1) f32
    float* out = (float*)d_out;                 // (8,2048,256) f32

    cudaFuncSetAttribute(k_attn_tc, cudaFuncAttributeMaxDynamicSharedMemorySize,
                         SMEM_DYN);

    k_gemm<<<dim3(4, 256), 256>>>(h, W);
    k_s   <<<ROWS, 256>>>(a);
    k_ml  <<<ROWS / 8, 256>>>(adj);
    k_tr  <<<dim3(NNODE / 32, FEAT / 32, BATCH), 256>>>();
    k_attn_tc<<<dim3(NNODE / 128, BATCH), 256, SMEM_DYN>>>(adj, out);
}

// round 7
// speedup vs baseline: 2.6249x; 2.0000x over previous
#include <cuda_runtime.h>
#include <cuda_bf16.h>
#include <math.h>
#include <stdint.h>

#define BATCH 8
#define NNODE 2048
#define FEAT  256
#define ROWS  (BATCH * NNODE)   // 16384
#define ALPHA_LR 0.2f
#define NEG_BIG  -9.0e15f

#if defined(__CUDA_ARCH_FEAT_SM103_ALL) || defined(__CUDA_ARCH_FEAT_SM100_ALL)
#define HAS_TC 1
#else
#define HAS_TC 0
#endif

// -------- scratch (device globals; no allocation allowed) --------
__device__ float g_Wh[(size_t)ROWS * FEAT];                      // 16 MB fp32
__device__ __nv_bfloat16 g_WhT_hi[(size_t)BATCH * FEAT * NNODE]; // 8 MB  Wh^T hi
__device__ __nv_bfloat16 g_WhT_lo[(size_t)BATCH * FEAT * NNODE]; // 8 MB  Wh^T lo
__device__ float g_s1[ROWS];
__device__ float g_s2[ROWS];
__device__ float g_m [ROWS];
__device__ float g_li[ROWS];

// ======================= helpers =======================
__device__ __forceinline__ uint32_t smem_u32(const void* p) {
    uint32_t a;
    asm("{ .reg .u64 t; cvta.to.shared.u64 t, %1; cvt.u32.u64 %0, t; }"
        : "=r"(a) : "l"(p));
    return a;
}
// packed fp32x2 (used by fallback path)
__device__ __forceinline__ void fma2(unsigned long long& d,
                                     unsigned long long a,
                                     unsigned long long b) {
    asm("fma.rn.f32x2 %0, %1, %2, %0;" : "+l"(d) : "l"(a), "l"(b));
}
__device__ __forceinline__ unsigned long long dup2(float w) {
    unsigned long long r;
    asm("mov.b64 %0, {%1, %1};" : "=l"(r) : "f"(w));
    return r;
}
__device__ __forceinline__ void unpack2(unsigned long long v, float& lo, float& hi) {
    asm("mov.b64 {%0, %1}, %2;" : "=f"(lo), "=f"(hi) : "l"(v));
}
// cp.async 16B (sm_80+, safe in all compile passes)
__device__ __forceinline__ void cp_async16(uint32_t dst, const void* src) {
    asm volatile("cp.async.cg.shared.global [%0], [%1], 16;" :: "r"(dst), "l"(src));
}
#define CP_COMMIT() asm volatile("cp.async.commit_group;" ::: "memory")
#define CP_WAIT0()  asm volatile("cp.async.wait_group 0;" ::: "memory")

#if HAS_TC
__device__ __forceinline__ uint32_t elect1() {
    uint32_t p;
    asm volatile("{ .reg .pred p; elect.sync _|p, 0xFFFFFFFF; selp.b32 %0,1,0,p; }"
                 : "=r"(p));
    return p;
}
#define TC_ALLOC(sm, n)   asm volatile("tcgen05.alloc.cta_group::1.sync.aligned.shared::cta.b32 [%0], %1;" :: "r"(sm), "r"(n) : "memory")
#define TC_DEALLOC(t, n)  asm volatile("tcgen05.dealloc.cta_group::1.sync.aligned.b32 %0, %1;" :: "r"(t), "r"(n))
#define TC_WAIT_LD()      asm volatile("tcgen05.wait::ld.sync.aligned;" ::: "memory")
#define TC_FENCE_AFTER()  asm volatile("tcgen05.fence::after_thread_sync;" ::: "memory")
#define FENCE_ASYNC_SH()  asm volatile("fence.proxy.async.shared::cta;" ::: "memory")
#define TC_COMMIT(mb)     asm volatile("tcgen05.commit.cta_group::1.mbarrier::arrive::one.shared::cluster.b64 [%0];" :: "r"(mb) : "memory")
#define MBAR_INIT(mb, c)  asm volatile("mbarrier.init.shared.b64 [%0], %1;" :: "r"(mb), "r"(c) : "memory")
#define MBAR_INVAL(mb)    asm volatile("mbarrier.inval.shared.b64 [%0];" :: "r"(mb) : "memory")

#define MBAR_WAIT(mb, ph) do {                                                   \
    uint32_t _mb = (mb); uint32_t _ph = (ph); uint32_t _done;                    \
    asm volatile("{ .reg .pred p; mbarrier.try_wait.parity.acquire.cta.shared::cta.b64 p, [%1], %2; selp.b32 %0,1,0,p; }" \
                 : "=r"(_done) : "r"(_mb), "r"(_ph) : "memory");                 \
    if (!_done) {                                                                \
        asm volatile("{ .reg .pred P1; WL_%=: mbarrier.try_wait.parity.acquire.cta.shared::cta.b64 P1, [%0], %1, 0x989680; @P1 bra.uni WD_%=; bra.uni WL_%=; WD_%=: }" \
                     :: "r"(_mb), "r"(_ph) : "memory");                          \
    }                                                                            \
} while (0)

#define TC_LD_X32(r, tm)                                                         \
    asm volatile("tcgen05.ld.sync.aligned.32x32b.x32.b32 "                       \
        "{%0,%1,%2,%3,%4,%5,%6,%7,%8,%9,%10,%11,%12,%13,%14,%15,"                \
        "%16,%17,%18,%19,%20,%21,%22,%23,%24,%25,%26,%27,%28,%29,%30,%31}, [%32];" \
        : "=r"((r)[0]),  "=r"((r)[1]),  "=r"((r)[2]),  "=r"((r)[3]),             \
          "=r"((r)[4]),  "=r"((r)[5]),  "=r"((r)[6]),  "=r"((r)[7]),             \
          "=r"((r)[8]),  "=r"((r)[9]),  "=r"((r)[10]), "=r"((r)[11]),            \
          "=r"((r)[12]), "=r"((r)[13]), "=r"((r)[14]), "=r"((r)[15]),            \
          "=r"((r)[16]), "=r"((r)[17]), "=r"((r)[18]), "=r"((r)[19]),            \
          "=r"((r)[20]), "=r"((r)[21]), "=r"((r)[22]), "=r"((r)[23]),            \
          "=r"((r)[24]), "=r"((r)[25]), "=r"((r)[26]), "=r"((r)[27]),            \
          "=r"((r)[28]), "=r"((r)[29]), "=r"((r)[30]), "=r"((r)[31])             \
        : "r"(tm))

// SS-mode bf16 MMA: A and B both via SMEM descriptors
__device__ __forceinline__ void mma_f16_ss(uint32_t d, uint64_t adesc, uint64_t bdesc,
                                           uint32_t idesc, uint32_t en) {
    asm volatile("{ .reg .pred p; setp.ne.u32 p, %4, 0;\n\t"
        "tcgen05.mma.cta_group::1.kind::f16 [%0], %1, %2, %3, {%5,%5,%5,%5}, p;\n\t}"
        :: "r"(d), "l"(adesc), "l"(bdesc), "r"(idesc), "r"(en), "r"(0u) : "memory");
}

// idesc kind::f16: dtype=F32, atype=btype=BF16, N=64, M=128
#define IDESC_F16 ((1u << 4) | (1u << 7) | (1u << 10) | (8u << 17) | (8u << 24))
#endif // HAS_TC

#define SWZ128(x) ((x) ^ (((x) >> 3) & 0x70))
#if HAS_TC
// K-major SW128 descriptor base: layout=2, version=1, SBO=64, LBO=1
__device__ __forceinline__ uint64_t kdesc(uint32_t addr) {
    const uint64_t base = (uint64_t(2) << 61) | (uint64_t(1) << 46)
                        | (uint64_t(64) << 32) | (uint64_t(1) << 16);
    return base | ((uint64_t)(addr >> 4) & 0x3FFF);
}
#endif

// ================= K1: Wh = h @ W  (fp32 SIMT) =================
__global__ __launch_bounds__(256) void k_gemm(const float* __restrict__ A,
                                              const float* __restrict__ B) {
    __shared__ float As[16][64];
    __shared__ float Bs[16][64];
    const int m0 = blockIdx.y * 64;
    const int n0 = blockIdx.x * 64;
    const int t  = threadIdx.x;
    const int ty = t >> 4, tx = t & 15;

    float acc[4][4];
#pragma unroll
    for (int i = 0; i < 4; i++)
#pragma unroll
        for (int j = 0; j < 4; j++) acc[i][j] = 0.f;

    for (int k0 = 0; k0 < 256; k0 += 16) {
        {
            int i  = t >> 2, kq = t & 3;
            float4 v = *(const float4*)&A[(size_t)(m0 + i) * 256 + k0 + kq * 4];
            As[kq * 4 + 0][i] = v.x; As[kq * 4 + 1][i] = v.y;
            As[kq * 4 + 2][i] = v.z; As[kq * 4 + 3][i] = v.w;
        }
        {
            int kk = t >> 4, j4 = t & 15;
            float4 v = *(const float4*)&B[(size_t)(k0 + kk) * 256 + n0 + j4 * 4];
            Bs[kk][j4 * 4 + 0] = v.x; Bs[kk][j4 * 4 + 1] = v.y;
            Bs[kk][j4 * 4 + 2] = v.z; Bs[kk][j4 * 4 + 3] = v.w;
        }
        __syncthreads();
#pragma unroll
        for (int kk = 0; kk < 16; kk++) {
            float a[4], b[4];
#pragma unroll
            for (int x = 0; x < 4; x++) { a[x] = As[kk][ty * 4 + x]; b[x] = Bs[kk][tx * 4 + x]; }
#pragma unroll
            for (int i = 0; i < 4; i++)
#pragma unroll
                for (int j = 0; j < 4; j++) acc[i][j] = fmaf(a[i], b[j], acc[i][j]);
        }
        __syncthreads();
    }
#pragma unroll
    for (int i = 0; i < 4; i++) {
        int row = m0 + ty * 4 + i;
#pragma unroll
        for (int j = 0; j < 4; j++)
            g_Wh[(size_t)row * 256 + n0 + tx * 4 + j] = acc[i][j];
    }
}

// ================= K2: s1/s2 row dot products =================
__global__ __launch_bounds__(256) void k_s(const float* __restrict__ a) {
    const int row = blockIdx.x;
    const int t   = threadIdx.x;
    float v  = g_Wh[(size_t)row * 256 + t];
    float p1 = v * a[t];
    float p2 = v * a[256 + t];
#pragma unroll
    for (int o = 16; o; o >>= 1) {
        p1 += __shfl_down_sync(0xffffffffu, p1, o);
        p2 += __shfl_down_sync(0xffffffffu, p2, o);
    }
    __shared__ float r1[8], r2[8];
    if ((t & 31) == 0) { r1[t >> 5] = p1; r2[t >> 5] = p2; }
    __syncthreads();
    if (t == 0) {
        float s1 = 0.f, s2 = 0.f;
#pragma unroll
        for (int w = 0; w < 8; w++) { s1 += r1[w]; s2 += r2[w]; }
        g_s1[row] = s1;
        g_s2[row] = s2;
    }
}

// ================= K3: per-row softmax stats (m, 1/l) =================
__global__ __launch_bounds__(256) void k_ml(const int* __restrict__ adj) {
    const int gwarp = (blockIdx.x * blockDim.x + threadIdx.x) >> 5;
    const int lane  = threadIdx.x & 31;
    if (gwarp >= ROWS) return;
    const int b = gwarp >> 11;
    const float  s1   = g_s1[gwarp];
    const int*   arow = adj + (size_t)gwarp * NNODE;
    const float* s2p  = g_s2 + (size_t)b * NNODE;

    float m = -INFINITY, l = 0.f;
    for (int j = lane; j < NNODE; j += 32) {
        float x = s1 + s2p[j];
        float e = (x > 0.f) ? x : ALPHA_LR * x;
        e = (arow[j] > 0) ? e : NEG_BIG;
        if (e > m) { l = l * __expf(m - e) + 1.f; m = e; }
        else       { l += __expf(e - m); }
    }
#pragma unroll
    for (int o = 16; o; o >>= 1) {
        float m2 = __shfl_down_sync(0xffffffffu, m, o);
        float l2 = __shfl_down_sync(0xffffffffu, l, o);
        float M  = fmaxf(m, m2);
        l = l * __expf(m - M) + l2 * __expf(m2 - M);
        m = M;
    }
    if (lane == 0) { g_m[gwarp] = m; g_li[gwarp] = 1.f / l; }
}

// ======== K3b: transpose + bf16 hi/lo split:  WhT[b][f][j] ========
__global__ __launch_bounds__(256) void k_tr() {
    __shared__ float tile[32][33];
    const int b  = blockIdx.z;
    const int j0 = blockIdx.x * 32;
    const int f0 = blockIdx.y * 32;
    const int tx = threadIdx.x & 31;
    const int ty = threadIdx.x >> 5;   // 0..7
#pragma unroll
    for (int k = 0; k < 4; k++) {
        int j = j0 + ty + k * 8;
        tile[ty + k * 8][tx] = g_Wh[((size_t)(b * NNODE + j)) * 256 + f0 + tx];
    }
    __syncthreads();
#pragma unroll
    for (int k = 0; k < 4; k++) {
        int f = f0 + ty + k * 8;
        float w = tile[tx][ty + k * 8];
        __nv_bfloat16 hi = __float2bfloat16(w);
        __nv_bfloat16 lo = __float2bfloat16(w - __bfloat162float(hi));
        size_t o = (((size_t)(b * FEAT + f)) << 11) + j0 + tx;
        g_WhT_hi[o] = hi;
        g_WhT_lo[o] = lo;
    }
}

// ================= K4: attention @ Wh + ELU =================
// TC path: SS-mode bf16 tcgen05 MMA, 2-stage pipelined, 512 threads.
//   P produce: warp -> 8 rows, lane -> 2 j  (adj LDG.64 coalesced).
//   B staging: cp.async 16B x8/thread, waited after P math.
//   P tile: 128 rows x 64 j bf16 K-major SW128 (hi 16K + lo 16K per buf).
//   B tile: 4 chunks x 64 n x 64 k bf16 SW128 (hi 32K + lo 32K per buf).
//   TMEM: D cols 0..255 fp32.
// Fallback (non-sm_103a compile): f32x2 register GEMM (threads 256-511 idle).
#define P_BUF_BYTES 32768
#define B_BUF_BYTES 65536
#define SMEM_DYN    (2 * P_BUF_BYTES + 2 * B_BUF_BYTES + 1024)   // 197632
__global__ __launch_bounds__(512, 1) void k_attn_tc(const int* __restrict__ adj,
                                                    float* __restrict__ out) {
    extern __shared__ char smraw[];
    __shared__ float s1S[128], mS[128], liS[128];

    const int t   = threadIdx.x;
    const int b   = blockIdx.y;
    const int i0  = blockIdx.x * 128;
    const int rowbase = b * NNODE + i0;

    if (t < 128) {
        s1S[t] = g_s1[rowbase + t];
        mS [t] = g_m [rowbase + t];
        liS[t] = g_li[rowbase + t];
    }

#if HAS_TC
    // ================== pipelined tcgen05 SS path ==================
    __shared__ uint32_t tmem_ptr_s;
    __shared__ __align__(8) unsigned long long mbar_s[2];

    char* smP = (char*)(((uintptr_t)smraw + 1023) & ~(uintptr_t)1023);
    char* smB = smP + 2 * P_BUF_BYTES;
    const uint32_t smP_u  = smem_u32(smP);
    const uint32_t smB_u  = smem_u32(smB);
    const uint32_t mbar_u = smem_u32(&mbar_s[0]);
    const uint32_t tptr_u = smem_u32(&tmem_ptr_s);
    const int wid  = t >> 5;
    const int lane = t & 31;

    if (wid == 0) TC_ALLOC(tptr_u, 256);
    if (t == 0) { MBAR_INIT(mbar_u, 1); MBAR_INIT(mbar_u + 8, 1); }
    __syncthreads();
    uint32_t tmem;
    asm volatile("ld.shared.b32 %0, [%1];" : "=r"(tmem) : "r"(tptr_u));

    int phase[2] = {0, 0};

    for (int t32 = 0; t32 < NNODE / 64; t32++) {
        const int buf = t32 & 1;
        const int j0  = t32 * 64;
        if (t32 >= 2) {               // buffer free once its prior MMA finished
            MBAR_WAIT(mbar_u + 8 * buf, phase[buf]);
            phase[buf] ^= 1;
        }

        // ---- kick off B staging first (cp.async, overlapped with P math)
        {
            const uint32_t dstB = smB_u + buf * B_BUF_BYTES;
#pragma unroll
            for (int i = 0; i < 8; i++) {
                int idx   = t + i * 512;
                int k4    = idx & 7;
                int n     = (idx >> 3) & 63;
                int chunk = (idx >> 9) & 3;
                int half  = (idx >> 11) & 1;
                const __nv_bfloat16* src = half ? g_WhT_lo : g_WhT_hi;
                const void* g = &src[(((size_t)(b * FEAT + chunk * 64 + n)) << 11) + j0 + k4 * 8];
                uint32_t off = (uint32_t)(half * 32768 + chunk * 8192)
                             + SWZ128((uint32_t)(n * 128 + k4 * 16));
                cp_async16(dstB + off, g);
            }
            CP_COMMIT();
        }

        // ---- produce P tile: warp -> 8 rows, lane -> 2 j (coalesced adj)
        {
            char* dstH = smP + buf * P_BUF_BYTES;
            char* dstL = dstH + 16384;
            float2 s2v = *(const float2*)&g_s2[b * NNODE + j0 + lane * 2];
#pragma unroll
            for (int r = 0; r < 8; r++) {
                const int row = wid * 8 + r;
                int2 av = *(const int2*)&adj[(size_t)(rowbase + row) * NNODE + j0 + lane * 2];
                const float s1v = s1S[row], mv = mS[row], lv = liS[row];
                float x0 = s1v + s2v.x;
                x0 = (x0 > 0.f) ? x0 : ALPHA_LR * x0;
                x0 = (av.x > 0) ? x0 : NEG_BIG;
                float x1 = s1v + s2v.y;
                x1 = (x1 > 0.f) ? x1 : ALPHA_LR * x1;
                x1 = (av.y > 0) ? x1 : NEG_BIG;
                float p0 = __expf(x0 - mv) * lv;
                float p1 = __expf(x1 - mv) * lv;
                __nv_bfloat16 h0 = __float2bfloat16(p0);
                __nv_bfloat16 h1 = __float2bfloat16(p1);
                float r0 = __bfloat162float(h0), r1 = __bfloat162float(h1);
                __nv_bfloat162 hh; hh.x = h0; hh.y = h1;
                __nv_bfloat162 ll = __floats2bfloat162_rn(p0 - r0, p1 - r1);
                uint32_t off = SWZ128((uint32_t)(row * 128 + lane * 4));
                *(uint32_t*)(dstH + off) = *(uint32_t*)&hh;
                *(uint32_t*)(dstL + off) = *(uint32_t*)&ll;
            }
        }

        CP_WAIT0();
        FENCE_ASYNC_SH();
        __syncthreads();

        // ---- issue MMAs (no wait — drains while next produce runs)
        if (wid == 0) {
            if (elect1()) {
                const uint32_t pbase = smP_u + buf * P_BUF_BYTES;
                const uint32_t bbase = smB_u + buf * B_BUF_BYTES;
                // terms: 0 = P_hi*W_hi, 1 = P_lo*W_hi, 2 = P_hi*W_lo
#pragma unroll
                for (int term = 0; term < 3; term++) {
                    const uint64_t ad = kdesc(pbase + ((term == 1) ? 16384u : 0u));
                    const uint32_t wh = (term == 2) ? 32768u : 0u;
#pragma unroll
                    for (int chunk = 0; chunk < 4; chunk++) {
                        const uint64_t bd = kdesc(bbase + wh + chunk * 8192);
                        const uint32_t dtm = tmem + chunk * 64;
#pragma unroll
                        for (int ks = 0; ks < 4; ks++) {
                            uint32_t en = (t32 != 0) | (term != 0) | (ks != 0);
                            mma_f16_ss(dtm, ad + ks * 2, bd + ks * 2, IDESC_F16, en);
                        }
                    }
                }
                TC_COMMIT(mbar_u + 8 * buf);
            }
        }
    }

    // drain the last two tiles
    MBAR_WAIT(mbar_u,     phase[0]);
    MBAR_WAIT(mbar_u + 8, phase[1]);
    TC_FENCE_AFTER();

    // ---- epilogue: LDTM over 8 warps, ELU, store
    if (wid < 8) {
        const int colbase = (wid >> 2) * 128;       // 0 or 128
        const int row = (wid & 3) * 32 + lane;      // warp's subpartition rows
        const size_t rowoff = (size_t)(rowbase + row) * 256;
#pragma unroll
        for (int cb = 0; cb < 128; cb += 32) {
            uint32_t d[32];
            TC_LD_X32(d, tmem + colbase + cb);
            TC_WAIT_LD();
#pragma unroll
            for (int q = 0; q < 8; q++) {
                float v0 = __uint_as_float(d[q * 4 + 0]);
                float v1 = __uint_as_float(d[q * 4 + 1]);
                float v2 = __uint_as_float(d[q * 4 + 2]);
                float v3 = __uint_as_float(d[q * 4 + 3]);
                float4 o;
                o.x = (v0 > 0.f) ? v0 : expm1f(v0);
                o.y = (v1 > 0.f) ? v1 : expm1f(v1);
                o.z = (v2 > 0.f) ? v2 : expm1f(v2);
                o.w = (v3 > 0.f) ? v3 : expm1f(v3);
                *(float4*)&out[rowoff + colbase + cb + q * 4] = o;
            }
        }
    }
    __syncthreads();
    if (t == 0) { MBAR_INVAL(mbar_u); MBAR_INVAL(mbar_u + 8); }
    __syncthreads();
    if (wid == 0) TC_DEALLOC(tmem, 256);

#else
    // ================== fallback: f32x2 register GEMM (threads 0-255 work) ==
    float (*whS)[128] = (float (*)[128])smraw;           // 16x128 = 8 KB
    float (*pS)[128]  = (float (*)[128])(smraw + 8192);  // 16x128 = 8 KB

    const int tr = t >> 4, tc = t & 15;
    const int w_kk = t >> 4, w_f0 = (t & 15) * 8;
    const int p_r  = t >> 1, p_kq = (t & 1) * 8;
    const bool act = (t < 256);

    for (int fb = 0; fb < 256; fb += 128) {
        unsigned long long acc[4][8];
#pragma unroll
        for (int i = 0; i < 4; i++)
#pragma unroll
            for (int c = 0; c < 8; c++) acc[i][c] = 0ull;

        for (int j0 = 0; j0 < NNODE; j0 += 16) {
            __syncthreads();
            if (act) {
                const float* src = &g_Wh[((size_t)(b * NNODE + j0 + w_kk)) * 256 + fb + w_f0];
                float4 v0 = *(const float4*)src;
                float4 v1 = *(const float4*)(src + 4);
                *(float4*)&whS[w_kk][w_f0]     = v0;
                *(float4*)&whS[w_kk][w_f0 + 4] = v1;

                const int* ar = &adj[((size_t)(rowbase + p_r)) * NNODE + j0 + p_kq];
                int4 a0 = *(const int4*)ar;
                int4 a1 = *(const int4*)(ar + 4);
                int av[8] = {a0.x, a0.y, a0.z, a0.w, a1.x, a1.y, a1.z, a1.w};
                float s1v = s1S[p_r], mv = mS[p_r], lv = liS[p_r];
                const float* s2p = &g_s2[b * NNODE + j0 + p_kq];
#pragma unroll
                for (int i = 0; i < 8; i++) {
                    float x = s1v + s2p[i];
                    float e = (x > 0.f) ? x : ALPHA_LR * x;
                    e = (av[i] > 0) ? e : NEG_BIG;
                    pS[p_kq + i][p_r] = __expf(e - mv) * lv;
                }
            }
            __syncthreads();

            if (act) {
#pragma unroll 4
                for (int kk = 0; kk < 16; kk++) {
                    ulonglong2 pA = *(const ulonglong2*)&pS[kk][tr * 4];
                    ulonglong2 pB = *(const ulonglong2*)&pS[kk][64 + tr * 4];
                    float4 wA = *(const float4*)&whS[kk][tc * 4];
                    float4 wB = *(const float4*)&whS[kk][64 + tc * 4];
                    unsigned long long w2[8];
                    w2[0] = dup2(wA.x); w2[1] = dup2(wA.y);
                    w2[2] = dup2(wA.z); w2[3] = dup2(wA.w);
                    w2[4] = dup2(wB.x); w2[5] = dup2(wB.y);
                    w2[6] = dup2(wB.z); w2[7] = dup2(wB.w);
#pragma unroll
                    for (int c = 0; c < 8; c++) {
                        fma2(acc[0][c], pA.x, w2[c]);
                        fma2(acc[1][c], pA.y, w2[c]);
                        fma2(acc[2][c], pB.x, w2[c]);
                        fma2(acc[3][c], pB.y, w2[c]);
                    }
                }
            }
        }

        if (act) {
#pragma unroll
            for (int ip = 0; ip < 4; ip++) {
                int rloc = (ip < 2) ? (tr * 4 + ip * 2) : (64 + tr * 4 + (ip - 2) * 2);
                float lo[8], hi[8];
#pragma unroll
                for (int c = 0; c < 8; c++) unpack2(acc[ip][c], lo[c], hi[c]);
#pragma unroll
                for (int h2 = 0; h2 < 2; h2++) {
                    float* v = h2 ? hi : lo;
                    size_t rowoff = ((size_t)(rowbase + rloc + h2)) * 256;
                    float4 oA, oB;
                    oA.x = (v[0] > 0.f) ? v[0] : expm1f(v[0]);
                    oA.y = (v[1] > 0.f) ? v[1] : expm1f(v[1]);
                    oA.z = (v[2] > 0.f) ? v[2] : expm1f(v[2]);
                    oA.w = (v[3] > 0.f) ? v[3] : expm1f(v[3]);
                    oB.x = (v[4] > 0.f) ? v[4] : expm1f(v[4]);
                    oB.y = (v[5] > 0.f) ? v[5] : expm1f(v[5]);
                    oB.z = (v[6] > 0.f) ? v[6] : expm1f(v[6]);
                    oB.w = (v[7] > 0.f) ? v[7] : expm1f(v[7]);
                    *(float4*)&out[rowoff + fb + tc * 4]      = oA;
                    *(float4*)&out[rowoff + fb + 64 + tc * 4] = oB;
                }
            }
        }
    }
#endif
}

// ================= launcher =================
extern "C" void kernel_launch(void* const* d_in, const int* in_sizes, int n_in,
                              void* d_out, int out_size) {
    const float* h   = (const float*)d_in[0];   // (8,2048,256) f32
    const int*   adj = (const int*)  d_in[1];   // (8,2048,2048) i32
    const float* W   = (const float*)d_in[2];   // (256,256) f32
    const float* a   = (const float*)d_in[3];   // (512,1) f32
    float* out = (float*)d_out;                 // (8,2048,256) f32

    cudaFuncSetAttribute(k_attn_tc, cudaFuncAttributeMaxDynamicSharedMemorySize,
                         SMEM_DYN);

    k_gemm<<<dim3(4, 256), 256>>>(h, W);
    k_s   <<<ROWS, 256>>>(a);
    k_ml  <<<ROWS / 8, 256>>>(adj);
    k_tr  <<<dim3(NNODE / 32, FEAT / 32, BATCH), 256>>>();
    k_attn_tc<<<dim3(NNODE / 128, BATCH), 512, SMEM_DYN>>>(adj, out);
}

// round 8
// speedup vs baseline: 3.0637x; 1.1671x over previous
#include <cuda_runtime.h>
#include <cuda_bf16.h>
#include <cuda_fp16.h>
#include <math.h>
#include <stdint.h>

#define BATCH 8
#define NNODE 2048
#define FEAT  256
#define ROWS  (BATCH * NNODE)   // 16384
#define ALPHA_LR 0.2f
#define NEG_BIG  -9.0e15f
#define L2E      1.4426950408889634f

#if defined(__CUDA_ARCH_FEAT_SM103_ALL) || defined(__CUDA_ARCH_FEAT_SM100_ALL)
#define HAS_TC 1
#else
#define HAS_TC 0
#endif

// -------- scratch (device globals; no allocation allowed) --------
__device__ float g_Wh[(size_t)ROWS * FEAT];                 // 16 MB fp32
__device__ __half g_WhT_hi[(size_t)BATCH * FEAT * NNODE];   // 8 MB  Wh^T hi (fp16)
__device__ __half g_WhT_lo[(size_t)BATCH * FEAT * NNODE];   // 8 MB  Wh^T lo (fp16)
__device__ uint32_t g_mask[(size_t)ROWS * (NNODE / 32)];    // 4.2 MB adj bitmask
__device__ float g_s1[ROWS];
__device__ float g_s2[ROWS];
__device__ float g_m [ROWS];
__device__ float g_li[ROWS];

// ======================= helpers =======================
__device__ __forceinline__ uint32_t smem_u32(const void* p) {
    uint32_t a;
    asm("{ .reg .u64 t; cvta.to.shared.u64 t, %1; cvt.u32.u64 %0, t; }"
        : "=r"(a) : "l"(p));
    return a;
}
// packed fp32x2 (used by fallback path)
__device__ __forceinline__ void fma2(unsigned long long& d,
                                     unsigned long long a,
                                     unsigned long long b) {
    asm("fma.rn.f32x2 %0, %1, %2, %0;" : "+l"(d) : "l"(a), "l"(b));
}
__device__ __forceinline__ unsigned long long dup2(float w) {
    unsigned long long r;
    asm("mov.b64 %0, {%1, %1};" : "=l"(r) : "f"(w));
    return r;
}
__device__ __forceinline__ void unpack2(unsigned long long v, float& lo, float& hi) {
    asm("mov.b64 {%0, %1}, %2;" : "=f"(lo), "=f"(hi) : "l"(v));
}
// cp.async 16B (sm_80+, safe in all compile passes)
__device__ __forceinline__ void cp_async16(uint32_t dst, const void* src) {
    asm volatile("cp.async.cg.shared.global [%0], [%1], 16;" :: "r"(dst), "l"(src));
}
#define CP_COMMIT() asm volatile("cp.async.commit_group;" ::: "memory")
#define CP_WAIT0()  asm volatile("cp.async.wait_group 0;" ::: "memory")

#if HAS_TC
__device__ __forceinline__ uint32_t elect1() {
    uint32_t p;
    asm volatile("{ .reg .pred p; elect.sync _|p, 0xFFFFFFFF; selp.b32 %0,1,0,p; }"
                 : "=r"(p));
    return p;
}
#define TC_ALLOC(sm, n)   asm volatile("tcgen05.alloc.cta_group::1.sync.aligned.shared::cta.b32 [%0], %1;" :: "r"(sm), "r"(n) : "memory")
#define TC_DEALLOC(t, n)  asm volatile("tcgen05.dealloc.cta_group::1.sync.aligned.b32 %0, %1;" :: "r"(t), "r"(n))
#define TC_WAIT_LD()      asm volatile("tcgen05.wait::ld.sync.aligned;" ::: "memory")
#define TC_FENCE_AFTER()  asm volatile("tcgen05.fence::after_thread_sync;" ::: "memory")
#define FENCE_ASYNC_SH()  asm volatile("fence.proxy.async.shared::cta;" ::: "memory")
#define TC_COMMIT(mb)     asm volatile("tcgen05.commit.cta_group::1.mbarrier::arrive::one.shared::cluster.b64 [%0];" :: "r"(mb) : "memory")
#define MBAR_INIT(mb, c)  asm volatile("mbarrier.init.shared.b64 [%0], %1;" :: "r"(mb), "r"(c) : "memory")
#define MBAR_INVAL(mb)    asm volatile("mbarrier.inval.shared.b64 [%0];" :: "r"(mb) : "memory")

#define MBAR_WAIT(mb, ph) do {                                                   \
    uint32_t _mb = (mb); uint32_t _ph = (ph); uint32_t _done;                    \
    asm volatile("{ .reg .pred p; mbarrier.try_wait.parity.acquire.cta.shared::cta.b64 p, [%1], %2; selp.b32 %0,1,0,p; }" \
                 : "=r"(_done) : "r"(_mb), "r"(_ph) : "memory");                 \
    if (!_done) {                                                                \
        asm volatile("{ .reg .pred P1; WL_%=: mbarrier.try_wait.parity.acquire.cta.shared::cta.b64 P1, [%0], %1, 0x989680; @P1 bra.uni WD_%=; bra.uni WL_%=; WD_%=: }" \
                     :: "r"(_mb), "r"(_ph) : "memory");                          \
    }                                                                            \
} while (0)

#define TC_LD_X32(r, tm)                                                         \
    asm volatile("tcgen05.ld.sync.aligned.32x32b.x32.b32 "                       \
        "{%0,%1,%2,%3,%4,%5,%6,%7,%8,%9,%10,%11,%12,%13,%14,%15,"                \
        "%16,%17,%18,%19,%20,%21,%22,%23,%24,%25,%26,%27,%28,%29,%30,%31}, [%32];" \
        : "=r"((r)[0]),  "=r"((r)[1]),  "=r"((r)[2]),  "=r"((r)[3]),             \
          "=r"((r)[4]),  "=r"((r)[5]),  "=r"((r)[6]),  "=r"((r)[7]),             \
          "=r"((r)[8]),  "=r"((r)[9]),  "=r"((r)[10]), "=r"((r)[11]),            \
          "=r"((r)[12]), "=r"((r)[13]), "=r"((r)[14]), "=r"((r)[15]),            \
          "=r"((r)[16]), "=r"((r)[17]), "=r"((r)[18]), "=r"((r)[19]),            \
          "=r"((r)[20]), "=r"((r)[21]), "=r"((r)[22]), "=r"((r)[23]),            \
          "=r"((r)[24]), "=r"((r)[25]), "=r"((r)[26]), "=r"((r)[27]),            \
          "=r"((r)[28]), "=r"((r)[29]), "=r"((r)[30]), "=r"((r)[31])             \
        : "r"(tm))

// SS-mode fp16 MMA: A and B both via SMEM descriptors
__device__ __forceinline__ void mma_f16_ss(uint32_t d, uint64_t adesc, uint64_t bdesc,
                                           uint32_t idesc, uint32_t en) {
    asm volatile("{ .reg .pred p; setp.ne.u32 p, %4, 0;\n\t"
        "tcgen05.mma.cta_group::1.kind::f16 [%0], %1, %2, %3, {%5,%5,%5,%5}, p;\n\t}"
        :: "r"(d), "l"(adesc), "l"(bdesc), "r"(idesc), "r"(en), "r"(0u) : "memory");
}

// idesc kind::f16: dtype=F32, atype=btype=FP16(0), N=64, M=128
#define IDESC_FP16 ((1u << 4) | (8u << 17) | (8u << 24))
#endif // HAS_TC

#define SWZ128(x) ((x) ^ (((x) >> 3) & 0x70))
#if HAS_TC
// K-major SW128 descriptor base: layout=2, version=1, SBO=64, LBO=1
__device__ __forceinline__ uint64_t kdesc(uint32_t addr) {
    const uint64_t base = (uint64_t(2) << 61) | (uint64_t(1) << 46)
                        | (uint64_t(64) << 32) | (uint64_t(1) << 16);
    return base | ((uint64_t)(addr >> 4) & 0x3FFF);
}
#endif

// ================= K1: Wh = h @ W  (fp32 SIMT) =================
__global__ __launch_bounds__(256) void k_gemm(const float* __restrict__ A,
                                              const float* __restrict__ B) {
    __shared__ float As[16][64];
    __shared__ float Bs[16][64];
    const int m0 = blockIdx.y * 64;
    const int n0 = blockIdx.x * 64;
    const int t  = threadIdx.x;
    const int ty = t >> 4, tx = t & 15;

    float acc[4][4];
#pragma unroll
    for (int i = 0; i < 4; i++)
#pragma unroll
        for (int j = 0; j < 4; j++) acc[i][j] = 0.f;

    for (int k0 = 0; k0 < 256; k0 += 16) {
        {
            int i  = t >> 2, kq = t & 3;
            float4 v = *(const float4*)&A[(size_t)(m0 + i) * 256 + k0 + kq * 4];
            As[kq * 4 + 0][i] = v.x; As[kq * 4 + 1][i] = v.y;
            As[kq * 4 + 2][i] = v.z; As[kq * 4 + 3][i] = v.w;
        }
        {
            int kk = t >> 4, j4 = t & 15;
            float4 v = *(const float4*)&B[(size_t)(k0 + kk) * 256 + n0 + j4 * 4];
            Bs[kk][j4 * 4 + 0] = v.x; Bs[kk][j4 * 4 + 1] = v.y;
            Bs[kk][j4 * 4 + 2] = v.z; Bs[kk][j4 * 4 + 3] = v.w;
        }
        __syncthreads();
#pragma unroll
        for (int kk = 0; kk < 16; kk++) {
            float a[4], b[4];
#pragma unroll
            for (int x = 0; x < 4; x++) { a[x] = As[kk][ty * 4 + x]; b[x] = Bs[kk][tx * 4 + x]; }
#pragma unroll
            for (int i = 0; i < 4; i++)
#pragma unroll
                for (int j = 0; j < 4; j++) acc[i][j] = fmaf(a[i], b[j], acc[i][j]);
        }
        __syncthreads();
    }
#pragma unroll
    for (int i = 0; i < 4; i++) {
        int row = m0 + ty * 4 + i;
#pragma unroll
        for (int j = 0; j < 4; j++)
            g_Wh[(size_t)row * 256 + n0 + tx * 4 + j] = acc[i][j];
    }
}

// ================= K2: s1/s2 row dot products =================
__global__ __launch_bounds__(256) void k_s(const float* __restrict__ a) {
    const int row = blockIdx.x;
    const int t   = threadIdx.x;
    float v  = g_Wh[(size_t)row * 256 + t];
    float p1 = v * a[t];
    float p2 = v * a[256 + t];
#pragma unroll
    for (int o = 16; o; o >>= 1) {
        p1 += __shfl_down_sync(0xffffffffu, p1, o);
        p2 += __shfl_down_sync(0xffffffffu, p2, o);
    }
    __shared__ float r1[8], r2[8];
    if ((t & 31) == 0) { r1[t >> 5] = p1; r2[t >> 5] = p2; }
    __syncthreads();
    if (t == 0) {
        float s1 = 0.f, s2 = 0.f;
#pragma unroll
        for (int w = 0; w < 8; w++) { s1 += r1[w]; s2 += r2[w]; }
        g_s1[row] = s1;
        g_s2[row] = s2;
    }
}

// ========== K3: per-row softmax stats (m, 1/l) + adj bitmask ==========
__global__ __launch_bounds__(256) void k_ml(const int* __restrict__ adj) {
    const int gwarp = (blockIdx.x * blockDim.x + threadIdx.x) >> 5;
    const int lane  = threadIdx.x & 31;
    if (gwarp >= ROWS) return;
    const int b = gwarp >> 11;
    const float  s1   = g_s1[gwarp];
    const int*   arow = adj + (size_t)gwarp * NNODE;
    const float* s2p  = g_s2 + (size_t)b * NNODE;
    uint32_t* mrow = &g_mask[(size_t)gwarp * (NNODE / 32)];

    float m = -INFINITY, l = 0.f;
    for (int it = 0; it < NNODE / 32; it++) {
        const int j = it * 32 + lane;
        const int av = arow[j];
        uint32_t w = __ballot_sync(0xffffffffu, av > 0);
        if (lane == 0) mrow[it] = w;
        float x = s1 + s2p[j];
        float e = (x > 0.f) ? x : ALPHA_LR * x;
        e = (av > 0) ? e : NEG_BIG;
        if (e > m) { l = l * __expf(m - e) + 1.f; m = e; }
        else       { l += __expf(e - m); }
    }
#pragma unroll
    for (int o = 16; o; o >>= 1) {
        float m2 = __shfl_down_sync(0xffffffffu, m, o);
        float l2 = __shfl_down_sync(0xffffffffu, l, o);
        float M  = fmaxf(m, m2);
        l = l * __expf(m - M) + l2 * __expf(m2 - M);
        m = M;
    }
    if (lane == 0) { g_m[gwarp] = m; g_li[gwarp] = 1.f / l; }
}

// ======== K3b: transpose + fp16 hi/lo split:  WhT[b][f][j] ========
__global__ __launch_bounds__(256) void k_tr() {
    __shared__ float tile[32][33];
    const int b  = blockIdx.z;
    const int j0 = blockIdx.x * 32;
    const int f0 = blockIdx.y * 32;
    const int tx = threadIdx.x & 31;
    const int ty = threadIdx.x >> 5;   // 0..7
#pragma unroll
    for (int k = 0; k < 4; k++) {
        int j = j0 + ty + k * 8;
        tile[ty + k * 8][tx] = g_Wh[((size_t)(b * NNODE + j)) * 256 + f0 + tx];
    }
    __syncthreads();
#pragma unroll
    for (int k = 0; k < 4; k++) {
        int f = f0 + ty + k * 8;
        float w = tile[tx][ty + k * 8];
        __half hi = __float2half_rn(w);
        __half lo = __float2half_rn(w - __half2float(hi));
        size_t o = (((size_t)(b * FEAT + f)) << 11) + j0 + tx;
        g_WhT_hi[o] = hi;
        g_WhT_lo[o] = lo;
    }
}

// ================= K4: attention @ Wh + ELU =================
// TC path: SS-mode fp16 tcgen05 MMA, 2-stage pipelined, 512 threads.
//   P: single fp16 tile (128 x 64), mask from g_mask bitwords.
//   W: fp16 hi/lo, 2 MMA terms (P*W_hi + P*W_lo), 32 MMAs/tile.
//   Row constants (s1, m*log2e, 1/l) hoisted to registers (8 rows/thread).
// Fallback (non-sm_103a compile): f32x2 register GEMM (threads 256-511 idle).
#define P_BUF_BYTES 16384
#define B_BUF_BYTES 65536
#define SMEM_DYN    (2 * P_BUF_BYTES + 2 * B_BUF_BYTES + 1024)   // 164864
__global__ __launch_bounds__(512, 1) void k_attn_tc(const int* __restrict__ adj,
                                                    float* __restrict__ out) {
    extern __shared__ char smraw[];
    __shared__ float s1S[128], mS[128], liS[128];

    const int t   = threadIdx.x;
    const int b   = blockIdx.y;
    const int i0  = blockIdx.x * 128;
    const int rowbase = b * NNODE + i0;

    if (t < 128) {
        s1S[t] = g_s1[rowbase + t];
        mS [t] = g_m [rowbase + t];
        liS[t] = g_li[rowbase + t];
    }

#if HAS_TC
    // ================== pipelined tcgen05 SS path ==================
    __shared__ uint32_t tmem_ptr_s;
    __shared__ __align__(8) unsigned long long mbar_s[2];

    char* smP = (char*)(((uintptr_t)smraw + 1023) & ~(uintptr_t)1023);
    char* smB = smP + 2 * P_BUF_BYTES;
    const uint32_t smP_u  = smem_u32(smP);
    const uint32_t smB_u  = smem_u32(smB);
    const uint32_t mbar_u = smem_u32(&mbar_s[0]);
    const uint32_t tptr_u = smem_u32(&tmem_ptr_s);
    const int wid  = t >> 5;
    const int lane = t & 31;

    if (wid == 0) TC_ALLOC(tptr_u, 256);
    if (t == 0) { MBAR_INIT(mbar_u, 1); MBAR_INIT(mbar_u + 8, 1); }
    __syncthreads();
    uint32_t tmem;
    asm volatile("ld.shared.b32 %0, [%1];" : "=r"(tmem) : "r"(tptr_u));

    // hoist row constants: this warp's 8 fixed rows
    float rs1[8], rm144[8], rli[8];
#pragma unroll
    for (int r = 0; r < 8; r++) {
        const int row = wid * 8 + r;
        rs1[r]   = s1S[row];
        rm144[r] = mS[row] * L2E;
        rli[r]   = liS[row];
    }
    // mask row pointers (word granularity): this thread's word column
    const uint32_t* mbase = &g_mask[(size_t)(rowbase + wid * 8) * (NNODE / 32) + (lane >> 4)];
    const int mbit = (lane * 2) & 31;

    int phase[2] = {0, 0};

    for (int t32 = 0; t32 < NNODE / 64; t32++) {
        const int buf = t32 & 1;
        const int j0  = t32 * 64;
        if (t32 >= 2) {               // buffer free once its prior MMA finished
            MBAR_WAIT(mbar_u + 8 * buf, phase[buf]);
            phase[buf] ^= 1;
        }

        // ---- kick off B staging first (cp.async, overlapped with P math)
        {
            const uint32_t dstB = smB_u + buf * B_BUF_BYTES;
#pragma unroll
            for (int i = 0; i < 8; i++) {
                int idx   = t + i * 512;
                int k4    = idx & 7;
                int n     = (idx >> 3) & 63;
                int chunk = (idx >> 9) & 3;
                int half  = (idx >> 11) & 1;
                const __half* src = half ? g_WhT_lo : g_WhT_hi;
                const void* g = &src[(((size_t)(b * FEAT + chunk * 64 + n)) << 11) + j0 + k4 * 8];
                uint32_t off = (uint32_t)(half * 32768 + chunk * 8192)
                             + SWZ128((uint32_t)(n * 128 + k4 * 16));
                cp_async16(dstB + off, g);
            }
            CP_COMMIT();
        }

        // ---- produce P tile: warp -> 8 rows, lane -> 2 j
        {
            char* dstP = smP + buf * P_BUF_BYTES;
            float2 s2v = *(const float2*)&g_s2[b * NNODE + j0 + lane * 2];
#pragma unroll
            for (int r = 0; r < 8; r++) {
                const int row = wid * 8 + r;
                const uint32_t w = mbase[(size_t)r * (NNODE / 32) + t32 * 2];
                float x0 = rs1[r] + s2v.x;
                float x1 = rs1[r] + s2v.y;
                x0 = fmaxf(x0, ALPHA_LR * x0);          // leakyrelu
                x1 = fmaxf(x1, ALPHA_LR * x1);
                float a0 = fmaf(x0, L2E, -rm144[r]);    // (e - m) * log2e
                float a1 = fmaf(x1, L2E, -rm144[r]);
                a0 = ((w >> mbit) & 1u)       ? a0 : -1e30f;
                a1 = ((w >> (mbit + 1)) & 1u) ? a1 : -1e30f;
                float p0 = exp2f(a0) * rli[r];
                float p1 = exp2f(a1) * rli[r];
                __half2 hh = __floats2half2_rn(p0, p1);
                uint32_t off = SWZ128((uint32_t)(row * 128 + lane * 4));
                *(uint32_t*)(dstP + off) = *(uint32_t*)&hh;
            }
        }

        CP_WAIT0();
        FENCE_ASYNC_SH();
        __syncthreads();

        // ---- issue MMAs (no wait — drains while next produce runs)
        if (wid == 0) {
            if (elect1()) {
                const uint64_t ad0   = kdesc(smP_u + buf * P_BUF_BYTES);
                const uint32_t bbase = smB_u + buf * B_BUF_BYTES;
                // terms: 0 = P*W_hi, 1 = P*W_lo
#pragma unroll
                for (int term = 0; term < 2; term++) {
                    const uint32_t wh = term ? 32768u : 0u;
#pragma unroll
                    for (int chunk = 0; chunk < 4; chunk++) {
                        const uint64_t bd = kdesc(bbase + wh + chunk * 8192);
                        const uint32_t dtm = tmem + chunk * 64;
#pragma unroll
                        for (int ks = 0; ks < 4; ks++) {
                            uint32_t en = (t32 != 0) | (term != 0) | (ks != 0);
                            mma_f16_ss(dtm, ad0 + ks * 2, bd + ks * 2, IDESC_FP16, en);
                        }
                    }
                }
                TC_COMMIT(mbar_u + 8 * buf);
            }
        }
    }

    // drain the last two tiles
    MBAR_WAIT(mbar_u,     phase[0]);
    MBAR_WAIT(mbar_u + 8, phase[1]);
    TC_FENCE_AFTER();

    // ---- epilogue: LDTM over 8 warps, ELU, store
    if (wid < 8) {
        const int colbase = (wid >> 2) * 128;       // 0 or 128
        const int row = (wid & 3) * 32 + lane;      // warp's subpartition rows
        const size_t rowoff = (size_t)(rowbase + row) * 256;
#pragma unroll
        for (int cb = 0; cb < 128; cb += 32) {
            uint32_t d[32];
            TC_LD_X32(d, tmem + colbase + cb);
            TC_WAIT_LD();
#pragma unroll
            for (int q = 0; q < 8; q++) {
                float v0 = __uint_as_float(d[q * 4 + 0]);
                float v1 = __uint_as_float(d[q * 4 + 1]);
                float v2 = __uint_as_float(d[q * 4 + 2]);
                float v3 = __uint_as_float(d[q * 4 + 3]);
                float4 o;
                o.x = (v0 > 0.f) ? v0 : expm1f(v0);
                o.y = (v1 > 0.f) ? v1 : expm1f(v1);
                o.z = (v2 > 0.f) ? v2 : expm1f(v2);
                o.w = (v3 > 0.f) ? v3 : expm1f(v3);
                *(float4*)&out[rowoff + colbase + cb + q * 4] = o;
            }
        }
    }
    __syncthreads();
    if (t == 0) { MBAR_INVAL(mbar_u); MBAR_INVAL(mbar_u + 8); }
    __syncthreads();
    if (wid == 0) TC_DEALLOC(tmem, 256);

#else
    // ================== fallback: f32x2 register GEMM (threads 0-255 work) ==
    float (*whS)[128] = (float (*)[128])smraw;           // 16x128 = 8 KB
    float (*pS)[128]  = (float (*)[128])(smraw + 8192);  // 16x128 = 8 KB

    const int tr = t >> 4, tc = t & 15;
    const int w_kk = t >> 4, w_f0 = (t & 15) * 8;
    const int p_r  = t >> 1, p_kq = (t & 1) * 8;
    const bool act = (t < 256);

    for (int fb = 0; fb < 256; fb += 128) {
        unsigned long long acc[4][8];
#pragma unroll
        for (int i = 0; i < 4; i++)
#pragma unroll
            for (int c = 0; c < 8; c++) acc[i][c] = 0ull;

        for (int j0 = 0; j0 < NNODE; j0 += 16) {
            __syncthreads();
            if (act) {
                const float* src = &g_Wh[((size_t)(b * NNODE + j0 + w_kk)) * 256 + fb + w_f0];
                float4 v0 = *(const float4*)src;
                float4 v1 = *(const float4*)(src + 4);
                *(float4*)&whS[w_kk][w_f0]     = v0;
                *(float4*)&whS[w_kk][w_f0 + 4] = v1;

                const int* ar = &adj[((size_t)(rowbase + p_r)) * NNODE + j0 + p_kq];
                int4 a0 = *(const int4*)ar;
                int4 a1 = *(const int4*)(ar + 4);
                int av[8] = {a0.x, a0.y, a0.z, a0.w, a1.x, a1.y, a1.z, a1.w};
                float s1v = s1S[p_r], mv = mS[p_r], lv = liS[p_r];
                const float* s2p = &g_s2[b * NNODE + j0 + p_kq];
#pragma unroll
                for (int i = 0; i < 8; i++) {
                    float x = s1v + s2p[i];
                    float e = (x > 0.f) ? x : ALPHA_LR * x;
                    e = (av[i] > 0) ? e : NEG_BIG;
                    pS[p_kq + i][p_r] = __expf(e - mv) * lv;
                }
            }
            __syncthreads();

            if (act) {
#pragma unroll 4
                for (int kk = 0; kk < 16; kk++) {
                    ulonglong2 pA = *(const ulonglong2*)&pS[kk][tr * 4];
                    ulonglong2 pB = *(const ulonglong2*)&pS[kk][64 + tr * 4];
                    float4 wA = *(const float4*)&whS[kk][tc * 4];
                    float4 wB = *(const float4*)&whS[kk][64 + tc * 4];
                    unsigned long long w2[8];
                    w2[0] = dup2(wA.x); w2[1] = dup2(wA.y);
                    w2[2] = dup2(wA.z); w2[3] = dup2(wA.w);
                    w2[4] = dup2(wB.x); w2[5] = dup2(wB.y);
                    w2[6] = dup2(wB.z); w2[7] = dup2(wB.w);
#pragma unroll
                    for (int c = 0; c < 8; c++) {
                        fma2(acc[0][c], pA.x, w2[c]);
                        fma2(acc[1][c], pA.y, w2[c]);
                        fma2(acc[2][c], pB.x, w2[c]);
                        fma2(acc[3][c], pB.y, w2[c]);
                    }
                }
            }
        }

        if (act) {
#pragma unroll
            for (int ip = 0; ip < 4; ip++) {
                int rloc = (ip < 2) ? (tr * 4 + ip * 2) : (64 + tr * 4 + (ip - 2) * 2);
                float lo[8], hi[8];
#pragma unroll
                for (int c = 0; c < 8; c++) unpack2(acc[ip][c], lo[c], hi[c]);
#pragma unroll
                for (int h2 = 0; h2 < 2; h2++) {
                    float* v = h2 ? hi : lo;
                    size_t rowoff = ((size_t)(rowbase + rloc + h2)) * 256;
                    float4 oA, oB;
                    oA.x = (v[0] > 0.f) ? v[0] : expm1f(v[0]);
                    oA.y = (v[1] > 0.f) ? v[1] : expm1f(v[1]);
                    oA.z = (v[2] > 0.f) ? v[2] : expm1f(v[2]);
                    oA.w = (v[3] > 0.f) ? v[3] : expm1f(v[3]);
                    oB.x = (v[4] > 0.f) ? v[4] : expm1f(v[4]);
                    oB.y = (v[5] > 0.f) ? v[5] : expm1f(v[5]);
                    oB.z = (v[6] > 0.f) ? v[6] : expm1f(v[6]);
                    oB.w = (v[7] > 0.f) ? v[7] : expm1f(v[7]);
                    *(float4*)&out[rowoff + fb + tc * 4]      = oA;
                    *(float4*)&out[rowoff + fb + 64 + tc * 4] = oB;
                }
            }
        }
    }
#endif
}

// ================= launcher =================
extern "C" void kernel_launch(void* const* d_in, const int* in_sizes, int n_in,
                              void* d_out, int out_size) {
    const float* h   = (const float*)d_in[0];   // (8,2048,256) f32
    const int*   adj = (const int*)  d_in[1];   // (8,2048,2048) i32
    const float* W   = (const float*)d_in[2];   // (256,256) f32
    const float* a   = (const float*)d_in[3];   // (512,1) f32
    float* out = (float*)d_out;                 // (8,2048,256) f32

    cudaFuncSetAttribute(k_attn_tc, cudaFuncAttributeMaxDynamicSharedMemorySize,
                         SMEM_DYN);

    k_gemm<<<dim3(4, 256), 256>>>(h, W);
    k_s   <<<ROWS, 256>>>(a);
    k_ml  <<<ROWS / 8, 256>>>(adj);
    k_tr  <<<dim3(NNODE / 32, FEAT / 32, BATCH), 256>>>();
    k_attn_tc<<<dim3(NNODE / 128, BATCH), 512, SMEM_DYN>>>(adj, out);
}

// round 9
// speedup vs baseline: 3.9595x; 1.2924x over previous
#include <cuda_runtime.h>
#include <cuda_bf16.h>
#include <cuda_fp16.h>
#include <math.h>
#include <stdint.h>

#define BATCH 8
#define NNODE 2048
#define FEAT  256
#define ROWS  (BATCH * NNODE)   // 16384
#define ALPHA_LR 0.2f
#define NEG_BIG  -9.0e15f
#define L2E      1.4426950408889634f

#if defined(__CUDA_ARCH_FEAT_SM103_ALL) || defined(__CUDA_ARCH_FEAT_SM100_ALL)
#define HAS_TC 1
#else
#define HAS_TC 0
#endif

// -------- scratch (device globals; no allocation allowed) --------
__device__ float g_Wh[(size_t)ROWS * FEAT];                 // 16 MB fp32
__device__ __half g_WhT_hi[(size_t)BATCH * FEAT * NNODE];   // 8 MB  Wh^T hi (fp16)
__device__ __half g_WhT_lo[(size_t)BATCH * FEAT * NNODE];   // 8 MB  Wh^T lo (fp16)
__device__ __half g_WT_hi[FEAT * FEAT];                     // 128 KB W^T hi [f][k]
__device__ __half g_WT_lo[FEAT * FEAT];                     // 128 KB W^T lo [f][k]
__device__ uint32_t g_mask[(size_t)ROWS * (NNODE / 32)];    // 4.2 MB adj bitmask
__device__ float g_s1[ROWS];
__device__ float g_s2[ROWS];
__device__ float g_m [ROWS];
__device__ float g_li[ROWS];

// ======================= helpers =======================
__device__ __forceinline__ uint32_t smem_u32(const void* p) {
    uint32_t a;
    asm("{ .reg .u64 t; cvta.to.shared.u64 t, %1; cvt.u32.u64 %0, t; }"
        : "=r"(a) : "l"(p));
    return a;
}
// packed fp32x2 (used by fallback path)
__device__ __forceinline__ void fma2(unsigned long long& d,
                                     unsigned long long a,
                                     unsigned long long b) {
    asm("fma.rn.f32x2 %0, %1, %2, %0;" : "+l"(d) : "l"(a), "l"(b));
}
__device__ __forceinline__ unsigned long long dup2(float w) {
    unsigned long long r;
    asm("mov.b64 %0, {%1, %1};" : "=l"(r) : "f"(w));
    return r;
}
__device__ __forceinline__ void unpack2(unsigned long long v, float& lo, float& hi) {
    asm("mov.b64 {%0, %1}, %2;" : "=f"(lo), "=f"(hi) : "l"(v));
}
// cp.async 16B (sm_80+, safe in all compile passes)
__device__ __forceinline__ void cp_async16(uint32_t dst, const void* src) {
    asm volatile("cp.async.cg.shared.global [%0], [%1], 16;" :: "r"(dst), "l"(src));
}
#define CP_COMMIT() asm volatile("cp.async.commit_group;" ::: "memory")
#define CP_WAIT0()  asm volatile("cp.async.wait_group 0;" ::: "memory")

#if HAS_TC
__device__ __forceinline__ uint32_t elect1() {
    uint32_t p;
    asm volatile("{ .reg .pred p; elect.sync _|p, 0xFFFFFFFF; selp.b32 %0,1,0,p; }"
                 : "=r"(p));
    return p;
}
#define TC_ALLOC(sm, n)   asm volatile("tcgen05.alloc.cta_group::1.sync.aligned.shared::cta.b32 [%0], %1;" :: "r"(sm), "r"(n) : "memory")
#define TC_DEALLOC(t, n)  asm volatile("tcgen05.dealloc.cta_group::1.sync.aligned.b32 %0, %1;" :: "r"(t), "r"(n))
#define TC_WAIT_LD()      asm volatile("tcgen05.wait::ld.sync.aligned;" ::: "memory")
#define TC_FENCE_AFTER()  asm volatile("tcgen05.fence::after_thread_sync;" ::: "memory")
#define FENCE_ASYNC_SH()  asm volatile("fence.proxy.async.shared::cta;" ::: "memory")
#define TC_COMMIT(mb)     asm volatile("tcgen05.commit.cta_group::1.mbarrier::arrive::one.shared::cluster.b64 [%0];" :: "r"(mb) : "memory")
#define MBAR_INIT(mb, c)  asm volatile("mbarrier.init.shared.b64 [%0], %1;" :: "r"(mb), "r"(c) : "memory")
#define MBAR_INVAL(mb)    asm volatile("mbarrier.inval.shared.b64 [%0];" :: "r"(mb) : "memory")

#define MBAR_WAIT(mb, ph) do {                                                   \
    uint32_t _mb = (mb); uint32_t _ph = (ph); uint32_t _done;                    \
    asm volatile("{ .reg .pred p; mbarrier.try_wait.parity.acquire.cta.shared::cta.b64 p, [%1], %2; selp.b32 %0,1,0,p; }" \
                 : "=r"(_done) : "r"(_mb), "r"(_ph) : "memory");                 \
    if (!_done) {                                                                \
        asm volatile("{ .reg .pred P1; WL_%=: mbarrier.try_wait.parity.acquire.cta.shared::cta.b64 P1, [%0], %1, 0x989680; @P1 bra.uni WD_%=; bra.uni WL_%=; WD_%=: }" \
                     :: "r"(_mb), "r"(_ph) : "memory");                          \
    }                                                                            \
} while (0)

#define TC_LD_X32(r, tm)                                                         \
    asm volatile("tcgen05.ld.sync.aligned.32x32b.x32.b32 "                       \
        "{%0,%1,%2,%3,%4,%5,%6,%7,%8,%9,%10,%11,%12,%13,%14,%15,"                \
        "%16,%17,%18,%19,%20,%21,%22,%23,%24,%25,%26,%27,%28,%29,%30,%31}, [%32];" \
        : "=r"((r)[0]),  "=r"((r)[1]),  "=r"((r)[2]),  "=r"((r)[3]),             \
          "=r"((r)[4]),  "=r"((r)[5]),  "=r"((r)[6]),  "=r"((r)[7]),             \
          "=r"((r)[8]),  "=r"((r)[9]),  "=r"((r)[10]), "=r"((r)[11]),            \
          "=r"((r)[12]), "=r"((r)[13]), "=r"((r)[14]), "=r"((r)[15]),            \
          "=r"((r)[16]), "=r"((r)[17]), "=r"((r)[18]), "=r"((r)[19]),            \
          "=r"((r)[20]), "=r"((r)[21]), "=r"((r)[22]), "=r"((r)[23]),            \
          "=r"((r)[24]), "=r"((r)[25]), "=r"((r)[26]), "=r"((r)[27]),            \
          "=r"((r)[28]), "=r"((r)[29]), "=r"((r)[30]), "=r"((r)[31])             \
        : "r"(tm))

// SS-mode fp16 MMA: A and B both via SMEM descriptors
__device__ __forceinline__ void mma_f16_ss(uint32_t d, uint64_t adesc, uint64_t bdesc,
                                           uint32_t idesc, uint32_t en) {
    asm volatile("{ .reg .pred p; setp.ne.u32 p, %4, 0;\n\t"
        "tcgen05.mma.cta_group::1.kind::f16 [%0], %1, %2, %3, {%5,%5,%5,%5}, p;\n\t}"
        :: "r"(d), "l"(adesc), "l"(bdesc), "r"(idesc), "r"(en), "r"(0u) : "memory");
}

// idesc kind::f16: dtype=F32, atype=btype=FP16(0), N=64, M=128
#define IDESC_FP16 ((1u << 4) | (8u << 17) | (8u << 24))
#endif // HAS_TC

#define SWZ128(x) ((x) ^ (((x) >> 3) & 0x70))
#if HAS_TC
// K-major SW128 descriptor base: layout=2, version=1, SBO=64, LBO=1
__device__ __forceinline__ uint64_t kdesc(uint32_t addr) {
    const uint64_t base = (uint64_t(2) << 61) | (uint64_t(1) << 46)
                        | (uint64_t(64) << 32) | (uint64_t(1) << 16);
    return base | ((uint64_t)(addr >> 4) & 0x3FFF);
}
#endif

// ======== K0: W split/transpose:  WT[f][k] fp16 hi/lo ========
__global__ __launch_bounds__(256) void k_wsplit(const float* __restrict__ W) {
    __shared__ float tile[32][33];
    const int k0 = blockIdx.x * 32;
    const int f0 = blockIdx.y * 32;
    const int tx = threadIdx.x & 31;
    const int ty = threadIdx.x >> 5;   // 0..7
#pragma unroll
    for (int i = 0; i < 4; i++) {
        int k = k0 + ty + i * 8;
        tile[ty + i * 8][tx] = W[k * 256 + f0 + tx];
    }
    __syncthreads();
#pragma unroll
    for (int i = 0; i < 4; i++) {
        int f = f0 + ty + i * 8;
        float w = tile[tx][ty + i * 8];     // = W[k0+tx][f]
        __half hi = __float2half_rn(w);
        __half lo = __float2half_rn(w - __half2float(hi));
        g_WT_hi[f * 256 + k0 + tx] = hi;
        g_WT_lo[f * 256 + k0 + tx] = lo;
    }
}

// ================= K1: Wh = h @ W  (tcgen05 fp16 hi/lo, 3 terms) =========
// CTA = 128 rows x 256 feats; k-chunks of 64, 2-buffer pipeline.
//   A buf: h split hi(16K)+lo(16K); B buf: WT hi(32K)+lo(32K).
#define GA_BUF 32768
#define GB_BUF 65536
#define SMEM_DYN_G (2 * GA_BUF + 2 * GB_BUF + 1024)   // 197632
__global__ __launch_bounds__(512, 1) void k_gemm_tc(const float* __restrict__ h,
                                                    const float* __restrict__ W) {
    extern __shared__ char smraw[];
    const int t = threadIdx.x;
    const int rowbase = blockIdx.x * 128;

#if HAS_TC
    __shared__ uint32_t tmem_ptr_s;
    __shared__ __align__(8) unsigned long long mbar_s[2];

    char* smA = (char*)(((uintptr_t)smraw + 1023) & ~(uintptr_t)1023);
    char* smB = smA + 2 * GA_BUF;
    const uint32_t smA_u  = smem_u32(smA);
    const uint32_t smB_u  = smem_u32(smB);
    const uint32_t mbar_u = smem_u32(&mbar_s[0]);
    const uint32_t tptr_u = smem_u32(&tmem_ptr_s);
    const int wid  = t >> 5;
    const int lane = t & 31;

    if (wid == 0) TC_ALLOC(tptr_u, 256);
    if (t == 0) { MBAR_INIT(mbar_u, 1); MBAR_INIT(mbar_u + 8, 1); }
    __syncthreads();
    uint32_t tmem;
    asm volatile("ld.shared.b32 %0, [%1];" : "=r"(tmem) : "r"(tptr_u));

    int phase[2] = {0, 0};

    for (int kc = 0; kc < 4; kc++) {
        const int buf = kc & 1;
        const int k0  = kc * 64;
        if (kc >= 2) {
            MBAR_WAIT(mbar_u + 8 * buf, phase[buf]);
            phase[buf] ^= 1;
        }

        // ---- B staging via cp.async: WT hi/lo, 4 f-chunks x [64 f][64 k]
        {
            const uint32_t dstB = smB_u + buf * GB_BUF;
#pragma unroll
            for (int i = 0; i < 8; i++) {
                int idx   = t + i * 512;
                int k4    = idx & 7;
                int n     = (idx >> 3) & 63;
                int chunk = (idx >> 9) & 3;
                int half  = (idx >> 11) & 1;
                const __half* src = half ? g_WT_lo : g_WT_hi;
                const void* g = &src[(chunk * 64 + n) * 256 + k0 + k4 * 8];
                uint32_t off = (uint32_t)(half * 32768 + chunk * 8192)
                             + SWZ128((uint32_t)(n * 128 + k4 * 16));
                cp_async16(dstB + off, g);
            }
            CP_COMMIT();
        }

        // ---- A staging: h fp32 -> fp16 hi/lo split, K-major SW128
        {
            char* dstH = smA + buf * GA_BUF;
            char* dstL = dstH + 16384;
#pragma unroll
            for (int i = 0; i < 4; i++) {
                int idx = t + i * 512;
                int row = idx >> 4, q = idx & 15;
                float4 v = *(const float4*)&h[(size_t)(rowbase + row) * 256 + k0 + q * 4];
                __half2 h0 = __floats2half2_rn(v.x, v.y);
                __half2 h1 = __floats2half2_rn(v.z, v.w);
                __half2 l0 = __floats2half2_rn(v.x - __half2float(__low2half(h0)),
                                               v.y - __half2float(__high2half(h0)));
                __half2 l1 = __floats2half2_rn(v.z - __half2float(__low2half(h1)),
                                               v.w - __half2float(__high2half(h1)));
                uint32_t so = SWZ128((uint32_t)(row * 128 + q * 8));
                *(uint32_t*)(dstH + so)     = *(uint32_t*)&h0;
                *(uint32_t*)(dstH + so + 4) = *(uint32_t*)&h1;
                *(uint32_t*)(dstL + so)     = *(uint32_t*)&l0;
                *(uint32_t*)(dstL + so + 4) = *(uint32_t*)&l1;
            }
        }

        CP_WAIT0();
        FENCE_ASYNC_SH();
        __syncthreads();

        // ---- issue MMAs (accumulate across k-chunks)
        if (wid == 0) {
            if (elect1()) {
                const uint32_t abase = smA_u + buf * GA_BUF;
                const uint32_t bbase = smB_u + buf * GB_BUF;
                // terms: 0 = Ah*Bh, 1 = Al*Bh, 2 = Ah*Bl
#pragma unroll
                for (int term = 0; term < 3; term++) {
                    const uint64_t ad = kdesc(abase + ((term == 1) ? 16384u : 0u));
                    const uint32_t wh = (term == 2) ? 32768u : 0u;
#pragma unroll
                    for (int chunk = 0; chunk < 4; chunk++) {
                        const uint64_t bd = kdesc(bbase + wh + chunk * 8192);
                        const uint32_t dtm = tmem + chunk * 64;
#pragma unroll
                        for (int ks = 0; ks < 4; ks++) {
                            uint32_t en = (kc != 0) | (term != 0) | (ks != 0);
                            mma_f16_ss(dtm, ad + ks * 2, bd + ks * 2, IDESC_FP16, en);
                        }
                    }
                }
                TC_COMMIT(mbar_u + 8 * buf);
            }
        }
    }

    // drain
    MBAR_WAIT(mbar_u,     phase[0]);
    MBAR_WAIT(mbar_u + 8, phase[1]);
    TC_FENCE_AFTER();

    // ---- epilogue: LDTM over 8 warps, store fp32 Wh
    if (wid < 8) {
        const int colbase = (wid >> 2) * 128;
        const int row = (wid & 3) * 32 + lane;
        const size_t rowoff = (size_t)(rowbase + row) * 256;
#pragma unroll
        for (int cb = 0; cb < 128; cb += 32) {
            uint32_t d[32];
            TC_LD_X32(d, tmem + colbase + cb);
            TC_WAIT_LD();
#pragma unroll
            for (int q = 0; q < 8; q++) {
                float4 o;
                o.x = __uint_as_float(d[q * 4 + 0]);
                o.y = __uint_as_float(d[q * 4 + 1]);
                o.z = __uint_as_float(d[q * 4 + 2]);
                o.w = __uint_as_float(d[q * 4 + 3]);
                *(float4*)&g_Wh[rowoff + colbase + cb + q * 4] = o;
            }
        }
    }
    __syncthreads();
    if (t == 0) { MBAR_INVAL(mbar_u); MBAR_INVAL(mbar_u + 8); }
    __syncthreads();
    if (wid == 0) TC_DEALLOC(tmem, 256);

#else
    // ---- fallback: SIMT fp32 (correctness only) ----
    const int row = t >> 2;
    const int cq  = t & 3;
#pragma unroll 1
    for (int pass = 0; pass < 2; pass++) {
        const int c0 = cq * 32 + pass * 128;
        float acc[32];
#pragma unroll
        for (int c = 0; c < 32; c++) acc[c] = 0.f;
        for (int k = 0; k < 256; k++) {
            float hv = h[(size_t)(rowbase + row) * 256 + k];
            const float* wr = &W[k * 256 + c0];
#pragma unroll
            for (int c = 0; c < 32; c++) acc[c] = fmaf(hv, wr[c], acc[c]);
        }
#pragma unroll
        for (int c = 0; c < 32; c++)
            g_Wh[(size_t)(rowbase + row) * 256 + c0 + c] = acc[c];
    }
#endif
}

// ================= K2: s1/s2 row dot products =================
__global__ __launch_bounds__(256) void k_s(const float* __restrict__ a) {
    const int row = blockIdx.x;
    const int t   = threadIdx.x;
    float v  = g_Wh[(size_t)row * 256 + t];
    float p1 = v * a[t];
    float p2 = v * a[256 + t];
#pragma unroll
    for (int o = 16; o; o >>= 1) {
        p1 += __shfl_down_sync(0xffffffffu, p1, o);
        p2 += __shfl_down_sync(0xffffffffu, p2, o);
    }
    __shared__ float r1[8], r2[8];
    if ((t & 31) == 0) { r1[t >> 5] = p1; r2[t >> 5] = p2; }
    __syncthreads();
    if (t == 0) {
        float s1 = 0.f, s2 = 0.f;
#pragma unroll
        for (int w = 0; w < 8; w++) { s1 += r1[w]; s2 += r2[w]; }
        g_s1[row] = s1;
        g_s2[row] = s2;
    }
}

// ========== K3: per-row softmax stats (m, 1/l) + adj bitmask ==========
__global__ __launch_bounds__(256) void k_ml(const int* __restrict__ adj) {
    const int gwarp = (blockIdx.x * blockDim.x + threadIdx.x) >> 5;
    const int lane  = threadIdx.x & 31;
    if (gwarp >= ROWS) return;
    const int b = gwarp >> 11;
    const float  s1   = g_s1[gwarp];
    const int*   arow = adj + (size_t)gwarp * NNODE;
    const float* s2p  = g_s2 + (size_t)b * NNODE;
    uint32_t* mrow = &g_mask[(size_t)gwarp * (NNODE / 32)];

    float m = -INFINITY, l = 0.f;
    for (int it = 0; it < NNODE / 32; it++) {
        const int j = it * 32 + lane;
        const int av = arow[j];
        uint32_t w = __ballot_sync(0xffffffffu, av > 0);
        if (lane == 0) mrow[it] = w;
        float x = s1 + s2p[j];
        float e = (x > 0.f) ? x : ALPHA_LR * x;
        e = (av > 0) ? e : NEG_BIG;
        if (e > m) { l = l * __expf(m - e) + 1.f; m = e; }
        else       { l += __expf(e - m); }
    }
#pragma unroll
    for (int o = 16; o; o >>= 1) {
        float m2 = __shfl_down_sync(0xffffffffu, m, o);
        float l2 = __shfl_down_sync(0xffffffffu, l, o);
        float M  = fmaxf(m, m2);
        l = l * __expf(m - M) + l2 * __expf(m2 - M);
        m = M;
    }
    if (lane == 0) { g_m[gwarp] = m; g_li[gwarp] = 1.f / l; }
}

// ======== K3b: transpose + fp16 hi/lo split:  WhT[b][f][j] ========
__global__ __launch_bounds__(256) void k_tr() {
    __shared__ float tile[32][33];
    const int b  = blockIdx.z;
    const int j0 = blockIdx.x * 32;
    const int f0 = blockIdx.y * 32;
    const int tx = threadIdx.x & 31;
    const int ty = threadIdx.x >> 5;   // 0..7
#pragma unroll
    for (int k = 0; k < 4; k++) {
        int j = j0 + ty + k * 8;
        tile[ty + k * 8][tx] = g_Wh[((size_t)(b * NNODE + j)) * 256 + f0 + tx];
    }
    __syncthreads();
#pragma unroll
    for (int k = 0; k < 4; k++) {
        int f = f0 + ty + k * 8;
        float w = tile[tx][ty + k * 8];
        __half hi = __float2half_rn(w);
        __half lo = __float2half_rn(w - __half2float(hi));
        size_t o = (((size_t)(b * FEAT + f)) << 11) + j0 + tx;
        g_WhT_hi[o] = hi;
        g_WhT_lo[o] = lo;
    }
}

// ================= K4: attention @ Wh + ELU =================
// (unchanged from R8 passing kernel)
#define P_BUF_BYTES 16384
#define B_BUF_BYTES 65536
#define SMEM_DYN    (2 * P_BUF_BYTES + 2 * B_BUF_BYTES + 1024)   // 164864
__global__ __launch_bounds__(512, 1) void k_attn_tc(const int* __restrict__ adj,
                                                    float* __restrict__ out) {
    extern __shared__ char smraw[];
    __shared__ float s1S[128], mS[128], liS[128];

    const int t   = threadIdx.x;
    const int b   = blockIdx.y;
    const int i0  = blockIdx.x * 128;
    const int rowbase = b * NNODE + i0;

    if (t < 128) {
        s1S[t] = g_s1[rowbase + t];
        mS [t] = g_m [rowbase + t];
        liS[t] = g_li[rowbase + t];
    }

#if HAS_TC
    __shared__ uint32_t tmem_ptr_s;
    __shared__ __align__(8) unsigned long long mbar_s[2];

    char* smP = (char*)(((uintptr_t)smraw + 1023) & ~(uintptr_t)1023);
    char* smB = smP + 2 * P_BUF_BYTES;
    const uint32_t smP_u  = smem_u32(smP);
    const uint32_t smB_u  = smem_u32(smB);
    const uint32_t mbar_u = smem_u32(&mbar_s[0]);
    const uint32_t tptr_u = smem_u32(&tmem_ptr_s);
    const int wid  = t >> 5;
    const int lane = t & 31;

    if (wid == 0) TC_ALLOC(tptr_u, 256);
    if (t == 0) { MBAR_INIT(mbar_u, 1); MBAR_INIT(mbar_u + 8, 1); }
    __syncthreads();
    uint32_t tmem;
    asm volatile("ld.shared.b32 %0, [%1];" : "=r"(tmem) : "r"(tptr_u));

    float rs1[8], rm144[8], rli[8];
#pragma unroll
    for (int r = 0; r < 8; r++) {
        const int row = wid * 8 + r;
        rs1[r]   = s1S[row];
        rm144[r] = mS[row] * L2E;
        rli[r]   = liS[row];
    }
    const uint32_t* mbase = &g_mask[(size_t)(rowbase + wid * 8) * (NNODE / 32) + (lane >> 4)];
    const int mbit = (lane * 2) & 31;

    int phase[2] = {0, 0};

    for (int t32 = 0; t32 < NNODE / 64; t32++) {
        const int buf = t32 & 1;
        const int j0  = t32 * 64;
        if (t32 >= 2) {
            MBAR_WAIT(mbar_u + 8 * buf, phase[buf]);
            phase[buf] ^= 1;
        }

        {
            const uint32_t dstB = smB_u + buf * B_BUF_BYTES;
#pragma unroll
            for (int i = 0; i < 8; i++) {
                int idx   = t + i * 512;
                int k4    = idx & 7;
                int n     = (idx >> 3) & 63;
                int chunk = (idx >> 9) & 3;
                int half  = (idx >> 11) & 1;
                const __half* src = half ? g_WhT_lo : g_WhT_hi;
                const void* g = &src[(((size_t)(b * FEAT + chunk * 64 + n)) << 11) + j0 + k4 * 8];
                uint32_t off = (uint32_t)(half * 32768 + chunk * 8192)
                             + SWZ128((uint32_t)(n * 128 + k4 * 16));
                cp_async16(dstB + off, g);
            }
            CP_COMMIT();
        }

        {
            char* dstP = smP + buf * P_BUF_BYTES;
            float2 s2v = *(const float2*)&g_s2[b * NNODE + j0 + lane * 2];
#pragma unroll
            for (int r = 0; r < 8; r++) {
                const int row = wid * 8 + r;
                const uint32_t w = mbase[(size_t)r * (NNODE / 32) + t32 * 2];
                float x0 = rs1[r] + s2v.x;
                float x1 = rs1[r] + s2v.y;
                x0 = fmaxf(x0, ALPHA_LR * x0);
                x1 = fmaxf(x1, ALPHA_LR * x1);
                float a0 = fmaf(x0, L2E, -rm144[r]);
                float a1 = fmaf(x1, L2E, -rm144[r]);
                a0 = ((w >> mbit) & 1u)       ? a0 : -1e30f;
                a1 = ((w >> (mbit + 1)) & 1u) ? a1 : -1e30f;
                float p0 = exp2f(a0) * rli[r];
                float p1 = exp2f(a1) * rli[r];
                __half2 hh = __floats2half2_rn(p0, p1);
                uint32_t off = SWZ128((uint32_t)(row * 128 + lane * 4));
                *(uint32_t*)(dstP + off) = *(uint32_t*)&hh;
            }
        }

        CP_WAIT0();
        FENCE_ASYNC_SH();
        __syncthreads();

        if (wid == 0) {
            if (elect1()) {
                const uint64_t ad0   = kdesc(smP_u + buf * P_BUF_BYTES);
                const uint32_t bbase = smB_u + buf * B_BUF_BYTES;
#pragma unroll
                for (int term = 0; term < 2; term++) {
                    const uint32_t wh = term ? 32768u : 0u;
#pragma unroll
                    for (int chunk = 0; chunk < 4; chunk++) {
                        const uint64_t bd = kdesc(bbase + wh + chunk * 8192);
                        const uint32_t dtm = tmem + chunk * 64;
#pragma unroll
                        for (int ks = 0; ks < 4; ks++) {
                            uint32_t en = (t32 != 0) | (term != 0) | (ks != 0);
                            mma_f16_ss(dtm, ad0 + ks * 2, bd + ks * 2, IDESC_FP16, en);
                        }
                    }
                }
                TC_COMMIT(mbar_u + 8 * buf);
            }
        }
    }

    MBAR_WAIT(mbar_u,     phase[0]);
    MBAR_WAIT(mbar_u + 8, phase[1]);
    TC_FENCE_AFTER();

    if (wid < 8) {
        const int colbase = (wid >> 2) * 128;
        const int row = (wid & 3) * 32 + lane;
        const size_t rowoff = (size_t)(rowbase + row) * 256;
#pragma unroll
        for (int cb = 0; cb < 128; cb += 32) {
            uint32_t d[32];
            TC_LD_X32(d, tmem + colbase + cb);
            TC_WAIT_LD();
#pragma unroll
            for (int q = 0; q < 8; q++) {
                float v0 = __uint_as_float(d[q * 4 + 0]);
                float v1 = __uint_as_float(d[q * 4 + 1]);
                float v2 = __uint_as_float(d[q * 4 + 2]);
                float v3 = __uint_as_float(d[q * 4 + 3]);
                float4 o;
                o.x = (v0 > 0.f) ? v0 : expm1f(v0);
                o.y = (v1 > 0.f) ? v1 : expm1f(v1);
                o.z = (v2 > 0.f) ? v2 : expm1f(v2);
                o.w = (v3 > 0.f) ? v3 : expm1f(v3);
                *(float4*)&out[rowoff + colbase + cb + q * 4] = o;
            }
        }
    }
    __syncthreads();
    if (t == 0) { MBAR_INVAL(mbar_u); MBAR_INVAL(mbar_u + 8); }
    __syncthreads();
    if (wid == 0) TC_DEALLOC(tmem, 256);

#else
    // ================== fallback: f32x2 register GEMM (threads 0-255 work) ==
    float (*whS)[128] = (float (*)[128])smraw;
    float (*pS)[128]  = (float (*)[128])(smraw + 8192);

    const int tr = t >> 4, tc = t & 15;
    const int w_kk = t >> 4, w_f0 = (t & 15) * 8;
    const int p_r  = t >> 1, p_kq = (t & 1) * 8;
    const bool act = (t < 256);

    for (int fb = 0; fb < 256; fb += 128) {
        unsigned long long acc[4][8];
#pragma unroll
        for (int i = 0; i < 4; i++)
#pragma unroll
            for (int c = 0; c < 8; c++) acc[i][c] = 0ull;

        for (int j0 = 0; j0 < NNODE; j0 += 16) {
            __syncthreads();
            if (act) {
                const float* src = &g_Wh[((size_t)(b * NNODE + j0 + w_kk)) * 256 + fb + w_f0];
                float4 v0 = *(const float4*)src;
                float4 v1 = *(const float4*)(src + 4);
                *(float4*)&whS[w_kk][w_f0]     = v0;
                *(float4*)&whS[w_kk][w_f0 + 4] = v1;

                const int* ar = &adj[((size_t)(rowbase + p_r)) * NNODE + j0 + p_kq];
                int4 a0 = *(const int4*)ar;
                int4 a1 = *(const int4*)(ar + 4);
                int av[8] = {a0.x, a0.y, a0.z, a0.w, a1.x, a1.y, a1.z, a1.w};
                float s1v = s1S[p_r], mv = mS[p_r], lv = liS[p_r];
                const float* s2p = &g_s2[b * NNODE + j0 + p_kq];
#pragma unroll
                for (int i = 0; i < 8; i++) {
                    float x = s1v + s2p[i];
                    float e = (x > 0.f) ? x : ALPHA_LR * x;
                    e = (av[i] > 0) ? e : NEG_BIG;
                    pS[p_kq + i][p_r] = __expf(e - mv) * lv;
                }
            }
            __syncthreads();

            if (act) {
#pragma unroll 4
                for (int kk = 0; kk < 16; kk++) {
                    ulonglong2 pA = *(const ulonglong2*)&pS[kk][tr * 4];
                    ulonglong2 pB = *(const ulonglong2*)&pS[kk][64 + tr * 4];
                    float4 wA = *(const float4*)&whS[kk][tc * 4];
                    float4 wB = *(const float4*)&whS[kk][64 + tc * 4];
                    unsigned long long w2[8];
                    w2[0] = dup2(wA.x); w2[1] = dup2(wA.y);
                    w2[2] = dup2(wA.z); w2[3] = dup2(wA.w);
                    w2[4] = dup2(wB.x); w2[5] = dup2(wB.y);
                    w2[6] = dup2(wB.z); w2[7] = dup2(wB.w);
#pragma unroll
                    for (int c = 0; c < 8; c++) {
                        fma2(acc[0][c], pA.x, w2[c]);
                        fma2(acc[1][c], pA.y, w2[c]);
                        fma2(acc[2][c], pB.x, w2[c]);
                        fma2(acc[3][c], pB.y, w2[c]);
                    }
                }
            }
        }

        if (act) {
#pragma unroll
            for (int ip = 0; ip < 4; ip++) {
                int rloc = (ip < 2) ? (tr * 4 + ip * 2) : (64 + tr * 4 + (ip - 2) * 2);
                float lo[8], hi[8];
#pragma unroll
                for (int c = 0; c < 8; c++) unpack2(acc[ip][c], lo[c], hi[c]);
#pragma unroll
                for (int h2 = 0; h2 < 2; h2++) {
                    float* v = h2 ? hi : lo;
                    size_t rowoff = ((size_t)(rowbase + rloc + h2)) * 256;
                    float4 oA, oB;
                    oA.x = (v[0] > 0.f) ? v[0] : expm1f(v[0]);
                    oA.y = (v[1] > 0.f) ? v[1] : expm1f(v[1]);
                    oA.z = (v[2] > 0.f) ? v[2] : expm1f(v[2]);
                    oA.w = (v[3] > 0.f) ? v[3] : expm1f(v[3]);
                    oB.x = (v[4] > 0.f) ? v[4] : expm1f(v[4]);
                    oB.y = (v[5] > 0.f) ? v[5] : expm1f(v[5]);
                    oB.z = (v[6] > 0.f) ? v[6] : expm1f(v[6]);
                    oB.w = (v[7] > 0.f) ? v[7] : expm1f(v[7]);
                    *(float4*)&out[rowoff + fb + tc * 4]      = oA;
                    *(float4*)&out[rowoff + fb + 64 + tc * 4] = oB;
                }
            }
        }
    }
#endif
}

// ================= launcher =================
extern "C" void kernel_launch(void* const* d_in, const int* in_sizes, int n_in,
                              void* d_out, int out_size) {
    const float* h   = (const float*)d_in[0];   // (8,2048,256) f32
    const int*   adj = (const int*)  d_in[1];   // (8,2048,2048) i32
    const float* W   = (const float*)d_in[2];   // (256,256) f32
    const float* a   = (const float*)d_in[3];   // (512,1) f32
    float* out = (float*)d_out;                 // (8,2048,256) f32

    cudaFuncSetAttribute(k_gemm_tc, cudaFuncAttributeMaxDynamicSharedMemorySize,
                         SMEM_DYN_G);
    cudaFuncSetAttribute(k_attn_tc, cudaFuncAttributeMaxDynamicSharedMemorySize,
                         SMEM_DYN);

    k_wsplit<<<dim3(8, 8), 256>>>(W);
    k_gemm_tc<<<ROWS / 128, 512, SMEM_DYN_G>>>(h, W);
    k_s   <<<ROWS, 256>>>(a);
    k_ml  <<<ROWS / 8, 256>>>(adj);
    k_tr  <<<dim3(NNODE / 32, FEAT / 32, BATCH), 256>>>();
    k_attn_tc<<<dim3(NNODE / 128, BATCH), 512, SMEM_DYN>>>(adj, out);
}

// round 10
// speedup vs baseline: 6.2967x; 1.5903x over previous
#include <cuda_runtime.h>
#include <cuda_bf16.h>
#include <cuda_fp16.h>
#include <math.h>
#include <stdint.h>

#define BATCH 8
#define NNODE 2048
#define FEAT  256
#define ROWS  (BATCH * NNODE)   // 16384
#define ALPHA_LR 0.2f
#define NEG_BIG  -9.0e15f
#define L2E      1.4426950408889634f
#define PSHIFT   13.0f           // P'' = exp2(x*L2E - PSHIFT); epilogue divides by sum

#if defined(__CUDA_ARCH_FEAT_SM103_ALL) || defined(__CUDA_ARCH_FEAT_SM100_ALL)
#define HAS_TC 1
#else
#define HAS_TC 0
#endif

// -------- scratch (device globals; no allocation allowed) --------
__device__ float g_Wh[(size_t)ROWS * FEAT];               // 16 MB fp32
__device__ __half g_WhT[(size_t)BATCH * FEAT * NNODE];    // 8 MB  Wh^T fp16
__device__ __half g_WT_hi[FEAT * FEAT];                   // 128 KB W^T hi [f][k]
__device__ __half g_WT_lo[FEAT * FEAT];                   // 128 KB W^T lo [f][k]
__device__ float g_s1[ROWS];
__device__ float g_s2[ROWS];

// ======================= helpers =======================
__device__ __forceinline__ uint32_t smem_u32(const void* p) {
    uint32_t a;
    asm("{ .reg .u64 t; cvta.to.shared.u64 t, %1; cvt.u32.u64 %0, t; }"
        : "=r"(a) : "l"(p));
    return a;
}
// packed fp32x2 (used by fallback path)
__device__ __forceinline__ void fma2(unsigned long long& d,
                                     unsigned long long a,
                                     unsigned long long b) {
    asm("fma.rn.f32x2 %0, %1, %2, %0;" : "+l"(d) : "l"(a), "l"(b));
}
__device__ __forceinline__ unsigned long long dup2(float w) {
    unsigned long long r;
    asm("mov.b64 %0, {%1, %1};" : "=l"(r) : "f"(w));
    return r;
}
__device__ __forceinline__ void unpack2(unsigned long long v, float& lo, float& hi) {
    asm("mov.b64 {%0, %1}, %2;" : "=f"(lo), "=f"(hi) : "l"(v));
}
// cp.async 16B (sm_80+, safe in all compile passes)
__device__ __forceinline__ void cp_async16(uint32_t dst, const void* src) {
    asm volatile("cp.async.cg.shared.global [%0], [%1], 16;" :: "r"(dst), "l"(src));
}
#define CP_COMMIT() asm volatile("cp.async.commit_group;" ::: "memory")
#define CP_WAIT0()  asm volatile("cp.async.wait_group 0;" ::: "memory")

#if HAS_TC
__device__ __forceinline__ uint32_t elect1() {
    uint32_t p;
    asm volatile("{ .reg .pred p; elect.sync _|p, 0xFFFFFFFF; selp.b32 %0,1,0,p; }"
                 : "=r"(p));
    return p;
}
#define TC_ALLOC(sm, n)   asm volatile("tcgen05.alloc.cta_group::1.sync.aligned.shared::cta.b32 [%0], %1;" :: "r"(sm), "r"(n) : "memory")
#define TC_DEALLOC(t, n)  asm volatile("tcgen05.dealloc.cta_group::1.sync.aligned.b32 %0, %1;" :: "r"(t), "r"(n))
#define TC_WAIT_LD()      asm volatile("tcgen05.wait::ld.sync.aligned;" ::: "memory")
#define TC_FENCE_AFTER()  asm volatile("tcgen05.fence::after_thread_sync;" ::: "memory")
#define FENCE_ASYNC_SH()  asm volatile("fence.proxy.async.shared::cta;" ::: "memory")
#define TC_COMMIT(mb)     asm volatile("tcgen05.commit.cta_group::1.mbarrier::arrive::one.shared::cluster.b64 [%0];" :: "r"(mb) : "memory")
#define MBAR_INIT(mb, c)  asm volatile("mbarrier.init.shared.b64 [%0], %1;" :: "r"(mb), "r"(c) : "memory")
#define MBAR_INVAL(mb)    asm volatile("mbarrier.inval.shared.b64 [%0];" :: "r"(mb) : "memory")

#define MBAR_WAIT(mb, ph) do {                                                   \
    uint32_t _mb = (mb); uint32_t _ph = (ph); uint32_t _done;                    \
    asm volatile("{ .reg .pred p; mbarrier.try_wait.parity.acquire.cta.shared::cta.b64 p, [%1], %2; selp.b32 %0,1,0,p; }" \
                 : "=r"(_done) : "r"(_mb), "r"(_ph) : "memory");                 \
    if (!_done) {                                                                \
        asm volatile("{ .reg .pred P1; WL_%=: mbarrier.try_wait.parity.acquire.cta.shared::cta.b64 P1, [%0], %1, 0x989680; @P1 bra.uni WD_%=; bra.uni WL_%=; WD_%=: }" \
                     :: "r"(_mb), "r"(_ph) : "memory");                          \
    }                                                                            \
} while (0)

#define TC_LD_X32(r, tm)                                                         \
    asm volatile("tcgen05.ld.sync.aligned.32x32b.x32.b32 "                       \
        "{%0,%1,%2,%3,%4,%5,%6,%7,%8,%9,%10,%11,%12,%13,%14,%15,"                \
        "%16,%17,%18,%19,%20,%21,%22,%23,%24,%25,%26,%27,%28,%29,%30,%31}, [%32];" \
        : "=r"((r)[0]),  "=r"((r)[1]),  "=r"((r)[2]),  "=r"((r)[3]),             \
          "=r"((r)[4]),  "=r"((r)[5]),  "=r"((r)[6]),  "=r"((r)[7]),             \
          "=r"((r)[8]),  "=r"((r)[9]),  "=r"((r)[10]), "=r"((r)[11]),            \
          "=r"((r)[12]), "=r"((r)[13]), "=r"((r)[14]), "=r"((r)[15]),            \
          "=r"((r)[16]), "=r"((r)[17]), "=r"((r)[18]), "=r"((r)[19]),            \
          "=r"((r)[20]), "=r"((r)[21]), "=r"((r)[22]), "=r"((r)[23]),            \
          "=r"((r)[24]), "=r"((r)[25]), "=r"((r)[26]), "=r"((r)[27]),            \
          "=r"((r)[28]), "=r"((r)[29]), "=r"((r)[30]), "=r"((r)[31])             \
        : "r"(tm))

// SS-mode fp16 MMA: A and B both via SMEM descriptors
__device__ __forceinline__ void mma_f16_ss(uint32_t d, uint64_t adesc, uint64_t bdesc,
                                           uint32_t idesc, uint32_t en) {
    asm volatile("{ .reg .pred p; setp.ne.u32 p, %4, 0;\n\t"
        "tcgen05.mma.cta_group::1.kind::f16 [%0], %1, %2, %3, {%5,%5,%5,%5}, p;\n\t}"
        :: "r"(d), "l"(adesc), "l"(bdesc), "r"(idesc), "r"(en), "r"(0u) : "memory");
}

// idesc kind::f16: dtype=F32, atype=btype=FP16(0), N=64, M=128
#define IDESC_FP16 ((1u << 4) | (8u << 17) | (8u << 24))
#endif // HAS_TC

#define SWZ128(x) ((x) ^ (((x) >> 3) & 0x70))
#if HAS_TC
// K-major SW128 descriptor base: layout=2, version=1, SBO=64, LBO=1
__device__ __forceinline__ uint64_t kdesc(uint32_t addr) {
    const uint64_t base = (uint64_t(2) << 61) | (uint64_t(1) << 46)
                        | (uint64_t(64) << 32) | (uint64_t(1) << 16);
    return base | ((uint64_t)(addr >> 4) & 0x3FFF);
}
#endif

// ======== K0: W split/transpose:  WT[f][k] fp16 hi/lo ========
__global__ __launch_bounds__(256) void k_wsplit(const float* __restrict__ W) {
    __shared__ float tile[32][33];
    const int k0 = blockIdx.x * 32;
    const int f0 = blockIdx.y * 32;
    const int tx = threadIdx.x & 31;
    const int ty = threadIdx.x >> 5;
#pragma unroll
    for (int i = 0; i < 4; i++) {
        int k = k0 + ty + i * 8;
        tile[ty + i * 8][tx] = W[k * 256 + f0 + tx];
    }
    __syncthreads();
#pragma unroll
    for (int i = 0; i < 4; i++) {
        int f = f0 + ty + i * 8;
        float w = tile[tx][ty + i * 8];
        __half hi = __float2half_rn(w);
        __half lo = __float2half_rn(w - __half2float(hi));
        g_WT_hi[f * 256 + k0 + tx] = hi;
        g_WT_lo[f * 256 + k0 + tx] = lo;
    }
}

// ================= K1: Wh = h @ W  (tcgen05 fp16 hi/lo, 3 terms) =========
#define GA_BUF 32768
#define GB_BUF 65536
#define SMEM_DYN_G (2 * GA_BUF + 2 * GB_BUF + 1024)
__global__ __launch_bounds__(512, 1) void k_gemm_tc(const float* __restrict__ h,
                                                    const float* __restrict__ W) {
    extern __shared__ char smraw[];
    const int t = threadIdx.x;
    const int rowbase = blockIdx.x * 128;

#if HAS_TC
    __shared__ uint32_t tmem_ptr_s;
    __shared__ __align__(8) unsigned long long mbar_s[2];

    char* smA = (char*)(((uintptr_t)smraw + 1023) & ~(uintptr_t)1023);
    char* smB = smA + 2 * GA_BUF;
    const uint32_t smA_u  = smem_u32(smA);
    const uint32_t smB_u  = smem_u32(smB);
    const uint32_t mbar_u = smem_u32(&mbar_s[0]);
    const uint32_t tptr_u = smem_u32(&tmem_ptr_s);
    const int wid  = t >> 5;
    const int lane = t & 31;

    if (wid == 0) TC_ALLOC(tptr_u, 256);
    if (t == 0) { MBAR_INIT(mbar_u, 1); MBAR_INIT(mbar_u + 8, 1); }
    __syncthreads();
    uint32_t tmem;
    asm volatile("ld.shared.b32 %0, [%1];" : "=r"(tmem) : "r"(tptr_u));

    int phase[2] = {0, 0};

    for (int kc = 0; kc < 4; kc++) {
        const int buf = kc & 1;
        const int k0  = kc * 64;
        if (kc >= 2) {
            MBAR_WAIT(mbar_u + 8 * buf, phase[buf]);
            phase[buf] ^= 1;
        }
        {
            const uint32_t dstB = smB_u + buf * GB_BUF;
#pragma unroll
            for (int i = 0; i < 8; i++) {
                int idx   = t + i * 512;
                int k4    = idx & 7;
                int n     = (idx >> 3) & 63;
                int chunk = (idx >> 9) & 3;
                int half  = (idx >> 11) & 1;
                const __half* src = half ? g_WT_lo : g_WT_hi;
                const void* g = &src[(chunk * 64 + n) * 256 + k0 + k4 * 8];
                uint32_t off = (uint32_t)(half * 32768 + chunk * 8192)
                             + SWZ128((uint32_t)(n * 128 + k4 * 16));
                cp_async16(dstB + off, g);
            }
            CP_COMMIT();
        }
        {
            char* dstH = smA + buf * GA_BUF;
            char* dstL = dstH + 16384;
#pragma unroll
            for (int i = 0; i < 4; i++) {
                int idx = t + i * 512;
                int row = idx >> 4, q = idx & 15;
                float4 v = *(const float4*)&h[(size_t)(rowbase + row) * 256 + k0 + q * 4];
                __half2 h0 = __floats2half2_rn(v.x, v.y);
                __half2 h1 = __floats2half2_rn(v.z, v.w);
                __half2 l0 = __floats2half2_rn(v.x - __half2float(__low2half(h0)),
                                               v.y - __half2float(__high2half(h0)));
                __half2 l1 = __floats2half2_rn(v.z - __half2float(__low2half(h1)),
                                               v.w - __half2float(__high2half(h1)));
                uint32_t so = SWZ128((uint32_t)(row * 128 + q * 8));
                *(uint32_t*)(dstH + so)     = *(uint32_t*)&h0;
                *(uint32_t*)(dstH + so + 4) = *(uint32_t*)&h1;
                *(uint32_t*)(dstL + so)     = *(uint32_t*)&l0;
                *(uint32_t*)(dstL + so + 4) = *(uint32_t*)&l1;
            }
        }

        CP_WAIT0();
        FENCE_ASYNC_SH();
        __syncthreads();

        if (wid == 0) {
            if (elect1()) {
                const uint32_t abase = smA_u + buf * GA_BUF;
                const uint32_t bbase = smB_u + buf * GB_BUF;
#pragma unroll
                for (int term = 0; term < 3; term++) {
                    const uint64_t ad = kdesc(abase + ((term == 1) ? 16384u : 0u));
                    const uint32_t wh = (term == 2) ? 32768u : 0u;
#pragma unroll
                    for (int chunk = 0; chunk < 4; chunk++) {
                        const uint64_t bd = kdesc(bbase + wh + chunk * 8192);
                        const uint32_t dtm = tmem + chunk * 64;
#pragma unroll
                        for (int ks = 0; ks < 4; ks++) {
                            uint32_t en = (kc != 0) | (term != 0) | (ks != 0);
                            mma_f16_ss(dtm, ad + ks * 2, bd + ks * 2, IDESC_FP16, en);
                        }
                    }
                }
                TC_COMMIT(mbar_u + 8 * buf);
            }
        }
    }

    MBAR_WAIT(mbar_u,     phase[0]);
    MBAR_WAIT(mbar_u + 8, phase[1]);
    TC_FENCE_AFTER();

    if (wid < 8) {
        const int colbase = (wid >> 2) * 128;
        const int row = (wid & 3) * 32 + lane;
        const size_t rowoff = (size_t)(rowbase + row) * 256;
#pragma unroll
        for (int cb = 0; cb < 128; cb += 32) {
            uint32_t d[32];
            TC_LD_X32(d, tmem + colbase + cb);
            TC_WAIT_LD();
#pragma unroll
            for (int q = 0; q < 8; q++) {
                float4 o;
                o.x = __uint_as_float(d[q * 4 + 0]);
                o.y = __uint_as_float(d[q * 4 + 1]);
                o.z = __uint_as_float(d[q * 4 + 2]);
                o.w = __uint_as_float(d[q * 4 + 3]);
                *(float4*)&g_Wh[rowoff + colbase + cb + q * 4] = o;
            }
        }
    }
    __syncthreads();
    if (t == 0) { MBAR_INVAL(mbar_u); MBAR_INVAL(mbar_u + 8); }
    __syncthreads();
    if (wid == 0) TC_DEALLOC(tmem, 256);

#else
    const int row = t >> 2;
    const int cq  = t & 3;
#pragma unroll 1
    for (int pass = 0; pass < 2; pass++) {
        const int c0 = cq * 32 + pass * 128;
        float acc[32];
#pragma unroll
        for (int c = 0; c < 32; c++) acc[c] = 0.f;
        for (int k = 0; k < 256; k++) {
            float hv = h[(size_t)(rowbase + row) * 256 + k];
            const float* wr = &W[k * 256 + c0];
#pragma unroll
            for (int c = 0; c < 32; c++) acc[c] = fmaf(hv, wr[c], acc[c]);
        }
#pragma unroll
        for (int c = 0; c < 32; c++)
            g_Wh[(size_t)(rowbase + row) * 256 + c0 + c] = acc[c];
    }
#endif
}

// ================= K2: s1/s2 row dot products =================
__global__ __launch_bounds__(256) void k_s(const float* __restrict__ a) {
    const int row = blockIdx.x;
    const int t   = threadIdx.x;
    float v  = g_Wh[(size_t)row * 256 + t];
    float p1 = v * a[t];
    float p2 = v * a[256 + t];
#pragma unroll
    for (int o = 16; o; o >>= 1) {
        p1 += __shfl_down_sync(0xffffffffu, p1, o);
        p2 += __shfl_down_sync(0xffffffffu, p2, o);
    }
    __shared__ float r1[8], r2[8];
    if ((t & 31) == 0) { r1[t >> 5] = p1; r2[t >> 5] = p2; }
    __syncthreads();
    if (t == 0) {
        float s1 = 0.f, s2 = 0.f;
#pragma unroll
        for (int w = 0; w < 8; w++) { s1 += r1[w]; s2 += r2[w]; }
        g_s1[row] = s1;
        g_s2[row] = s2;
    }
}

// ======== K3: transpose + fp16:  WhT[b][f][j] ========
__global__ __launch_bounds__(256) void k_tr() {
    __shared__ float tile[32][33];
    const int b  = blockIdx.z;
    const int j0 = blockIdx.x * 32;
    const int f0 = blockIdx.y * 32;
    const int tx = threadIdx.x & 31;
    const int ty = threadIdx.x >> 5;
#pragma unroll
    for (int k = 0; k < 4; k++) {
        int j = j0 + ty + k * 8;
        tile[ty + k * 8][tx] = g_Wh[((size_t)(b * NNODE + j)) * 256 + f0 + tx];
    }
    __syncthreads();
#pragma unroll
    for (int k = 0; k < 4; k++) {
        int f = f0 + ty + k * 8;
        float w = tile[tx][ty + k * 8];
        g_WhT[(((size_t)(b * FEAT + f)) << 11) + j0 + tx] = __float2half_rn(w);
    }
}

// ================= K4: fused attention (softmax stats in-kernel) ==========
// TC path, 544 threads: warps 0-15 produce (8 rows x 2j per lane), warp 16
// issues MMAs. P'' = exp2(x*L2E - 13) fp16, per-row fp32 sums in registers,
// normalization + ELU in the LDTM epilogue. W single fp16 (1 MMA term).
#define P_BUF_BYTES 16384
#define B_BUF_BYTES 32768
#define SMEM_DYN    (2 * P_BUF_BYTES + 2 * B_BUF_BYTES + 1024)   // 99328
__global__ __launch_bounds__(544, 1) void k_attn_tc(const int* __restrict__ adj,
                                                    float* __restrict__ out) {
    extern __shared__ char smraw[];
    __shared__ float s1S[128];
    __shared__ float lsm[128];

    const int t   = threadIdx.x;
    const int b   = blockIdx.y;
    const int i0  = blockIdx.x * 128;
    const int rowbase = b * NNODE + i0;

    if (t < 128) s1S[t] = g_s1[rowbase + t];

#if HAS_TC
    __shared__ uint32_t tmem_ptr_s;
    __shared__ __align__(8) unsigned long long mbar_s[2];

    char* smP = (char*)(((uintptr_t)smraw + 1023) & ~(uintptr_t)1023);
    char* smB = smP + 2 * P_BUF_BYTES;
    const uint32_t smP_u  = smem_u32(smP);
    const uint32_t smB_u  = smem_u32(smB);
    const uint32_t mbar_u = smem_u32(&mbar_s[0]);
    const uint32_t tptr_u = smem_u32(&tmem_ptr_s);
    const int wid  = t >> 5;
    const int lane = t & 31;

    if (wid == 0) TC_ALLOC(tptr_u, 256);
    if (t == 0) { MBAR_INIT(mbar_u, 1); MBAR_INIT(mbar_u + 8, 1); }
    __syncthreads();
    uint32_t tmem;
    asm volatile("ld.shared.b32 %0, [%1];" : "=r"(tmem) : "r"(tptr_u));

    float rs1[8], lsum[8];
    if (wid < 16) {
#pragma unroll
        for (int r = 0; r < 8; r++) {
            rs1[r]  = s1S[wid * 8 + r];
            lsum[r] = 0.f;
        }
    }

    int phase[2] = {0, 0};

    for (int t32 = 0; t32 < NNODE / 64; t32++) {
        const int buf = t32 & 1;
        const int j0  = t32 * 64;
        if (t32 >= 2) {                       // all 17 warps
            MBAR_WAIT(mbar_u + 8 * buf, phase[buf]);
            phase[buf] ^= 1;
        }

        if (wid < 16) {
            // ---- B staging (W single fp16): 4 cp.async/thread
            const uint32_t dstB = smB_u + buf * B_BUF_BYTES;
#pragma unroll
            for (int i = 0; i < 4; i++) {
                int idx   = t + i * 512;      // t < 512 here
                int k4    = idx & 7;
                int n     = (idx >> 3) & 63;
                int chunk = (idx >> 9) & 3;
                const void* g = &g_WhT[(((size_t)(b * FEAT + chunk * 64 + n)) << 11) + j0 + k4 * 8];
                uint32_t off = (uint32_t)(chunk * 8192)
                             + SWZ128((uint32_t)(n * 128 + k4 * 16));
                cp_async16(dstB + off, g);
            }
            CP_COMMIT();

            // ---- produce P'' tile + row sums
            char* dstP = smP + buf * P_BUF_BYTES;
            float2 s2v = *(const float2*)&g_s2[b * NNODE + j0 + lane * 2];
#pragma unroll
            for (int r = 0; r < 8; r++) {
                const int row = wid * 8 + r;
                int2 av = *(const int2*)&adj[(size_t)(rowbase + row) * NNODE + j0 + lane * 2];
                float x0 = rs1[r] + s2v.x;
                float x1 = rs1[r] + s2v.y;
                x0 = fmaxf(x0, ALPHA_LR * x0);
                x1 = fmaxf(x1, ALPHA_LR * x1);
                float a0 = fmaf(x0, L2E, -PSHIFT);
                float a1 = fmaf(x1, L2E, -PSHIFT);
                a0 = (av.x > 0) ? a0 : -1e30f;
                a1 = (av.y > 0) ? a1 : -1e30f;
                float e0 = exp2f(a0);
                float e1 = exp2f(a1);
                lsum[r] += e0 + e1;
                __half2 hh = __floats2half2_rn(e0, e1);
                uint32_t off = SWZ128((uint32_t)(row * 128 + lane * 4));
                *(uint32_t*)(dstP + off) = *(uint32_t*)&hh;
            }
            CP_WAIT0();
            FENCE_ASYNC_SH();
        }
        __syncthreads();

        // ---- dedicated MMA warp: issue + commit (overlaps next produce)
        if (wid == 16) {
            if (elect1()) {
                const uint64_t ad0   = kdesc(smP_u + buf * P_BUF_BYTES);
                const uint32_t bbase = smB_u + buf * B_BUF_BYTES;
#pragma unroll
                for (int chunk = 0; chunk < 4; chunk++) {
                    const uint64_t bd = kdesc(bbase + chunk * 8192);
                    const uint32_t dtm = tmem + chunk * 64;
#pragma unroll
                    for (int ks = 0; ks < 4; ks++) {
                        uint32_t en = (t32 != 0) | (ks != 0);
                        mma_f16_ss(dtm, ad0 + ks * 2, bd + ks * 2, IDESC_FP16, en);
                    }
                }
                TC_COMMIT(mbar_u + 8 * buf);
            }
        }
    }

    // ---- row-sum reduction -> smem
    if (wid < 16) {
#pragma unroll
        for (int r = 0; r < 8; r++) {
            float v = lsum[r];
#pragma unroll
            for (int o = 16; o; o >>= 1) v += __shfl_down_sync(0xffffffffu, v, o);
            if (lane == 0) lsm[wid * 8 + r] = v;
        }
    }

    // drain
    MBAR_WAIT(mbar_u,     phase[0]);
    MBAR_WAIT(mbar_u + 8, phase[1]);
    TC_FENCE_AFTER();
    __syncthreads();   // lsm visible

    // ---- epilogue: LDTM, normalize, ELU, store
    if (wid < 8) {
        const int colbase = (wid >> 2) * 128;
        const int row = (wid & 3) * 32 + lane;
        const float sf = 1.0f / lsm[row];
        const size_t rowoff = (size_t)(rowbase + row) * 256;
#pragma unroll
        for (int cb = 0; cb < 128; cb += 32) {
            uint32_t d[32];
            TC_LD_X32(d, tmem + colbase + cb);
            TC_WAIT_LD();
#pragma unroll
            for (int q = 0; q < 8; q++) {
                float v0 = __uint_as_float(d[q * 4 + 0]) * sf;
                float v1 = __uint_as_float(d[q * 4 + 1]) * sf;
                float v2 = __uint_as_float(d[q * 4 + 2]) * sf;
                float v3 = __uint_as_float(d[q * 4 + 3]) * sf;
                float4 o;
                o.x = (v0 > 0.f) ? v0 : expm1f(v0);
                o.y = (v1 > 0.f) ? v1 : expm1f(v1);
                o.z = (v2 > 0.f) ? v2 : expm1f(v2);
                o.w = (v3 > 0.f) ? v3 : expm1f(v3);
                *(float4*)&out[rowoff + colbase + cb + q * 4] = o;
            }
        }
    }
    __syncthreads();
    if (t == 0) { MBAR_INVAL(mbar_u); MBAR_INVAL(mbar_u + 8); }
    __syncthreads();
    if (wid == 0) TC_DEALLOC(tmem, 256);

#else
    // ============== fallback (never runs on sm_103a; must compile) ========
    float (*whS)[128] = (float (*)[128])smraw;
    float (*pS)[128]  = (float (*)[128])(smraw + 8192);

    const int tr = t >> 4, tc = t & 15;
    const int w_kk = t >> 4, w_f0 = (t & 15) * 8;
    const int p_r  = t >> 1, p_kq = (t & 1) * 8;
    const bool act = (t < 256);

    if (t < 128) lsm[t] = 0.f;
    __syncthreads();

    for (int fb = 0; fb < 256; fb += 128) {
        unsigned long long acc[4][8];
#pragma unroll
        for (int i = 0; i < 4; i++)
#pragma unroll
            for (int c = 0; c < 8; c++) acc[i][c] = 0ull;

        for (int j0 = 0; j0 < NNODE; j0 += 16) {
            __syncthreads();
            if (act) {
                const float* src = &g_Wh[((size_t)(b * NNODE + j0 + w_kk)) * 256 + fb + w_f0];
                float4 v0 = *(const float4*)src;
                float4 v1 = *(const float4*)(src + 4);
                *(float4*)&whS[w_kk][w_f0]     = v0;
                *(float4*)&whS[w_kk][w_f0 + 4] = v1;

                const int* ar = &adj[((size_t)(rowbase + p_r)) * NNODE + j0 + p_kq];
                int4 a0 = *(const int4*)ar;
                int4 a1 = *(const int4*)(ar + 4);
                int av[8] = {a0.x, a0.y, a0.z, a0.w, a1.x, a1.y, a1.z, a1.w};
                float s1v = s1S[p_r];
                const float* s2p = &g_s2[b * NNODE + j0 + p_kq];
                float ls = 0.f;
#pragma unroll
                for (int i = 0; i < 8; i++) {
                    float x = s1v + s2p[i];
                    x = fmaxf(x, ALPHA_LR * x);
                    float aa = fmaf(x, L2E, -PSHIFT);
                    aa = (av[i] > 0) ? aa : -1e30f;
                    float e = exp2f(aa);
                    pS[p_kq + i][p_r] = e;
                    ls += e;
                }
                if (fb == 0) atomicAdd(&lsm[p_r], ls);
            }
            __syncthreads();

            if (act) {
#pragma unroll 4
                for (int kk = 0; kk < 16; kk++) {
                    ulonglong2 pA = *(const ulonglong2*)&pS[kk][tr * 4];
                    ulonglong2 pB = *(const ulonglong2*)&pS[kk][64 + tr * 4];
                    float4 wA = *(const float4*)&whS[kk][tc * 4];
                    float4 wB = *(const float4*)&whS[kk][64 + tc * 4];
                    unsigned long long w2[8];
                    w2[0] = dup2(wA.x); w2[1] = dup2(wA.y);
                    w2[2] = dup2(wA.z); w2[3] = dup2(wA.w);
                    w2[4] = dup2(wB.x); w2[5] = dup2(wB.y);
                    w2[6] = dup2(wB.z); w2[7] = dup2(wB.w);
#pragma unroll
                    for (int c = 0; c < 8; c++) {
                        fma2(acc[0][c], pA.x, w2[c]);
                        fma2(acc[1][c], pA.y, w2[c]);
                        fma2(acc[2][c], pB.x, w2[c]);
                        fma2(acc[3][c], pB.y, w2[c]);
                    }
                }
            }
        }
        __syncthreads();   // lsm complete before reads

        if (act) {
#pragma unroll
            for (int ip = 0; ip < 4; ip++) {
                int rloc = (ip < 2) ? (tr * 4 + ip * 2) : (64 + tr * 4 + (ip - 2) * 2);
                float sf0 = 1.0f / lsm[rloc];
                float sf1 = 1.0f / lsm[rloc + 1];
                float lo[8], hi[8];
#pragma unroll
                for (int c = 0; c < 8; c++) unpack2(acc[ip][c], lo[c], hi[c]);
#pragma unroll
                for (int h2 = 0; h2 < 2; h2++) {
                    float* v = h2 ? hi : lo;
                    float sf = h2 ? sf1 : sf0;
                    size_t rowoff = ((size_t)(rowbase + rloc + h2)) * 256;
                    float4 oA, oB;
                    float u0 = v[0] * sf, u1 = v[1] * sf, u2 = v[2] * sf, u3 = v[3] * sf;
                    float u4 = v[4] * sf, u5 = v[5] * sf, u6 = v[6] * sf, u7 = v[7] * sf;
                    oA.x = (u0 > 0.f) ? u0 : expm1f(u0);
                    oA.y = (u1 > 0.f) ? u1 : expm1f(u1);
                    oA.z = (u2 > 0.f) ? u2 : expm1f(u2);
                    oA.w = (u3 > 0.f) ? u3 : expm1f(u3);
                    oB.x = (u4 > 0.f) ? u4 : expm1f(u4);
                    oB.y = (u5 > 0.f) ? u5 : expm1f(u5);
                    oB.z = (u6 > 0.f) ? u6 : expm1f(u6);
                    oB.w = (u7 > 0.f) ? u7 : expm1f(u7);
                    *(float4*)&out[rowoff + fb + tc * 4]      = oA;
                    *(float4*)&out[rowoff + fb + 64 + tc * 4] = oB;
                }
            }
        }
    }
#endif
}

// ================= launcher =================
extern "C" void kernel_launch(void* const* d_in, const int* in_sizes, int n_in,
                              void* d_out, int out_size) {
    const float* h   = (const float*)d_in[0];   // (8,2048,256) f32
    const int*   adj = (const int*)  d_in[1];   // (8,2048,2048) i32
    const float* W   = (const float*)d_in[2];   // (256,256) f32
    const float* a   = (const float*)d_in[3];   // (512,1) f32
    float* out = (float*)d_out;                 // (8,2048,256) f32

    cudaFuncSetAttribute(k_gemm_tc, cudaFuncAttributeMaxDynamicSharedMemorySize,
                         SMEM_DYN_G);
    cudaFuncSetAttribute(k_attn_tc, cudaFuncAttributeMaxDynamicSharedMemorySize,
                         SMEM_DYN);

    k_wsplit<<<dim3(8, 8), 256>>>(W);
    k_gemm_tc<<<ROWS / 128, 512, SMEM_DYN_G>>>(h, W);
    k_s   <<<ROWS, 256>>>(a);
    k_tr  <<<dim3(NNODE / 32, FEAT / 32, BATCH), 256>>>();
    k_attn_tc<<<dim3(NNODE / 128, BATCH), 544, SMEM_DYN>>>(adj, out);
}

// round 11
// speedup vs baseline: 8.2361x; 1.3080x over previous
#include <cuda_runtime.h>
#include <cuda_bf16.h>
#include <cuda_fp16.h>
#include <math.h>
#include <stdint.h>

#define BATCH 8
#define NNODE 2048
#define FEAT  256
#define ROWS  (BATCH * NNODE)   // 16384
#define ALPHA_LR 0.2f
#define NEG_BIG  -9.0e15f
#define L2E      1.4426950408889634f
#define PSHIFT   13.0f           // P'' = exp2(x*L2E - PSHIFT); epilogue divides by sum

#if defined(__CUDA_ARCH_FEAT_SM103_ALL) || defined(__CUDA_ARCH_FEAT_SM100_ALL)
#define HAS_TC 1
#else
#define HAS_TC 0
#endif

// -------- scratch (device globals; no allocation allowed) --------
__device__ float g_Wh[(size_t)ROWS * FEAT];               // 16 MB fp32 (fallback path only)
__device__ __half g_WhT[(size_t)BATCH * FEAT * NNODE];    // 8 MB  Wh^T fp16
__device__ __half g_WT_hi[FEAT * FEAT];                   // 128 KB W^T hi [f][k]
__device__ __half g_WT_lo[FEAT * FEAT];                   // 128 KB W^T lo [f][k]
__device__ float g_s1[ROWS];
__device__ float g_s2[ROWS];

// ======================= helpers =======================
__device__ __forceinline__ uint32_t smem_u32(const void* p) {
    uint32_t a;
    asm("{ .reg .u64 t; cvta.to.shared.u64 t, %1; cvt.u32.u64 %0, t; }"
        : "=r"(a) : "l"(p));
    return a;
}
// packed fp32x2 (used by fallback path)
__device__ __forceinline__ void fma2(unsigned long long& d,
                                     unsigned long long a,
                                     unsigned long long b) {
    asm("fma.rn.f32x2 %0, %1, %2, %0;" : "+l"(d) : "l"(a), "l"(b));
}
__device__ __forceinline__ unsigned long long dup2(float w) {
    unsigned long long r;
    asm("mov.b64 %0, {%1, %1};" : "=l"(r) : "f"(w));
    return r;
}
__device__ __forceinline__ void unpack2(unsigned long long v, float& lo, float& hi) {
    asm("mov.b64 {%0, %1}, %2;" : "=f"(lo), "=f"(hi) : "l"(v));
}
// cp.async 16B (sm_80+, safe in all compile passes)
__device__ __forceinline__ void cp_async16(uint32_t dst, const void* src) {
    asm volatile("cp.async.cg.shared.global [%0], [%1], 16;" :: "r"(dst), "l"(src));
}
#define CP_COMMIT() asm volatile("cp.async.commit_group;" ::: "memory")
#define CP_WAIT0()  asm volatile("cp.async.wait_group 0;" ::: "memory")

#if HAS_TC
__device__ __forceinline__ uint32_t elect1() {
    uint32_t p;
    asm volatile("{ .reg .pred p; elect.sync _|p, 0xFFFFFFFF; selp.b32 %0,1,0,p; }"
                 : "=r"(p));
    return p;
}
#define TC_ALLOC(sm, n)   asm volatile("tcgen05.alloc.cta_group::1.sync.aligned.shared::cta.b32 [%0], %1;" :: "r"(sm), "r"(n) : "memory")
#define TC_DEALLOC(t, n)  asm volatile("tcgen05.dealloc.cta_group::1.sync.aligned.b32 %0, %1;" :: "r"(t), "r"(n))
#define TC_WAIT_LD()      asm volatile("tcgen05.wait::ld.sync.aligned;" ::: "memory")
#define TC_FENCE_AFTER()  asm volatile("tcgen05.fence::after_thread_sync;" ::: "memory")
#define FENCE_ASYNC_SH()  asm volatile("fence.proxy.async.shared::cta;" ::: "memory")
#define TC_COMMIT(mb)     asm volatile("tcgen05.commit.cta_group::1.mbarrier::arrive::one.shared::cluster.b64 [%0];" :: "r"(mb) : "memory")
#define MBAR_INIT(mb, c)  asm volatile("mbarrier.init.shared.b64 [%0], %1;" :: "r"(mb), "r"(c) : "memory")
#define MBAR_INVAL(mb)    asm volatile("mbarrier.inval.shared.b64 [%0];" :: "r"(mb) : "memory")

#define MBAR_WAIT(mb, ph) do {                                                   \
    uint32_t _mb = (mb); uint32_t _ph = (ph); uint32_t _done;                    \
    asm volatile("{ .reg .pred p; mbarrier.try_wait.parity.acquire.cta.shared::cta.b64 p, [%1], %2; selp.b32 %0,1,0,p; }" \
                 : "=r"(_done) : "r"(_mb), "r"(_ph) : "memory");                 \
    if (!_done) {                                                                \
        asm volatile("{ .reg .pred P1; WL_%=: mbarrier.try_wait.parity.acquire.cta.shared::cta.b64 P1, [%0], %1, 0x989680; @P1 bra.uni WD_%=; bra.uni WL_%=; WD_%=: }" \
                     :: "r"(_mb), "r"(_ph) : "memory");                          \
    }                                                                            \
} while (0)

#define TC_LD_X32(r, tm)                                                         \
    asm volatile("tcgen05.ld.sync.aligned.32x32b.x32.b32 "                       \
        "{%0,%1,%2,%3,%4,%5,%6,%7,%8,%9,%10,%11,%12,%13,%14,%15,"                \
        "%16,%17,%18,%19,%20,%21,%22,%23,%24,%25,%26,%27,%28,%29,%30,%31}, [%32];" \
        : "=r"((r)[0]),  "=r"((r)[1]),  "=r"((r)[2]),  "=r"((r)[3]),             \
          "=r"((r)[4]),  "=r"((r)[5]),  "=r"((r)[6]),  "=r"((r)[7]),             \
          "=r"((r)[8]),  "=r"((r)[9]),  "=r"((r)[10]), "=r"((r)[11]),            \
          "=r"((r)[12]), "=r"((r)[13]), "=r"((r)[14]), "=r"((r)[15]),            \
          "=r"((r)[16]), "=r"((r)[17]), "=r"((r)[18]), "=r"((r)[19]),            \
          "=r"((r)[20]), "=r"((r)[21]), "=r"((r)[22]), "=r"((r)[23]),            \
          "=r"((r)[24]), "=r"((r)[25]), "=r"((r)[26]), "=r"((r)[27]),            \
          "=r"((r)[28]), "=r"((r)[29]), "=r"((r)[30]), "=r"((r)[31])             \
        : "r"(tm))

// SS-mode fp16 MMA: A and B both via SMEM descriptors
__device__ __forceinline__ void mma_f16_ss(uint32_t d, uint64_t adesc, uint64_t bdesc,
                                           uint32_t idesc, uint32_t en) {
    asm volatile("{ .reg .pred p; setp.ne.u32 p, %4, 0;\n\t"
        "tcgen05.mma.cta_group::1.kind::f16 [%0], %1, %2, %3, {%5,%5,%5,%5}, p;\n\t}"
        :: "r"(d), "l"(adesc), "l"(bdesc), "r"(idesc), "r"(en), "r"(0u) : "memory");
}

// idesc kind::f16: dtype=F32, atype=btype=FP16(0), N=64, M=128
#define IDESC_FP16 ((1u << 4) | (8u << 17) | (8u << 24))
#endif // HAS_TC

#define SWZ128(x) ((x) ^ (((x) >> 3) & 0x70))
#if HAS_TC
// K-major SW128 descriptor base: layout=2, version=1, SBO=64, LBO=1
__device__ __forceinline__ uint64_t kdesc(uint32_t addr) {
    const uint64_t base = (uint64_t(2) << 61) | (uint64_t(1) << 46)
                        | (uint64_t(64) << 32) | (uint64_t(1) << 16);
    return base | ((uint64_t)(addr >> 4) & 0x3FFF);
}
#endif

// ======== K0: W split/transpose:  WT[f][k] fp16 hi/lo ========
__global__ __launch_bounds__(256) void k_wsplit(const float* __restrict__ W) {
    __shared__ float tile[32][33];
    const int k0 = blockIdx.x * 32;
    const int f0 = blockIdx.y * 32;
    const int tx = threadIdx.x & 31;
    const int ty = threadIdx.x >> 5;
#pragma unroll
    for (int i = 0; i < 4; i++) {
        int k = k0 + ty + i * 8;
        tile[ty + i * 8][tx] = W[k * 256 + f0 + tx];
    }
    __syncthreads();
#pragma unroll
    for (int i = 0; i < 4; i++) {
        int f = f0 + ty + i * 8;
        float w = tile[tx][ty + i * 8];
        __half hi = __float2half_rn(w);
        __half lo = __float2half_rn(w - __half2float(hi));
        g_WT_hi[f * 256 + k0 + tx] = hi;
        g_WT_lo[f * 256 + k0 + tx] = lo;
    }
}

// ====== K1: Wh = h @ W (tcgen05) + fused s1/s2 + fused WhT fp16 transpose ==
#define GA_BUF 32768
#define GB_BUF 65536
#define SMEM_DYN_G (2 * GA_BUF + 2 * GB_BUF + 1024)
__global__ __launch_bounds__(512, 1) void k_gemm_tc(const float* __restrict__ h,
                                                    const float* __restrict__ W,
                                                    const float* __restrict__ avec) {
    extern __shared__ char smraw[];
    __shared__ float2 aS[256];
    __shared__ float s1p[128], s2p[128];
    const int t = threadIdx.x;
    const int rowbase = blockIdx.x * 128;

    if (t < 256) aS[t] = make_float2(avec[t], avec[256 + t]);
    if (t < 128) { s1p[t] = 0.f; s2p[t] = 0.f; }

#if HAS_TC
    __shared__ uint32_t tmem_ptr_s;
    __shared__ __align__(8) unsigned long long mbar_s[2];

    char* smA = (char*)(((uintptr_t)smraw + 1023) & ~(uintptr_t)1023);
    char* smB = smA + 2 * GA_BUF;
    const uint32_t smA_u  = smem_u32(smA);
    const uint32_t smB_u  = smem_u32(smB);
    const uint32_t mbar_u = smem_u32(&mbar_s[0]);
    const uint32_t tptr_u = smem_u32(&tmem_ptr_s);
    const int wid  = t >> 5;
    const int lane = t & 31;

    if (wid == 0) TC_ALLOC(tptr_u, 256);
    if (t == 0) { MBAR_INIT(mbar_u, 1); MBAR_INIT(mbar_u + 8, 1); }
    __syncthreads();
    uint32_t tmem;
    asm volatile("ld.shared.b32 %0, [%1];" : "=r"(tmem) : "r"(tptr_u));

    int phase[2] = {0, 0};

    for (int kc = 0; kc < 4; kc++) {
        const int buf = kc & 1;
        const int k0  = kc * 64;
        if (kc >= 2) {
            MBAR_WAIT(mbar_u + 8 * buf, phase[buf]);
            phase[buf] ^= 1;
        }
        {
            const uint32_t dstB = smB_u + buf * GB_BUF;
#pragma unroll
            for (int i = 0; i < 8; i++) {
                int idx   = t + i * 512;
                int k4    = idx & 7;
                int n     = (idx >> 3) & 63;
                int chunk = (idx >> 9) & 3;
                int half  = (idx >> 11) & 1;
                const __half* src = half ? g_WT_lo : g_WT_hi;
                const void* g = &src[(chunk * 64 + n) * 256 + k0 + k4 * 8];
                uint32_t off = (uint32_t)(half * 32768 + chunk * 8192)
                             + SWZ128((uint32_t)(n * 128 + k4 * 16));
                cp_async16(dstB + off, g);
            }
            CP_COMMIT();
        }
        {
            char* dstH = smA + buf * GA_BUF;
            char* dstL = dstH + 16384;
#pragma unroll
            for (int i = 0; i < 4; i++) {
                int idx = t + i * 512;
                int row = idx >> 4, q = idx & 15;
                float4 v = *(const float4*)&h[(size_t)(rowbase + row) * 256 + k0 + q * 4];
                __half2 h0 = __floats2half2_rn(v.x, v.y);
                __half2 h1 = __floats2half2_rn(v.z, v.w);
                __half2 l0 = __floats2half2_rn(v.x - __half2float(__low2half(h0)),
                                               v.y - __half2float(__high2half(h0)));
                __half2 l1 = __floats2half2_rn(v.z - __half2float(__low2half(h1)),
                                               v.w - __half2float(__high2half(h1)));
                uint32_t so = SWZ128((uint32_t)(row * 128 + q * 8));
                *(uint32_t*)(dstH + so)     = *(uint32_t*)&h0;
                *(uint32_t*)(dstH + so + 4) = *(uint32_t*)&h1;
                *(uint32_t*)(dstL + so)     = *(uint32_t*)&l0;
                *(uint32_t*)(dstL + so + 4) = *(uint32_t*)&l1;
            }
        }

        CP_WAIT0();
        FENCE_ASYNC_SH();
        __syncthreads();

        if (wid == 0) {
            if (elect1()) {
                const uint32_t abase = smA_u + buf * GA_BUF;
                const uint32_t bbase = smB_u + buf * GB_BUF;
#pragma unroll
                for (int term = 0; term < 3; term++) {
                    const uint64_t ad = kdesc(abase + ((term == 1) ? 16384u : 0u));
                    const uint32_t wh = (term == 2) ? 32768u : 0u;
#pragma unroll
                    for (int chunk = 0; chunk < 4; chunk++) {
                        const uint64_t bd = kdesc(bbase + wh + chunk * 8192);
                        const uint32_t dtm = tmem + chunk * 64;
#pragma unroll
                        for (int ks = 0; ks < 4; ks++) {
                            uint32_t en = (kc != 0) | (term != 0) | (ks != 0);
                            mma_f16_ss(dtm, ad + ks * 2, bd + ks * 2, IDESC_FP16, en);
                        }
                    }
                }
                TC_COMMIT(mbar_u + 8 * buf);
            }
        }
    }

    MBAR_WAIT(mbar_u,     phase[0]);
    MBAR_WAIT(mbar_u + 8, phase[1]);
    TC_FENCE_AFTER();

    // ---- fused epilogue: WhT fp16 (transposed scatter, 64B/warp coalesced)
    //      + s1/s2 partial dots
    if (wid < 8) {
        const int colbase = (wid >> 2) * 128;
        const int row = (wid & 3) * 32 + lane;
        const int grow = rowbase + row;
        const int b2 = grow >> 11;
        const int j  = grow & 2047;
        float p1 = 0.f, p2 = 0.f;
#pragma unroll
        for (int cb = 0; cb < 128; cb += 32) {
            uint32_t d[32];
            TC_LD_X32(d, tmem + colbase + cb);
            TC_WAIT_LD();
#pragma unroll
            for (int e = 0; e < 32; e++) {
                const int f = colbase + cb + e;
                float v = __uint_as_float(d[e]);
                float2 av = aS[f];
                p1 = fmaf(v, av.x, p1);
                p2 = fmaf(v, av.y, p2);
                g_WhT[(((size_t)(b2 * 256 + f)) << 11) + j] = __float2half_rn(v);
            }
        }
        atomicAdd(&s1p[row], p1);
        atomicAdd(&s2p[row], p2);
    }
    __syncthreads();
    if (t < 128) {
        g_s1[rowbase + t] = s1p[t];
        g_s2[rowbase + t] = s2p[t];
    }
    if (t == 0) { MBAR_INVAL(mbar_u); MBAR_INVAL(mbar_u + 8); }
    __syncthreads();
    if (wid == 0) TC_DEALLOC(tmem, 256);

#else
    // ---- fallback: SIMT fp32 gemm + s1/s2 (g_Wh for fallback attn) ----
    float* sp1 = (float*)smraw;            // [128][4]
    float* sp2 = sp1 + 512;
    const int row = t >> 2;
    const int cq  = t & 3;
    float p1 = 0.f, p2 = 0.f;
#pragma unroll 1
    for (int pass = 0; pass < 2; pass++) {
        const int c0 = cq * 32 + pass * 128;
        float acc[32];
#pragma unroll
        for (int c = 0; c < 32; c++) acc[c] = 0.f;
        for (int k = 0; k < 256; k++) {
            float hv = h[(size_t)(rowbase + row) * 256 + k];
            const float* wr = &W[k * 256 + c0];
#pragma unroll
            for (int c = 0; c < 32; c++) acc[c] = fmaf(hv, wr[c], acc[c]);
        }
#pragma unroll
        for (int c = 0; c < 32; c++) {
            g_Wh[(size_t)(rowbase + row) * 256 + c0 + c] = acc[c];
            p1 = fmaf(acc[c], avec[c0 + c], p1);
            p2 = fmaf(acc[c], avec[256 + c0 + c], p2);
        }
    }
    sp1[row * 4 + cq] = p1;
    sp2[row * 4 + cq] = p2;
    __syncthreads();
    if (cq == 0) {
        float s1 = sp1[row * 4] + sp1[row * 4 + 1] + sp1[row * 4 + 2] + sp1[row * 4 + 3];
        float s2 = sp2[row * 4] + sp2[row * 4 + 1] + sp2[row * 4 + 2] + sp2[row * 4 + 3];
        g_s1[rowbase + row] = s1;
        g_s2[rowbase + row] = s2;
    }
#endif
}

// ================= K4: fused attention (softmax stats in-kernel) ==========
// TC path, 544 threads: warps 0-15 produce (8 rows x 2j per lane), warp 16
// issues MMAs. P'' = exp2(x*L2E - 13) fp16, per-row fp32 sums in registers,
// normalization + ELU in the LDTM epilogue. W single fp16 (1 MMA term).
#define P_BUF_BYTES 16384
#define B_BUF_BYTES 32768
#define SMEM_DYN    (2 * P_BUF_BYTES + 2 * B_BUF_BYTES + 1024)   // 99328
__global__ __launch_bounds__(544, 1) void k_attn_tc(const int* __restrict__ adj,
                                                    float* __restrict__ out) {
    extern __shared__ char smraw[];
    __shared__ float s1S[128];
    __shared__ float lsm[128];

    const int t   = threadIdx.x;
    const int b   = blockIdx.y;
    const int i0  = blockIdx.x * 128;
    const int rowbase = b * NNODE + i0;

    if (t < 128) s1S[t] = g_s1[rowbase + t];

#if HAS_TC
    __shared__ uint32_t tmem_ptr_s;
    __shared__ __align__(8) unsigned long long mbar_s[2];

    char* smP = (char*)(((uintptr_t)smraw + 1023) & ~(uintptr_t)1023);
    char* smB = smP + 2 * P_BUF_BYTES;
    const uint32_t smP_u  = smem_u32(smP);
    const uint32_t smB_u  = smem_u32(smB);
    const uint32_t mbar_u = smem_u32(&mbar_s[0]);
    const uint32_t tptr_u = smem_u32(&tmem_ptr_s);
    const int wid  = t >> 5;
    const int lane = t & 31;

    if (wid == 0) TC_ALLOC(tptr_u, 256);
    if (t == 0) { MBAR_INIT(mbar_u, 1); MBAR_INIT(mbar_u + 8, 1); }
    __syncthreads();
    uint32_t tmem;
    asm volatile("ld.shared.b32 %0, [%1];" : "=r"(tmem) : "r"(tptr_u));

    float rs1[8], lsum[8];
    if (wid < 16) {
#pragma unroll
        for (int r = 0; r < 8; r++) {
            rs1[r]  = s1S[wid * 8 + r];
            lsum[r] = 0.f;
        }
    }

    int phase[2] = {0, 0};

    for (int t32 = 0; t32 < NNODE / 64; t32++) {
        const int buf = t32 & 1;
        const int j0  = t32 * 64;
        if (t32 >= 2) {                       // all 17 warps
            MBAR_WAIT(mbar_u + 8 * buf, phase[buf]);
            phase[buf] ^= 1;
        }

        if (wid < 16) {
            // ---- B staging (W single fp16): 4 cp.async/thread
            const uint32_t dstB = smB_u + buf * B_BUF_BYTES;
#pragma unroll
            for (int i = 0; i < 4; i++) {
                int idx   = t + i * 512;      // t < 512 here
                int k4    = idx & 7;
                int n     = (idx >> 3) & 63;
                int chunk = (idx >> 9) & 3;
                const void* g = &g_WhT[(((size_t)(b * FEAT + chunk * 64 + n)) << 11) + j0 + k4 * 8];
                uint32_t off = (uint32_t)(chunk * 8192)
                             + SWZ128((uint32_t)(n * 128 + k4 * 16));
                cp_async16(dstB + off, g);
            }
            CP_COMMIT();

            // ---- produce P'' tile + row sums
            char* dstP = smP + buf * P_BUF_BYTES;
            float2 s2v = *(const float2*)&g_s2[b * NNODE + j0 + lane * 2];
#pragma unroll
            for (int r = 0; r < 8; r++) {
                const int row = wid * 8 + r;
                int2 av = *(const int2*)&adj[(size_t)(rowbase + row) * NNODE + j0 + lane * 2];
                float x0 = rs1[r] + s2v.x;
                float x1 = rs1[r] + s2v.y;
                x0 = fmaxf(x0, ALPHA_LR * x0);
                x1 = fmaxf(x1, ALPHA_LR * x1);
                float a0 = fmaf(x0, L2E, -PSHIFT);
                float a1 = fmaf(x1, L2E, -PSHIFT);
                a0 = (av.x > 0) ? a0 : -1e30f;
                a1 = (av.y > 0) ? a1 : -1e30f;
                float e0 = exp2f(a0);
                float e1 = exp2f(a1);
                lsum[r] += e0 + e1;
                __half2 hh = __floats2half2_rn(e0, e1);
                uint32_t off = SWZ128((uint32_t)(row * 128 + lane * 4));
                *(uint32_t*)(dstP + off) = *(uint32_t*)&hh;
            }
            CP_WAIT0();
            FENCE_ASYNC_SH();
        }
        __syncthreads();

        // ---- dedicated MMA warp: issue + commit (overlaps next produce)
        if (wid == 16) {
            if (elect1()) {
                const uint64_t ad0   = kdesc(smP_u + buf * P_BUF_BYTES);
                const uint32_t bbase = smB_u + buf * B_BUF_BYTES;
#pragma unroll
                for (int chunk = 0; chunk < 4; chunk++) {
                    const uint64_t bd = kdesc(bbase + chunk * 8192);
                    const uint32_t dtm = tmem + chunk * 64;
#pragma unroll
                    for (int ks = 0; ks < 4; ks++) {
                        uint32_t en = (t32 != 0) | (ks != 0);
                        mma_f16_ss(dtm, ad0 + ks * 2, bd + ks * 2, IDESC_FP16, en);
                    }
                }
                TC_COMMIT(mbar_u + 8 * buf);
            }
        }
    }

    // ---- row-sum reduction -> smem
    if (wid < 16) {
#pragma unroll
        for (int r = 0; r < 8; r++) {
            float v = lsum[r];
#pragma unroll
            for (int o = 16; o; o >>= 1) v += __shfl_down_sync(0xffffffffu, v, o);
            if (lane == 0) lsm[wid * 8 + r] = v;
        }
    }

    // drain
    MBAR_WAIT(mbar_u,     phase[0]);
    MBAR_WAIT(mbar_u + 8, phase[1]);
    TC_FENCE_AFTER();
    __syncthreads();   // lsm visible

    // ---- epilogue: LDTM, normalize, ELU, store
    if (wid < 8) {
        const int colbase = (wid >> 2) * 128;
        const int row = (wid & 3) * 32 + lane;
        const float sf = 1.0f / lsm[row];
        const size_t rowoff = (size_t)(rowbase + row) * 256;
#pragma unroll
        for (int cb = 0; cb < 128; cb += 32) {
            uint32_t d[32];
            TC_LD_X32(d, tmem + colbase + cb);
            TC_WAIT_LD();
#pragma unroll
            for (int q = 0; q < 8; q++) {
                float v0 = __uint_as_float(d[q * 4 + 0]) * sf;
                float v1 = __uint_as_float(d[q * 4 + 1]) * sf;
                float v2 = __uint_as_float(d[q * 4 + 2]) * sf;
                float v3 = __uint_as_float(d[q * 4 + 3]) * sf;
                float4 o;
                o.x = (v0 > 0.f) ? v0 : expm1f(v0);
                o.y = (v1 > 0.f) ? v1 : expm1f(v1);
                o.z = (v2 > 0.f) ? v2 : expm1f(v2);
                o.w = (v3 > 0.f) ? v3 : expm1f(v3);
                *(float4*)&out[rowoff + colbase + cb + q * 4] = o;
            }
        }
    }
    __syncthreads();
    if (t == 0) { MBAR_INVAL(mbar_u); MBAR_INVAL(mbar_u + 8); }
    __syncthreads();
    if (wid == 0) TC_DEALLOC(tmem, 256);

#else
    // ============== fallback (never runs on sm_103a; must compile) ========
    float (*whS)[128] = (float (*)[128])smraw;
    float (*pS)[128]  = (float (*)[128])(smraw + 8192);

    const int tr = t >> 4, tc = t & 15;
    const int w_kk = t >> 4, w_f0 = (t & 15) * 8;
    const int p_r  = t >> 1, p_kq = (t & 1) * 8;
    const bool act = (t < 256);

    if (t < 128) lsm[t] = 0.f;
    __syncthreads();

    for (int fb = 0; fb < 256; fb += 128) {
        unsigned long long acc[4][8];
#pragma unroll
        for (int i = 0; i < 4; i++)
#pragma unroll
            for (int c = 0; c < 8; c++) acc[i][c] = 0ull;

        for (int j0 = 0; j0 < NNODE; j0 += 16) {
            __syncthreads();
            if (act) {
                const float* src = &g_Wh[((size_t)(b * NNODE + j0 + w_kk)) * 256 + fb + w_f0];
                float4 v0 = *(const float4*)src;
                float4 v1 = *(const float4*)(src + 4);
                *(float4*)&whS[w_kk][w_f0]     = v0;
                *(float4*)&whS[w_kk][w_f0 + 4] = v1;

                const int* ar = &adj[((size_t)(rowbase + p_r)) * NNODE + j0 + p_kq];
                int4 a0 = *(const int4*)ar;
                int4 a1 = *(const int4*)(ar + 4);
                int av[8] = {a0.x, a0.y, a0.z, a0.w, a1.x, a1.y, a1.z, a1.w};
                float s1v = s1S[p_r];
                const float* s2p = &g_s2[b * NNODE + j0 + p_kq];
                float ls = 0.f;
#pragma unroll
                for (int i = 0; i < 8; i++) {
                    float x = s1v + s2p[i];
                    x = fmaxf(x, ALPHA_LR * x);
                    float aa = fmaf(x, L2E, -PSHIFT);
                    aa = (av[i] > 0) ? aa : -1e30f;
                    float e = exp2f(aa);
                    pS[p_kq + i][p_r] = e;
                    ls += e;
                }
                if (fb == 0) atomicAdd(&lsm[p_r], ls);
            }
            __syncthreads();

            if (act) {
#pragma unroll 4
                for (int kk = 0; kk < 16; kk++) {
                    ulonglong2 pA = *(const ulonglong2*)&pS[kk][tr * 4];
                    ulonglong2 pB = *(const ulonglong2*)&pS[kk][64 + tr * 4];
                    float4 wA = *(const float4*)&whS[kk][tc * 4];
                    float4 wB = *(const float4*)&whS[kk][64 + tc * 4];
                    unsigned long long w2[8];
                    w2[0] = dup2(wA.x); w2[1] = dup2(wA.y);
                    w2[2] = dup2(wA.z); w2[3] = dup2(wA.w);
                    w2[4] = dup2(wB.x); w2[5] = dup2(wB.y);
                    w2[6] = dup2(wB.z); w2[7] = dup2(wB.w);
#pragma unroll
                    for (int c = 0; c < 8; c++) {
                        fma2(acc[0][c], pA.x, w2[c]);
                        fma2(acc[1][c], pA.y, w2[c]);
                        fma2(acc[2][c], pB.x, w2[c]);
                        fma2(acc[3][c], pB.y, w2[c]);
                    }
                }
            }
        }
        __syncthreads();   // lsm complete before reads

        if (act) {
#pragma unroll
            for (int ip = 0; ip < 4; ip++) {
                int rloc = (ip < 2) ? (tr * 4 + ip * 2) : (64 + tr * 4 + (ip - 2) * 2);
                float sf0 = 1.0f / lsm[rloc];
                float sf1 = 1.0f / lsm[rloc + 1];
                float lo[8], hi[8];
#pragma unroll
                for (int c = 0; c < 8; c++) unpack2(acc[ip][c], lo[c], hi[c]);
#pragma unroll
                for (int h2 = 0; h2 < 2; h2++) {
                    float* v = h2 ? hi : lo;
                    float sf = h2 ? sf1 : sf0;
                    size_t rowoff = ((size_t)(rowbase + rloc + h2)) * 256;
                    float4 oA, oB;
                    float u0 = v[0] * sf, u1 = v[1] * sf, u2 = v[2] * sf, u3 = v[3] * sf;
                    float u4 = v[4] * sf, u5 = v[5] * sf, u6 = v[6] * sf, u7 = v[7] * sf;
                    oA.x = (u0 > 0.f) ? u0 : expm1f(u0);
                    oA.y = (u1 > 0.f) ? u1 : expm1f(u1);
                    oA.z = (u2 > 0.f) ? u2 : expm1f(u2);
                    oA.w = (u3 > 0.f) ? u3 : expm1f(u3);
                    oB.x = (u4 > 0.f) ? u4 : expm1f(u4);
                    oB.y = (u5 > 0.f) ? u5 : expm1f(u5);
                    oB.z = (u6 > 0.f) ? u6 : expm1f(u6);
                    oB.w = (u7 > 0.f) ? u7 : expm1f(u7);
                    *(float4*)&out[rowoff + fb + tc * 4]      = oA;
                    *(float4*)&out[rowoff + fb + 64 + tc * 4] = oB;
                }
            }
        }
    }
#endif
}

// ================= launcher =================
extern "C" void kernel_launch(void* const* d_in, const int* in_sizes, int n_in,
                              void* d_out, int out_size) {
    const float* h   = (const float*)d_in[0];   // (8,2048,256) f32
    const int*   adj = (const int*)  d_in[1];   // (8,2048,2048) i32
    const float* W   = (const float*)d_in[2];   // (256,256) f32
    const float* a   = (const float*)d_in[3];   // (512,1) f32
    float* out = (float*)d_out;                 // (8,2048,256) f32

    cudaFuncSetAttribute(k_gemm_tc, cudaFuncAttributeMaxDynamicSharedMemorySize,
                         SMEM_DYN_G);
    cudaFuncSetAttribute(k_attn_tc, cudaFuncAttributeMaxDynamicSharedMemorySize,
                         SMEM_DYN);

    k_wsplit<<<dim3(8, 8), 256>>>(W);
    k_gemm_tc<<<ROWS / 128, 512, SMEM_DYN_G>>>(h, W, a);
    k_attn_tc<<<dim3(NNODE / 128, BATCH), 544, SMEM_DYN>>>(adj, out);
}